// round 13
// baseline (speedup 1.0000x reference)
#include <cuda_runtime.h>
#include <cuda_bf16.h>
#include <cuda_fp16.h>
#include <cstdint>

#define BB 256
#define NT 256
#define TILE 34816          // 128 rows x 272B
#define TILEA 69632         // 256 rows x 272B

// ---------------- scratch (device globals; no allocation APIs) ---------------
__device__ __half g_c1hi[(size_t)BB*576*128];
__device__ __half g_c1lo[(size_t)BB*576*128];
__device__ float  g_c2f [(size_t)BB*576*128];
__device__ __half g_p1hi[(size_t)BB*144*128];
__device__ __half g_p1lo[(size_t)BB*144*128];
__device__ float  g_c3f [(size_t)BB*144*128];
__device__ float  g_zn  [(size_t)BB*36*128];
__device__ __nv_bfloat16 g_valh[(size_t)BB*36*128];
__device__ __nv_bfloat16 g_f1h[(size_t)BB*81*128];
__device__ __nv_bfloat16 g_f2h[(size_t)BB*400*128];
__device__ __nv_bfloat16 g_f3h[(size_t)BB*576*128];
__device__ __nv_bfloat16 g_f4h[(size_t)BB*784*128];
__device__ __nv_bfloat16 g_wp1[16*128*136];
__device__ __nv_bfloat16 g_wpt2[16*128*136];
__device__ __nv_bfloat16 g_wp3[25*128*136];
__device__ __nv_bfloat16 g_wp4[25*128*136];
__device__ __half g_w2hi[25*128*136];
__device__ __half g_w2lo[25*128*136];
__device__ __half g_w3hi[25*128*136];
__device__ __half g_w3lo[25*128*136];
__device__ double g_rec_sum;
__device__ double g_dict_sum;

__inline__ __device__ float warp_sum(float v) {
    #pragma unroll
    for (int o = 16; o; o >>= 1) v += __shfl_xor_sync(0xffffffffu, v, o);
    return v;
}

// ---------------- mma / cp.async helpers --------------------------------------
__device__ __forceinline__ uint32_t smem_u32(const void* p) {
    uint32_t a;
    asm("{ .reg .u64 t; cvta.to.shared.u64 t, %1; cvt.u32.u64 %0, t; }"
        : "=r"(a) : "l"(p));
    return a;
}

#define LDSM_X4(r0, r1, r2, r3, addr)                                          \
    asm volatile("ldmatrix.sync.aligned.m8n8.x4.shared.b16 {%0,%1,%2,%3}, [%4];" \
                 : "=r"(r0), "=r"(r1), "=r"(r2), "=r"(r3) : "r"(addr))

#define MMA_BF16(c, a0, a1, a2, a3, b0, b1)                                    \
    asm volatile("mma.sync.aligned.m16n8k16.row.col.f32.bf16.bf16.f32 "        \
                 "{%0,%1,%2,%3}, {%4,%5,%6,%7}, {%8,%9}, {%0,%1,%2,%3};"       \
                 : "+f"((c)[0]), "+f"((c)[1]), "+f"((c)[2]), "+f"((c)[3])      \
                 : "r"(a0), "r"(a1), "r"(a2), "r"(a3), "r"(b0), "r"(b1))

#define MMA_F16(c, a0, a1, a2, a3, b0, b1)                                     \
    asm volatile("mma.sync.aligned.m16n8k16.row.col.f32.f16.f16.f32 "          \
                 "{%0,%1,%2,%3}, {%4,%5,%6,%7}, {%8,%9}, {%0,%1,%2,%3};"       \
                 : "+f"((c)[0]), "+f"((c)[1]), "+f"((c)[2]), "+f"((c)[3])      \
                 : "r"(a0), "r"(a1), "r"(a2), "r"(a3), "r"(b0), "r"(b1))

#define CP16(d, s, n)                                                          \
    asm volatile("cp.async.cg.shared.global [%0], [%1], 16, %2;"               \
                 :: "r"(d), "l"(s), "r"(n))
#define CP_COMMIT() asm volatile("cp.async.commit_group;" ::: "memory")
#define CP_WAIT0()  asm volatile("cp.async.wait_group 0;" ::: "memory")
#define CP_WAIT1()  asm volatile("cp.async.wait_group 1;" ::: "memory")
#define CP_WAIT2()  asm volatile("cp.async.wait_group 2;" ::: "memory")

// ---------------- fused weight prepack (all layers, one launch) ---------------
__device__ __forceinline__ void pp_fwd_split(const float* W, __half* dh, __half* dl,
                                             int tap)
{
    int ky = tap / 5, kx = tap - ky * 5;
    size_t tb = (size_t)tap * 128 * 136;
    for (int i = threadIdx.x; i < 16384; i += blockDim.x) {
        int co = i >> 7, ci = i & 127;
        float v = W[(((size_t)co * 128 + ci) * 5 + ky) * 5 + kx];
        __half h = __float2half_rn(v);
        dh[tb + co * 136 + ci] = h;
        dl[tb + co * 136 + ci] = __float2half_rn(v - __half2float(h));
    }
}

__device__ __forceinline__ void pp_deconv(const float* W, __nv_bfloat16* dst,
                                          int tap, int K)
{
    int ky = tap / K, kx = tap - ky * K;
    __nv_bfloat16* base = dst + (size_t)tap * 128 * 136;
    for (int i = threadIdx.x; i < 16384; i += blockDim.x) {
        int co = i >> 7, ci = i & 127;
        float v = W[(((size_t)ci * 128 + co) * K + (K - 1 - ky)) * K + (K - 1 - kx)];
        base[co * 136 + ci] = __float2bfloat16(v);
    }
}

__device__ __forceinline__ void pp_t2(const float* W, __nv_bfloat16* dst, int idx)
{
    int par = idx >> 2, tap = idx & 3;
    int py = par >> 1, px = par & 1;
    int ti = tap >> 1, tj = tap & 1;
    int ky = py + 2 * ti, kx = px + 2 * tj;
    __nv_bfloat16* base = dst + (size_t)idx * 128 * 136;
    for (int i = threadIdx.x; i < 16384; i += blockDim.x) {
        int co = i >> 7, ci = i & 127;
        float v = W[(((size_t)ci * 128 + co) * 4 + ky) * 4 + kx];
        base[co * 136 + ci] = __float2bfloat16(v);
    }
}

__global__ void prepack_all(const float* w2, const float* w3,
                            const float* t1w, const float* t2w,
                            const float* t3w, const float* t4w,
                            __half* w2hi, __half* w2lo,
                            __half* w3hi, __half* w3lo,
                            __nv_bfloat16* wp1, __nv_bfloat16* wpt2,
                            __nv_bfloat16* wp3, __nv_bfloat16* wp4)
{
    int bid = blockIdx.x;
    if (bid == 0 && threadIdx.x == 0) { g_rec_sum = 0.0; g_dict_sum = 0.0; }
    if      (bid < 25)  pp_fwd_split(w2, w2hi, w2lo, bid);
    else if (bid < 50)  pp_fwd_split(w3, w3hi, w3lo, bid - 25);
    else if (bid < 66)  pp_deconv(t1w, wp1, bid - 50, 4);
    else if (bid < 82)  pp_t2(t2w, wpt2, bid - 66);
    else if (bid < 107) pp_deconv(t3w, wp3, bid - 82, 5);
    else                pp_deconv(t4w, wp4, bid - 107, 5);
}

// ====== fused 3-pass fp16-split encoder conv, M=256, chunked-B pipeline =======
__global__ void __launch_bounds__(512, 1)
tc_enc3(const uint16_t* __restrict__ inHi, const uint16_t* __restrict__ inLo,
        const uint16_t* __restrict__ wHi,  const uint16_t* __restrict__ wLo,
        const float* __restrict__ bias, float* __restrict__ outp,
        int Hin, int Win, int Hout, int Wout, int pad, int relu)
{
    extern __shared__ char dsm[];
    __shared__ float sbias[128];
    const int tid  = threadIdx.x;
    const int wid  = tid >> 5;
    const int lane = tid & 31;
    const int Npix = Hout * Wout;
    const int totalPx = BB * Npix;
    const int pbase = blockIdx.x * 256;

    const uint32_t smA   = smem_u32(dsm);
    const uint32_t smBhi = smA + 2 * TILEA;
    const uint32_t smBlo = smBhi + TILE;
    if (tid < 128) sbias[tid] = bias[tid];

    const int arow = tid >> 1, ahalf = tid & 1;
    const int ap = pbase + arow;
    const bool apv = (ap < totalPx);
    const int bA  = apv ? ap / Npix : 0;
    const int apn = apv ? ap - bA * Npix : 0;
    const int apy = apn / Wout;
    const int apx = apn - apy * Wout;
    const uint32_t adst0 = smA + arow * 272 + ahalf * 128;

    const int pxg = wid >> 1, cog = wid & 1;
    float acc[2][8][4];
    #pragma unroll
    for (int m = 0; m < 2; m++)
        #pragma unroll
        for (int n = 0; n < 8; n++)
            #pragma unroll
            for (int j = 0; j < 4; j++) acc[m][n][j] = 0.f;

    const uint32_t a_rd0 = smA + (pxg * 32 + (lane & 15)) * 272 + ((lane >> 4) << 4);
    const uint32_t b_rdb = (cog * 64 + ((lane >> 4) << 3) + (lane & 7)) * 272
                         + (((lane >> 3) & 1) << 4);

    auto stage_A = [&](int it) {
        const int tap = (it < 25) ? it : it - 25;
        const uint16_t* abuf = (it < 25) ? inHi : inLo;
        const int ky = tap / 5, kx = tap - ky * 5;
        const int iy = apy + ky - pad, ix = apx + kx - pad;
        const bool inb = apv && (unsigned)iy < (unsigned)Hin && (unsigned)ix < (unsigned)Win;
        const char* as = inb ? (const char*)(abuf + ((size_t)(bA * Hin + iy) * Win + ix) * 128
                                             + ahalf * 64)
                             : (const char*)abuf;
        const uint32_t ad = adst0 + (it & 1) * TILEA;
        const int sz = inb ? 16 : 0;
        #pragma unroll
        for (int j = 0; j < 8; ++j)
            CP16(ad + j * 16, as + (size_t)j * 16, sz);
    };

    // stage half of a B tile: chunk c covers bytes [c*128, c*128+128) of each row
    auto stage_Bchunk = [&](const uint16_t* wbuf, int tap, uint32_t bd, int c) {
        const char* wb = (const char*)(wbuf + (size_t)tap * 128 * 136);
        #pragma unroll
        for (int j = 0; j < 2; ++j) {
            int i = j * 512 + tid;                 // 1024 16B chunks
            int row = i >> 3, w16 = i & 7;
            uint32_t off = row * 272 + c * 128 + w16 * 16;
            CP16(bd + off, wb + off, 16);
        }
    };

    auto mma_half = [&](uint32_t abase, int ks0, int ph) {
        #pragma unroll
        for (int ks = ks0; ks < ks0 + 4; ++ks) {
            uint32_t a[2][4], bq[4][4];
            #pragma unroll
            for (int i = 0; i < 2; ++i)
                LDSM_X4(a[i][0], a[i][1], a[i][2], a[i][3],
                        a_rd0 + abase + i * 16 * 272 + ks * 32);
            #pragma unroll
            for (int nb = 0; nb < 4; ++nb)
                LDSM_X4(bq[nb][0], bq[nb][1], bq[nb][2], bq[nb][3],
                        smBhi + b_rdb + nb * 16 * 272 + ks * 32);
            #pragma unroll
            for (int nb = 0; nb < 4; ++nb)
                #pragma unroll
                for (int i = 0; i < 2; ++i) {
                    MMA_F16(acc[i][2 * nb],     a[i][0], a[i][1], a[i][2], a[i][3],
                            bq[nb][0], bq[nb][1]);
                    MMA_F16(acc[i][2 * nb + 1], a[i][0], a[i][1], a[i][2], a[i][3],
                            bq[nb][2], bq[nb][3]);
                }
            if (ph == 0) {
                #pragma unroll
                for (int nb = 0; nb < 4; ++nb)
                    LDSM_X4(bq[nb][0], bq[nb][1], bq[nb][2], bq[nb][3],
                            smBlo + b_rdb + nb * 16 * 272 + ks * 32);
                #pragma unroll
                for (int nb = 0; nb < 4; ++nb)
                    #pragma unroll
                    for (int i = 0; i < 2; ++i) {
                        MMA_F16(acc[i][2 * nb],     a[i][0], a[i][1], a[i][2], a[i][3],
                                bq[nb][0], bq[nb][1]);
                        MMA_F16(acc[i][2 * nb + 1], a[i][0], a[i][1], a[i][2], a[i][3],
                                bq[nb][2], bq[nb][3]);
                    }
            }
        }
    };

    stage_A(0);
    CP_COMMIT();

    for (int it = 0; it < 50; ++it) {
        const int tap = (it < 25) ? it : it - 25;
        const int ph  = (it < 25) ? 0 : 1;
        // commit order: B chunk0, B chunk1, A(it+1)
        stage_Bchunk(wHi, tap, smBhi, 0);
        if (ph == 0) stage_Bchunk(wLo, tap, smBlo, 0);
        CP_COMMIT();
        stage_Bchunk(wHi, tap, smBhi, 1);
        if (ph == 0) stage_Bchunk(wLo, tap, smBlo, 1);
        CP_COMMIT();
        if (it < 49) {
            stage_A(it + 1);
            CP_COMMIT();
            CP_WAIT2();                 // A(it) + B chunk0 complete
        } else {
            CP_WAIT1();
        }
        __syncthreads();
        const uint32_t abase = (it & 1) * TILEA;
        mma_half(abase, 0, ph);         // ks 0-3 use B bytes [0,128)
        if (it < 49) CP_WAIT1(); else CP_WAIT0();   // B chunk1 complete
        __syncthreads();
        mma_half(abase, 4, ph);         // ks 4-7 use B bytes [128,256)
        __syncthreads();
    }

    #pragma unroll
    for (int mb = 0; mb < 2; ++mb) {
        const int row0 = pbase + pxg * 32 + mb * 16 + (lane >> 2);
        const int row1 = row0 + 8;
        const bool v0 = (row0 < totalPx), v1 = (row1 < totalPx);
        #pragma unroll
        for (int nt = 0; nt < 8; ++nt) {
            const int co = cog * 64 + nt * 8 + 2 * (lane & 3);
            const float bz0 = sbias[co], bz1 = sbias[co + 1];
            float p00 = acc[mb][nt][0] + bz0, p01 = acc[mb][nt][1] + bz1;
            float p10 = acc[mb][nt][2] + bz0, p11 = acc[mb][nt][3] + bz1;
            if (relu) {
                p00 = fmaxf(p00, 0.f); p01 = fmaxf(p01, 0.f);
                p10 = fmaxf(p10, 0.f); p11 = fmaxf(p11, 0.f);
            }
            if (v0) *(float2*)(outp + (size_t)row0 * 128 + co) = make_float2(p00, p01);
            if (v1) *(float2*)(outp + (size_t)row1 * 128 + co) = make_float2(p10, p11);
        }
    }
}

// ================= 1-pass bf16 engine, M=256, 512 threads =====================
__global__ void __launch_bounds__(512, 1)
tc_eng1(const uint16_t* __restrict__ in, const uint16_t* __restrict__ wpack,
        const float* __restrict__ bias, __nv_bfloat16* __restrict__ outp,
        int Hin, int Win, int Hout, int Wout, int pad, int K)
{
    extern __shared__ char dsm[];
    __shared__ float sbias[128];
    const int tid  = threadIdx.x;
    const int wid  = tid >> 5;
    const int lane = tid & 31;
    const int Npix = Hout * Wout;
    const int totalPx = BB * Npix;
    const int pbase = blockIdx.x * 256;

    const uint32_t smA = smem_u32(dsm);
    const uint32_t smB = smA + 2 * TILEA;
    if (tid < 128) sbias[tid] = bias[tid];

    const int arow = tid >> 1, ahalf = tid & 1;
    const int ap = pbase + arow;
    const bool apv = (ap < totalPx);
    const int bA  = apv ? ap / Npix : 0;
    const int apn = apv ? ap - bA * Npix : 0;
    const int apy = apn / Wout;
    const int apx = apn - apy * Wout;
    const uint32_t adst0 = smA + arow * 272 + ahalf * 128;

    const int pxg = wid >> 1, cog = wid & 1;
    float acc[2][8][4];
    #pragma unroll
    for (int m = 0; m < 2; m++)
        #pragma unroll
        for (int n = 0; n < 8; n++)
            #pragma unroll
            for (int j = 0; j < 4; j++) acc[m][n][j] = 0.f;

    const uint32_t a_rd0 = smA + (pxg * 32 + (lane & 15)) * 272 + ((lane >> 4) << 4);
    const uint32_t b_rdb = (cog * 64 + ((lane >> 4) << 3) + (lane & 7)) * 272
                         + (((lane >> 3) & 1) << 4);
    const int NIT = K * K;

    auto stage = [&](int tap) {
        const int buf = tap & 1;
        const int ky = tap / K, kx = tap - ky * K;
        const char* wb = (const char*)(wpack + (size_t)tap * 128 * 136);
        const uint32_t bd = smB + buf * TILE;
        #pragma unroll
        for (int j = 0; j < 4; ++j)
            CP16(bd + (j * 512 + tid) * 16, wb + (size_t)(j * 512 + tid) * 16, 16);
        if (tid < 128)
            CP16(bd + (2048 + tid) * 16, wb + (size_t)(2048 + tid) * 16, 16);
        const int iy = apy + ky - pad, ix = apx + kx - pad;
        const bool inb = apv && (unsigned)iy < (unsigned)Hin && (unsigned)ix < (unsigned)Win;
        const char* as = inb ? (const char*)(in + ((size_t)(bA * Hin + iy) * Win + ix) * 128
                                             + ahalf * 64)
                             : (const char*)in;
        const uint32_t ad = adst0 + buf * TILEA;
        const int sz = inb ? 16 : 0;
        #pragma unroll
        for (int j = 0; j < 8; ++j)
            CP16(ad + j * 16, as + (size_t)j * 16, sz);
        CP_COMMIT();
    };

    stage(0);
    for (int it = 0; it < NIT; ++it) {
        CP_WAIT0();
        __syncthreads();
        if (it + 1 < NIT) stage(it + 1);
        const uint32_t abase = (it & 1) * TILEA;
        const uint32_t bbase = smB + (it & 1) * TILE;
        #pragma unroll
        for (int ks = 0; ks < 8; ++ks) {
            uint32_t a[2][4], bq[4][4];
            #pragma unroll
            for (int i = 0; i < 2; ++i)
                LDSM_X4(a[i][0], a[i][1], a[i][2], a[i][3],
                        a_rd0 + abase + i * 16 * 272 + ks * 32);
            #pragma unroll
            for (int nb = 0; nb < 4; ++nb)
                LDSM_X4(bq[nb][0], bq[nb][1], bq[nb][2], bq[nb][3],
                        bbase + b_rdb + nb * 16 * 272 + ks * 32);
            #pragma unroll
            for (int nb = 0; nb < 4; ++nb)
                #pragma unroll
                for (int i = 0; i < 2; ++i) {
                    MMA_BF16(acc[i][2 * nb],     a[i][0], a[i][1], a[i][2], a[i][3],
                             bq[nb][0], bq[nb][1]);
                    MMA_BF16(acc[i][2 * nb + 1], a[i][0], a[i][1], a[i][2], a[i][3],
                             bq[nb][2], bq[nb][3]);
                }
        }
    }

    #pragma unroll
    for (int mb = 0; mb < 2; ++mb) {
        const int row0 = pbase + pxg * 32 + mb * 16 + (lane >> 2);
        const int row1 = row0 + 8;
        const bool v0 = (row0 < totalPx), v1 = (row1 < totalPx);
        #pragma unroll
        for (int nt = 0; nt < 8; ++nt) {
            const int co = cog * 64 + nt * 8 + 2 * (lane & 3);
            const float bz0 = sbias[co], bz1 = sbias[co + 1];
            float p00 = fmaxf(acc[mb][nt][0] + bz0, 0.f);
            float p01 = fmaxf(acc[mb][nt][1] + bz1, 0.f);
            float p10 = fmaxf(acc[mb][nt][2] + bz0, 0.f);
            float p11 = fmaxf(acc[mb][nt][3] + bz1, 0.f);
            if (v0) {
                __nv_bfloat162 h = __floats2bfloat162_rn(p00, p01);
                *(uint32_t*)(outp + (size_t)row0 * 128 + co) = *reinterpret_cast<uint32_t*>(&h);
            }
            if (v1) {
                __nv_bfloat162 h = __floats2bfloat162_rn(p10, p11);
                *(uint32_t*)(outp + (size_t)row1 * 128 + co) = *reinterpret_cast<uint32_t*>(&h);
            }
        }
    }
}

// ================= t2 stride-2 deconv, parity decomposition, 512 thr ==========
__global__ void __launch_bounds__(512, 1)
tc_t2(const uint16_t* __restrict__ in, const uint16_t* __restrict__ wpack,
      const float* __restrict__ bias, __nv_bfloat16* __restrict__ outp)
{
    extern __shared__ char dsm[];
    __shared__ float sbias[128];
    const int tid  = threadIdx.x;
    const int wid  = tid >> 5;
    const int lane = tid & 31;
    const int par  = blockIdx.z;
    const int py   = par >> 1, px = par & 1;
    const int totalPx = BB * 100;
    const int pbase = blockIdx.x * 256;

    const uint32_t smA = smem_u32(dsm);
    const uint32_t smB = smA + 2 * TILEA;
    if (tid < 128) sbias[tid] = bias[tid];

    const int arow = tid >> 1, ahalf = tid & 1;
    const int ap = pbase + arow;
    const bool apv = (ap < totalPx);
    const int bA  = apv ? ap / 100 : 0;
    const int apn = apv ? ap - bA * 100 : 0;
    const int apy = apn / 10;
    const int apx = apn - apy * 10;
    const uint32_t adst0 = smA + arow * 272 + ahalf * 128;

    const int pxg = wid >> 1, cog = wid & 1;
    float acc[2][8][4];
    #pragma unroll
    for (int m = 0; m < 2; m++)
        #pragma unroll
        for (int n = 0; n < 8; n++)
            #pragma unroll
            for (int j = 0; j < 4; j++) acc[m][n][j] = 0.f;

    const uint32_t a_rd0 = smA + (pxg * 32 + (lane & 15)) * 272 + ((lane >> 4) << 4);
    const uint32_t b_rdb = (cog * 64 + ((lane >> 4) << 3) + (lane & 7)) * 272
                         + (((lane >> 3) & 1) << 4);

    auto stage = [&](int tap) {
        const int buf = tap & 1;
        const int ti = tap >> 1, tj = tap & 1;
        const char* wb = (const char*)(wpack + (size_t)(par * 4 + tap) * 128 * 136);
        const uint32_t bd = smB + buf * TILE;
        #pragma unroll
        for (int j = 0; j < 4; ++j)
            CP16(bd + (j * 512 + tid) * 16, wb + (size_t)(j * 512 + tid) * 16, 16);
        if (tid < 128)
            CP16(bd + (2048 + tid) * 16, wb + (size_t)(2048 + tid) * 16, 16);
        const int iy = apy - ti, ix = apx - tj;
        const bool inb = apv && (unsigned)iy < 9u && (unsigned)ix < 9u;
        const char* as = inb ? (const char*)(in + ((size_t)(bA * 9 + iy) * 9 + ix) * 128
                                             + ahalf * 64)
                             : (const char*)in;
        const uint32_t ad = adst0 + buf * TILEA;
        const int sz = inb ? 16 : 0;
        #pragma unroll
        for (int j = 0; j < 8; ++j)
            CP16(ad + j * 16, as + (size_t)j * 16, sz);
        CP_COMMIT();
    };

    stage(0);
    for (int it = 0; it < 4; ++it) {
        CP_WAIT0();
        __syncthreads();
        if (it + 1 < 4) stage(it + 1);
        const uint32_t abase = (it & 1) * TILEA;
        const uint32_t bbase = smB + (it & 1) * TILE;
        #pragma unroll
        for (int ks = 0; ks < 8; ++ks) {
            uint32_t a[2][4], bq[4][4];
            #pragma unroll
            for (int i = 0; i < 2; ++i)
                LDSM_X4(a[i][0], a[i][1], a[i][2], a[i][3],
                        a_rd0 + abase + i * 16 * 272 + ks * 32);
            #pragma unroll
            for (int nb = 0; nb < 4; ++nb)
                LDSM_X4(bq[nb][0], bq[nb][1], bq[nb][2], bq[nb][3],
                        bbase + b_rdb + nb * 16 * 272 + ks * 32);
            #pragma unroll
            for (int nb = 0; nb < 4; ++nb)
                #pragma unroll
                for (int i = 0; i < 2; ++i) {
                    MMA_BF16(acc[i][2 * nb],     a[i][0], a[i][1], a[i][2], a[i][3],
                             bq[nb][0], bq[nb][1]);
                    MMA_BF16(acc[i][2 * nb + 1], a[i][0], a[i][1], a[i][2], a[i][3],
                             bq[nb][2], bq[nb][3]);
                }
        }
    }

    #pragma unroll
    for (int mb = 0; mb < 2; ++mb) {
        const int r0g = pbase + pxg * 32 + mb * 16 + (lane >> 2);
        const int r1g = r0g + 8;
        int b0 = r0g / 100, q0 = r0g - b0 * 100, y0 = q0 / 10, x0 = q0 - y0 * 10;
        int b1 = r1g / 100, q1 = r1g - b1 * 100, y1 = q1 / 10, x1 = q1 - y1 * 10;
        size_t o0 = ((size_t)b0 * 400 + (2 * y0 + py) * 20 + 2 * x0 + px) * 128;
        size_t o1 = ((size_t)b1 * 400 + (2 * y1 + py) * 20 + 2 * x1 + px) * 128;
        #pragma unroll
        for (int nt = 0; nt < 8; ++nt) {
            const int co = cog * 64 + nt * 8 + 2 * (lane & 3);
            const float bz0 = sbias[co], bz1 = sbias[co + 1];
            float p00 = fmaxf(acc[mb][nt][0] + bz0, 0.f);
            float p01 = fmaxf(acc[mb][nt][1] + bz1, 0.f);
            float p10 = fmaxf(acc[mb][nt][2] + bz0, 0.f);
            float p11 = fmaxf(acc[mb][nt][3] + bz1, 0.f);
            if (r0g < totalPx) {
                __nv_bfloat162 h = __floats2bfloat162_rn(p00, p01);
                *(uint32_t*)(outp + o0 + co) = *reinterpret_cast<uint32_t*>(&h);
            }
            if (r1g < totalPx) {
                __nv_bfloat162 h = __floats2bfloat162_rn(p10, p11);
                *(uint32_t*)(outp + o1 + co) = *reinterpret_cast<uint32_t*>(&h);
            }
        }
    }
}

// ---------------- conv1: 8 px/block, weights in registers ---------------------
__global__ void __launch_bounds__(128)
conv1_split(const float* __restrict__ x, const float* __restrict__ w1,
            const float* __restrict__ b1, __half* __restrict__ hi,
            __half* __restrict__ lo)
{
    const int b = blockIdx.x, g = blockIdx.y;
    const int p0 = g * 8;
    const int oy = p0 / 24, ox0 = p0 - oy * 24;
    const int co = threadIdx.x;
    __shared__ float xs[5][12];
    for (int i = co; i < 60; i += 128) {
        int r = i / 12, c = i - r * 12;
        xs[r][c] = x[(size_t)b * 784 + (oy + r) * 28 + ox0 + c];
    }
    __syncthreads();
    float w[25];
    #pragma unroll
    for (int t = 0; t < 25; ++t) w[t] = w1[co * 25 + t];
    const float bz = b1[co];
    #pragma unroll
    for (int px = 0; px < 8; ++px) {
        float v = bz;
        #pragma unroll
        for (int t = 0; t < 25; ++t)
            v += w[t] * xs[t / 5][t % 5 + px];
        v = fmaxf(v, 0.f);
        __half h = __float2half_rn(v);
        size_t o = ((size_t)b * 576 + p0 + px) * 128 + co;
        hi[o] = h;
        lo[o] = __float2half_rn(v - __half2float(h));
    }
}

// ---------------- NHWC maxpool 2x2: fp32 -> fp16 hi/lo -----------------------
__global__ void mp_split_nhwc(const float* __restrict__ in, __half* __restrict__ hi,
                              __half* __restrict__ lo, int Hin, int Win)
{
    const int Ho = Hin >> 1, Wo = Win >> 1;
    const size_t total = (size_t)BB * Ho * Wo * 128;
    for (size_t i = (size_t)blockIdx.x * blockDim.x + threadIdx.x; i < total;
         i += (size_t)gridDim.x * blockDim.x) {
        int c = (int)(i & 127);
        size_t r = i >> 7;
        int wo = (int)(r % Wo); r /= Wo;
        int ho = (int)(r % Ho); int b = (int)(r / Ho);
        const float* p = in + (((size_t)b * Hin + 2 * ho) * Win + 2 * wo) * 128 + c;
        float v = fmaxf(fmaxf(p[0], p[128]),
                        fmaxf(p[(size_t)Win * 128], p[(size_t)(Win + 1) * 128]));
        __half h = __float2half_rn(v);
        hi[i] = h;
        lo[i] = __float2half_rn(v - __half2float(h));
    }
}

// ---------------- NHWC maxpool 2x2: fp32 -> fp32 -----------------------------
__global__ void mp_nhwc(const float* __restrict__ in, float* __restrict__ out,
                        int Hin, int Win)
{
    const int Ho = Hin >> 1, Wo = Win >> 1;
    const size_t total = (size_t)BB * Ho * Wo * 128;
    for (size_t i = (size_t)blockIdx.x * blockDim.x + threadIdx.x; i < total;
         i += (size_t)gridDim.x * blockDim.x) {
        int c = (int)(i & 127);
        size_t r = i >> 7;
        int wo = (int)(r % Wo); r /= Wo;
        int ho = (int)(r % Ho); int b = (int)(r / Ho);
        const float* p = in + (((size_t)b * Hin + 2 * ho) * Win + 2 * wo) * 128 + c;
        out[i] = fmaxf(fmaxf(p[0], p[128]),
                       fmaxf(p[(size_t)Win * 128], p[(size_t)(Win + 1) * 128]));
    }
}

// ---------------- VQ: argmax(d2), gather val (NHWC bf16), dict MSE ------------
__global__ void __launch_bounds__(256)
vq_kernel(const float* __restrict__ z, const float* __restrict__ dict,
          __nv_bfloat16* __restrict__ valh, float* __restrict__ idx_out)
{
    extern __shared__ float dsmf[];
    __shared__ float zt[36 * 128];
    __shared__ float wn[128];
    __shared__ int   sidx[36];

    const int b = blockIdx.x, tid = threadIdx.x;

    for (int i = tid; i < 128 * 128; i += NT) {
        int k = i >> 7; int c = i & 127;
        dsmf[k * 129 + c] = dict[i];
    }
    for (int i = tid; i < 36 * 128; i += NT)
        zt[i] = z[(size_t)b * 4608 + i];
    __syncthreads();
    if (tid < 128) {
        float s = 0.f;
        const float* dp = dsmf + tid * 129;
        for (int c = 0; c < 128; c++) s += dp[c] * dp[c];
        wn[tid] = s;
    }
    __syncthreads();

    const int lane = tid & 31, wid = tid >> 5;
    for (int pos = wid; pos < 36; pos += 8) {
        float d0 = 0.f, d1 = 0.f, d2s = 0.f, d3 = 0.f, zn = 0.f;
        const float* zp = zt + pos * 128;
        const float* p0 = dsmf + (lane      ) * 129;
        const float* p1 = dsmf + (lane + 32 ) * 129;
        const float* p2 = dsmf + (lane + 64 ) * 129;
        const float* p3 = dsmf + (lane + 96 ) * 129;
        for (int c = 0; c < 128; c++) {
            float zv = zp[c];
            zn += zv * zv;
            d0 += p0[c] * zv; d1 += p1[c] * zv;
            d2s += p2[c] * zv; d3 += p3[c] * zv;
        }
        float bv = zn + wn[lane] - 2.f * d0; int bk = lane;
        float v1 = zn + wn[lane + 32] - 2.f * d1; if (v1 > bv) { bv = v1; bk = lane + 32; }
        float v2 = zn + wn[lane + 64] - 2.f * d2s; if (v2 > bv) { bv = v2; bk = lane + 64; }
        float v3 = zn + wn[lane + 96] - 2.f * d3; if (v3 > bv) { bv = v3; bk = lane + 96; }
        #pragma unroll
        for (int o = 16; o; o >>= 1) {
            float ov = __shfl_xor_sync(0xffffffffu, bv, o);
            int   ok = __shfl_xor_sync(0xffffffffu, bk, o);
            if (ov > bv || (ov == bv && ok < bk)) { bv = ov; bk = ok; }
        }
        if (lane == 0) {
            sidx[pos] = bk;
            if (idx_out) idx_out[b * 36 + pos] = (float)bk;
        }
    }
    __syncthreads();

    float lsum = 0.f;
    for (int i = tid; i < 4608; i += NT) {
        int pos = i >> 7; int c = i & 127;
        float v  = dsmf[sidx[pos] * 129 + c];
        float zv = zt[i];
        valh[(size_t)b * 4608 + i] = __float2bfloat16(v);
        float d = v - zv;
        lsum += d * d;
    }
    lsum = warp_sum(lsum);
    if ((tid & 31) == 0) atomicAdd(&g_dict_sum, (double)lsum);
}

// ---------------- mu (1x1 conv) fused with reconstruction loss (NHWC bf16) ---
__global__ void __launch_bounds__(256)
mu_loss(const __nv_bfloat16* __restrict__ f4, const float* __restrict__ x,
        const float* __restrict__ mw, const float* __restrict__ mb)
{
    __shared__ float mws[128];
    const int b = blockIdx.x, tid = threadIdx.x;
    if (tid < 128) mws[tid] = mw[tid];
    __syncthreads();
    float lsum = 0.f;
    for (int px = tid; px < 784; px += NT) {
        const uint4* fp = (const uint4*)(f4 + ((size_t)b * 784 + px) * 128);
        float s = mb[0];
        #pragma unroll
        for (int j = 0; j < 16; j++) {
            uint4 v = fp[j];
            const __nv_bfloat16* h = (const __nv_bfloat16*)&v;
            #pragma unroll
            for (int t = 0; t < 8; t++)
                s += __bfloat162float(h[t]) * mws[j * 8 + t];
        }
        float d = s - x[(size_t)b * 784 + px];
        lsum += d * d;
    }
    lsum = warp_sum(lsum);
    if ((tid & 31) == 0) atomicAdd(&g_rec_sum, (double)lsum);
}

__global__ void finalize_kernel(float* loss_out)
{
    if (loss_out) {
        double dict_mse = g_dict_sum / 1179648.0;
        loss_out[0] = (float)(g_rec_sum / 200704.0);
        loss_out[1] = (float)(dict_mse * 5.0);
        loss_out[2] = (float)(dict_mse * 1.25);
        loss_out[3] = 0.f;
    }
}

// ---------------- host side ----------------------------------------------------
extern "C" void kernel_launch(void* const* d_in, const int* in_sizes, int n_in,
                              void* d_out, int out_size)
{
    const float* x    = (const float*)d_in[0];
    const float* w1   = (const float*)d_in[1];
    const float* b1   = (const float*)d_in[2];
    const float* w2   = (const float*)d_in[3];
    const float* b2   = (const float*)d_in[4];
    const float* w3   = (const float*)d_in[5];
    const float* b3   = (const float*)d_in[6];
    const float* t1w  = (const float*)d_in[7];
    const float* t1b  = (const float*)d_in[8];
    const float* t2w  = (const float*)d_in[9];
    const float* t2b  = (const float*)d_in[10];
    const float* t3w  = (const float*)d_in[11];
    const float* t3b  = (const float*)d_in[12];
    const float* t4w  = (const float*)d_in[13];
    const float* t4b  = (const float*)d_in[14];
    const float* mw   = (const float*)d_in[15];
    const float* mb   = (const float*)d_in[16];
    const float* dictw= (const float*)d_in[17];

    float* outp = (float*)d_out;
    float* loss_ptr = outp;
    float* idx_ptr  = outp + 4;
    if (out_size < 9220) { loss_ptr = nullptr; idx_ptr = outp; }

    __half *c1hi, *c1lo, *p1hi, *p1lo, *w2hi, *w2lo, *w3hi, *w3lo;
    float *c2f, *c3f, *zn;
    __nv_bfloat16 *valh, *f1h, *f2h, *f3h, *f4h, *wp1, *wpt2, *wp3, *wp4;
    cudaGetSymbolAddress((void**)&c1hi, g_c1hi);
    cudaGetSymbolAddress((void**)&c1lo, g_c1lo);
    cudaGetSymbolAddress((void**)&c2f,  g_c2f);
    cudaGetSymbolAddress((void**)&p1hi, g_p1hi);
    cudaGetSymbolAddress((void**)&p1lo, g_p1lo);
    cudaGetSymbolAddress((void**)&c3f,  g_c3f);
    cudaGetSymbolAddress((void**)&zn,   g_zn);
    cudaGetSymbolAddress((void**)&valh, g_valh);
    cudaGetSymbolAddress((void**)&f1h,  g_f1h);
    cudaGetSymbolAddress((void**)&f2h,  g_f2h);
    cudaGetSymbolAddress((void**)&f3h,  g_f3h);
    cudaGetSymbolAddress((void**)&f4h,  g_f4h);
    cudaGetSymbolAddress((void**)&wp1,  g_wp1);
    cudaGetSymbolAddress((void**)&wpt2, g_wpt2);
    cudaGetSymbolAddress((void**)&wp3,  g_wp3);
    cudaGetSymbolAddress((void**)&wp4,  g_wp4);
    cudaGetSymbolAddress((void**)&w2hi, g_w2hi);
    cudaGetSymbolAddress((void**)&w2lo, g_w2lo);
    cudaGetSymbolAddress((void**)&w3hi, g_w3hi);
    cudaGetSymbolAddress((void**)&w3lo, g_w3lo);

    static bool attr_set = false;
    if (!attr_set) {
        cudaFuncSetAttribute(vq_kernel, cudaFuncAttributeMaxDynamicSharedMemorySize,
                             128 * 129 * (int)sizeof(float));
        cudaFuncSetAttribute(tc_eng1, cudaFuncAttributeMaxDynamicSharedMemorySize,
                             2 * TILEA + 2 * TILE);
        cudaFuncSetAttribute(tc_t2, cudaFuncAttributeMaxDynamicSharedMemorySize,
                             2 * TILEA + 2 * TILE);
        cudaFuncSetAttribute(tc_enc3, cudaFuncAttributeMaxDynamicSharedMemorySize,
                             2 * TILEA + 2 * TILE);
        attr_set = true;
    }

    prepack_all<<<132, 256>>>(w2, w3, t1w, t2w, t3w, t4w,       // 0 (also inits sums)
                              w2hi, w2lo, w3hi, w3lo, wp1, wpt2, wp3, wp4);
    conv1_split<<<dim3(BB, 72), 128>>>(x, w1, b1, c1hi, c1lo);  // 1
    tc_enc3<<<576, 512, 2 * TILEA + 2 * TILE>>>(                // 2
        (const uint16_t*)c1hi, (const uint16_t*)c1lo,
        (const uint16_t*)w2hi, (const uint16_t*)w2lo,
        b2, c2f, 24, 24, 24, 24, 2, 1);
    mp_split_nhwc<<<4096, 256>>>(c2f, p1hi, p1lo, 24, 24);
    tc_enc3<<<144, 512, 2 * TILEA + 2 * TILE>>>(
        (const uint16_t*)p1hi, (const uint16_t*)p1lo,
        (const uint16_t*)w3hi, (const uint16_t*)w3lo,
        b3, c3f, 12, 12, 12, 12, 2, 0);
    mp_nhwc<<<2048, 256>>>(c3f, zn, 12, 12);

    vq_kernel<<<BB, NT, 128 * 129 * sizeof(float)>>>(zn, dictw, valh, idx_ptr);

    tc_eng1<<<81, 512, 2 * TILEA + 2 * TILE>>>(
        (const uint16_t*)valh, (const uint16_t*)wp1, t1b, f1h, 6, 6, 9, 9, 3, 4);
    tc_t2<<<dim3(100, 1, 4), 512, 2 * TILEA + 2 * TILE>>>(
        (const uint16_t*)f1h, (const uint16_t*)wpt2, t2b, f2h);
    tc_eng1<<<576, 512, 2 * TILEA + 2 * TILE>>>(
        (const uint16_t*)f2h, (const uint16_t*)wp3, t3b, f3h, 20, 20, 24, 24, 4, 5);
    tc_eng1<<<784, 512, 2 * TILEA + 2 * TILE>>>(
        (const uint16_t*)f3h, (const uint16_t*)wp4, t4b, f4h, 24, 24, 28, 28, 4, 5);

    mu_loss<<<BB, NT>>>(f4h, x, mw, mb);
    finalize_kernel<<<1, 1>>>(loss_ptr);
}

// round 14
// speedup vs baseline: 1.0790x; 1.0790x over previous
#include <cuda_runtime.h>
#include <cuda_bf16.h>
#include <cuda_fp16.h>
#include <cstdint>

#define BB 256
#define NT 256
#define TILE 34816          // 128 rows x 272B

// ---------------- scratch (device globals; no allocation APIs) ---------------
__device__ __half g_c1hi[(size_t)BB*576*128];
__device__ __half g_c1lo[(size_t)BB*576*128];
__device__ float  g_c2f [(size_t)BB*576*128];
__device__ __half g_p1hi[(size_t)BB*144*128];
__device__ __half g_p1lo[(size_t)BB*144*128];
__device__ float  g_c3f [(size_t)BB*144*128];
__device__ float  g_zn  [(size_t)BB*36*128];
__device__ __nv_bfloat16 g_valh[(size_t)BB*36*128];
__device__ __nv_bfloat16 g_f1h[(size_t)BB*81*128];
__device__ __nv_bfloat16 g_f2h[(size_t)BB*400*128];
__device__ __nv_bfloat16 g_f3h[(size_t)BB*576*128];
__device__ __nv_bfloat16 g_f4h[(size_t)BB*784*128];
__device__ __nv_bfloat16 g_wp1[16*128*136];
__device__ __nv_bfloat16 g_wpt2[16*128*136];
__device__ __nv_bfloat16 g_wp3[25*128*136];
__device__ __nv_bfloat16 g_wp4[25*128*136];
__device__ __half g_w2hi[25*128*136];
__device__ __half g_w2lo[25*128*136];
__device__ __half g_w3hi[25*128*136];
__device__ __half g_w3lo[25*128*136];
__device__ double g_rec_sum;
__device__ double g_dict_sum;

__inline__ __device__ float warp_sum(float v) {
    #pragma unroll
    for (int o = 16; o; o >>= 1) v += __shfl_xor_sync(0xffffffffu, v, o);
    return v;
}

// ---------------- mma / cp.async helpers --------------------------------------
__device__ __forceinline__ uint32_t smem_u32(const void* p) {
    uint32_t a;
    asm("{ .reg .u64 t; cvta.to.shared.u64 t, %1; cvt.u32.u64 %0, t; }"
        : "=r"(a) : "l"(p));
    return a;
}

#define LDSM_X4(r0, r1, r2, r3, addr)                                          \
    asm volatile("ldmatrix.sync.aligned.m8n8.x4.shared.b16 {%0,%1,%2,%3}, [%4];" \
                 : "=r"(r0), "=r"(r1), "=r"(r2), "=r"(r3) : "r"(addr))

#define MMA_BF16(c, a0, a1, a2, a3, b0, b1)                                    \
    asm volatile("mma.sync.aligned.m16n8k16.row.col.f32.bf16.bf16.f32 "        \
                 "{%0,%1,%2,%3}, {%4,%5,%6,%7}, {%8,%9}, {%0,%1,%2,%3};"       \
                 : "+f"((c)[0]), "+f"((c)[1]), "+f"((c)[2]), "+f"((c)[3])      \
                 : "r"(a0), "r"(a1), "r"(a2), "r"(a3), "r"(b0), "r"(b1))

#define MMA_F16(c, a0, a1, a2, a3, b0, b1)                                     \
    asm volatile("mma.sync.aligned.m16n8k16.row.col.f32.f16.f16.f32 "          \
                 "{%0,%1,%2,%3}, {%4,%5,%6,%7}, {%8,%9}, {%0,%1,%2,%3};"       \
                 : "+f"((c)[0]), "+f"((c)[1]), "+f"((c)[2]), "+f"((c)[3])      \
                 : "r"(a0), "r"(a1), "r"(a2), "r"(a3), "r"(b0), "r"(b1))

#define CP16(d, s, n)                                                          \
    asm volatile("cp.async.cg.shared.global [%0], [%1], 16, %2;"               \
                 :: "r"(d), "l"(s), "r"(n))
#define CP_COMMIT() asm volatile("cp.async.commit_group;" ::: "memory")
#define CP_WAIT0()  asm volatile("cp.async.wait_group 0;" ::: "memory")
#define CP_WAIT1()  asm volatile("cp.async.wait_group 1;" ::: "memory")

// ---------------- fused weight prepack (all layers, one launch) ---------------
__device__ __forceinline__ void pp_fwd_split(const float* W, __half* dh, __half* dl,
                                             int tap)
{
    int ky = tap / 5, kx = tap - ky * 5;
    size_t tb = (size_t)tap * 128 * 136;
    for (int i = threadIdx.x; i < 16384; i += blockDim.x) {
        int co = i >> 7, ci = i & 127;
        float v = W[(((size_t)co * 128 + ci) * 5 + ky) * 5 + kx];
        __half h = __float2half_rn(v);
        dh[tb + co * 136 + ci] = h;
        dl[tb + co * 136 + ci] = __float2half_rn(v - __half2float(h));
    }
}

__device__ __forceinline__ void pp_deconv(const float* W, __nv_bfloat16* dst,
                                          int tap, int K)
{
    int ky = tap / K, kx = tap - ky * K;
    __nv_bfloat16* base = dst + (size_t)tap * 128 * 136;
    for (int i = threadIdx.x; i < 16384; i += blockDim.x) {
        int co = i >> 7, ci = i & 127;
        float v = W[(((size_t)ci * 128 + co) * K + (K - 1 - ky)) * K + (K - 1 - kx)];
        base[co * 136 + ci] = __float2bfloat16(v);
    }
}

__device__ __forceinline__ void pp_t2(const float* W, __nv_bfloat16* dst, int idx)
{
    int par = idx >> 2, tap = idx & 3;
    int py = par >> 1, px = par & 1;
    int ti = tap >> 1, tj = tap & 1;
    int ky = py + 2 * ti, kx = px + 2 * tj;
    __nv_bfloat16* base = dst + (size_t)idx * 128 * 136;
    for (int i = threadIdx.x; i < 16384; i += blockDim.x) {
        int co = i >> 7, ci = i & 127;
        float v = W[(((size_t)ci * 128 + co) * 4 + ky) * 4 + kx];
        base[co * 136 + ci] = __float2bfloat16(v);
    }
}

__global__ void prepack_all(const float* w2, const float* w3,
                            const float* t1w, const float* t2w,
                            const float* t3w, const float* t4w,
                            __half* w2hi, __half* w2lo,
                            __half* w3hi, __half* w3lo,
                            __nv_bfloat16* wp1, __nv_bfloat16* wpt2,
                            __nv_bfloat16* wp3, __nv_bfloat16* wp4)
{
    int bid = blockIdx.x;
    if (bid == 0 && threadIdx.x == 0) { g_rec_sum = 0.0; g_dict_sum = 0.0; }
    if      (bid < 25)  pp_fwd_split(w2, w2hi, w2lo, bid);
    else if (bid < 50)  pp_fwd_split(w3, w3hi, w3lo, bid - 25);
    else if (bid < 66)  pp_deconv(t1w, wp1, bid - 50, 4);
    else if (bid < 82)  pp_t2(t2w, wpt2, bid - 66);
    else if (bid < 107) pp_deconv(t3w, wp3, bid - 82, 5);
    else                pp_deconv(t4w, wp4, bid - 107, 5);
}

// ====== fused 3-pass fp16-split encoder conv, M=128, 2 CTAs/SM ================
// SMEM: A TILE + Bhi TILE + Blo TILE = 104448 B. Per-CTA staging exposed;
// covered by the co-resident CTA's MMA stream.
__global__ void __launch_bounds__(256, 2)
tc_enc3(const uint16_t* __restrict__ inHi, const uint16_t* __restrict__ inLo,
        const uint16_t* __restrict__ wHi,  const uint16_t* __restrict__ wLo,
        const float* __restrict__ bias, float* __restrict__ outp,
        int Hin, int Win, int Hout, int Wout, int pad, int relu)
{
    extern __shared__ char dsm[];
    __shared__ float sbias[128];
    const int tid  = threadIdx.x;
    const int wid  = tid >> 5;
    const int lane = tid & 31;
    const int Npix = Hout * Wout;
    const int totalPx = BB * Npix;
    const int pbase = blockIdx.x * 128;

    const uint32_t smA   = smem_u32(dsm);
    const uint32_t smBhi = smA + TILE;
    const uint32_t smBlo = smBhi + TILE;
    if (tid < 128) sbias[tid] = bias[tid];

    const int arow = tid >> 1, ahalf = tid & 1;
    const int ap = pbase + arow;
    const bool apv = (ap < totalPx);
    const int bA  = apv ? ap / Npix : 0;
    const int apn = apv ? ap - bA * Npix : 0;
    const int apy = apn / Wout;
    const int apx = apn - apy * Wout;
    const uint32_t adst0 = smA + arow * 272 + ahalf * 128;

    const int pxg = wid >> 1, cog = wid & 1;
    float acc[2][8][4];
    #pragma unroll
    for (int m = 0; m < 2; m++)
        #pragma unroll
        for (int n = 0; n < 8; n++)
            #pragma unroll
            for (int j = 0; j < 4; j++) acc[m][n][j] = 0.f;

    const uint32_t a_rd0 = smA + (pxg * 32 + (lane & 15)) * 272 + ((lane >> 4) << 4);
    const uint32_t b_rdb = (cog * 64 + ((lane >> 4) << 3) + (lane & 7)) * 272
                         + (((lane >> 3) & 1) << 4);

    auto stage_A = [&](int it) {
        const int tap = (it < 25) ? it : it - 25;
        const uint16_t* abuf = (it < 25) ? inHi : inLo;
        const int ky = tap / 5, kx = tap - ky * 5;
        const int iy = apy + ky - pad, ix = apx + kx - pad;
        const bool inb = apv && (unsigned)iy < (unsigned)Hin && (unsigned)ix < (unsigned)Win;
        const char* as = inb ? (const char*)(abuf + ((size_t)(bA * Hin + iy) * Win + ix) * 128
                                             + ahalf * 64)
                             : (const char*)abuf;
        const int sz = inb ? 16 : 0;
        #pragma unroll
        for (int j = 0; j < 8; ++j)
            CP16(adst0 + j * 16, as + (size_t)j * 16, sz);
    };

    auto stage_Btile = [&](const uint16_t* wbuf, int tap, uint32_t bd) {
        const char* wb = (const char*)(wbuf + (size_t)tap * 128 * 136);
        #pragma unroll
        for (int j = 0; j < 8; ++j)
            CP16(bd + (j * 256 + tid) * 16, wb + (size_t)(j * 256 + tid) * 16, 16);
        if (tid < 128)
            CP16(bd + (2048 + tid) * 16, wb + (size_t)(2048 + tid) * 16, 16);
    };

    for (int it = 0; it < 50; ++it) {
        const int tap = (it < 25) ? it : it - 25;
        const int ph  = (it < 25) ? 0 : 1;
        __syncthreads();                    // protect prev-iteration reads
        stage_A(it);
        stage_Btile(wHi, tap, smBhi);
        if (ph == 0) stage_Btile(wLo, tap, smBlo);
        CP_COMMIT();
        CP_WAIT0();
        __syncthreads();

        #pragma unroll
        for (int ks = 0; ks < 8; ++ks) {
            uint32_t a[2][4], bq[4][4];
            #pragma unroll
            for (int i = 0; i < 2; ++i)
                LDSM_X4(a[i][0], a[i][1], a[i][2], a[i][3],
                        a_rd0 + i * 16 * 272 + ks * 32);
            #pragma unroll
            for (int nb = 0; nb < 4; ++nb)
                LDSM_X4(bq[nb][0], bq[nb][1], bq[nb][2], bq[nb][3],
                        smBhi + b_rdb + nb * 16 * 272 + ks * 32);
            #pragma unroll
            for (int nb = 0; nb < 4; ++nb)
                #pragma unroll
                for (int i = 0; i < 2; ++i) {
                    MMA_F16(acc[i][2 * nb],     a[i][0], a[i][1], a[i][2], a[i][3],
                            bq[nb][0], bq[nb][1]);
                    MMA_F16(acc[i][2 * nb + 1], a[i][0], a[i][1], a[i][2], a[i][3],
                            bq[nb][2], bq[nb][3]);
                }
            if (ph == 0) {
                #pragma unroll
                for (int nb = 0; nb < 4; ++nb)
                    LDSM_X4(bq[nb][0], bq[nb][1], bq[nb][2], bq[nb][3],
                            smBlo + b_rdb + nb * 16 * 272 + ks * 32);
                #pragma unroll
                for (int nb = 0; nb < 4; ++nb)
                    #pragma unroll
                    for (int i = 0; i < 2; ++i) {
                        MMA_F16(acc[i][2 * nb],     a[i][0], a[i][1], a[i][2], a[i][3],
                                bq[nb][0], bq[nb][1]);
                        MMA_F16(acc[i][2 * nb + 1], a[i][0], a[i][1], a[i][2], a[i][3],
                                bq[nb][2], bq[nb][3]);
                    }
            }
        }
    }

    #pragma unroll
    for (int mb = 0; mb < 2; ++mb) {
        const int row0 = pbase + pxg * 32 + mb * 16 + (lane >> 2);
        const int row1 = row0 + 8;
        const bool v0 = (row0 < totalPx), v1 = (row1 < totalPx);
        #pragma unroll
        for (int nt = 0; nt < 8; ++nt) {
            const int co = cog * 64 + nt * 8 + 2 * (lane & 3);
            const float bz0 = sbias[co], bz1 = sbias[co + 1];
            float p00 = acc[mb][nt][0] + bz0, p01 = acc[mb][nt][1] + bz1;
            float p10 = acc[mb][nt][2] + bz0, p11 = acc[mb][nt][3] + bz1;
            if (relu) {
                p00 = fmaxf(p00, 0.f); p01 = fmaxf(p01, 0.f);
                p10 = fmaxf(p10, 0.f); p11 = fmaxf(p11, 0.f);
            }
            if (v0) *(float2*)(outp + (size_t)row0 * 128 + co) = make_float2(p00, p01);
            if (v1) *(float2*)(outp + (size_t)row1 * 128 + co) = make_float2(p10, p11);
        }
    }
}

// ====== 1-pass bf16 engine, M=128, 2 CTAs/SM, A double + B single =============
__global__ void __launch_bounds__(256, 2)
tc_eng1(const uint16_t* __restrict__ in, const uint16_t* __restrict__ wpack,
        const float* __restrict__ bias, __nv_bfloat16* __restrict__ outp,
        int Hin, int Win, int Hout, int Wout, int pad, int K)
{
    extern __shared__ char dsm[];
    __shared__ float sbias[128];
    const int tid  = threadIdx.x;
    const int wid  = tid >> 5;
    const int lane = tid & 31;
    const int Npix = Hout * Wout;
    const int totalPx = BB * Npix;
    const int pbase = blockIdx.x * 128;

    const uint32_t smA = smem_u32(dsm);      // 2 x TILE
    const uint32_t smB = smA + 2 * TILE;     // 1 x TILE
    if (tid < 128) sbias[tid] = bias[tid];

    const int arow = tid >> 1, ahalf = tid & 1;
    const int ap = pbase + arow;
    const bool apv = (ap < totalPx);
    const int bA  = apv ? ap / Npix : 0;
    const int apn = apv ? ap - bA * Npix : 0;
    const int apy = apn / Wout;
    const int apx = apn - apy * Wout;
    const uint32_t adst0 = smA + arow * 272 + ahalf * 128;

    const int pxg = wid >> 1, cog = wid & 1;
    float acc[2][8][4];
    #pragma unroll
    for (int m = 0; m < 2; m++)
        #pragma unroll
        for (int n = 0; n < 8; n++)
            #pragma unroll
            for (int j = 0; j < 4; j++) acc[m][n][j] = 0.f;

    const uint32_t a_rd0 = smA + (pxg * 32 + (lane & 15)) * 272 + ((lane >> 4) << 4);
    const uint32_t b_rdb = smB + (cog * 64 + ((lane >> 4) << 3) + (lane & 7)) * 272
                         + (((lane >> 3) & 1) << 4);
    const int NIT = K * K;

    auto stage_A = [&](int it) {
        const int ky = it / K, kx = it - (it / K) * K;
        const int iy = apy + ky - pad, ix = apx + kx - pad;
        const bool inb = apv && (unsigned)iy < (unsigned)Hin && (unsigned)ix < (unsigned)Win;
        const char* as = inb ? (const char*)(in + ((size_t)(bA * Hin + iy) * Win + ix) * 128
                                             + ahalf * 64)
                             : (const char*)in;
        const uint32_t ad = adst0 + (it & 1) * TILE;
        const int sz = inb ? 16 : 0;
        #pragma unroll
        for (int j = 0; j < 8; ++j)
            CP16(ad + j * 16, as + (size_t)j * 16, sz);
    };

    auto stage_B = [&](int tap) {
        const char* wb = (const char*)(wpack + (size_t)tap * 128 * 136);
        #pragma unroll
        for (int j = 0; j < 8; ++j)
            CP16(smB + (j * 256 + tid) * 16, wb + (size_t)(j * 256 + tid) * 16, 16);
        if (tid < 128)
            CP16(smB + (2048 + tid) * 16, wb + (size_t)(2048 + tid) * 16, 16);
    };

    stage_A(0);
    CP_COMMIT();
    for (int it = 0; it < NIT; ++it) {
        stage_B(it);
        CP_COMMIT();
        if (it + 1 < NIT) {
            stage_A(it + 1);
            CP_COMMIT();
            CP_WAIT1();                 // A(it) + B(it) complete
        } else {
            CP_WAIT0();
        }
        __syncthreads();
        const uint32_t abase = (it & 1) * TILE;
        #pragma unroll
        for (int ks = 0; ks < 8; ++ks) {
            uint32_t a[2][4], bq[4][4];
            #pragma unroll
            for (int i = 0; i < 2; ++i)
                LDSM_X4(a[i][0], a[i][1], a[i][2], a[i][3],
                        a_rd0 + abase + i * 16 * 272 + ks * 32);
            #pragma unroll
            for (int nb = 0; nb < 4; ++nb)
                LDSM_X4(bq[nb][0], bq[nb][1], bq[nb][2], bq[nb][3],
                        b_rdb + nb * 16 * 272 + ks * 32);
            #pragma unroll
            for (int nb = 0; nb < 4; ++nb)
                #pragma unroll
                for (int i = 0; i < 2; ++i) {
                    MMA_BF16(acc[i][2 * nb],     a[i][0], a[i][1], a[i][2], a[i][3],
                             bq[nb][0], bq[nb][1]);
                    MMA_BF16(acc[i][2 * nb + 1], a[i][0], a[i][1], a[i][2], a[i][3],
                             bq[nb][2], bq[nb][3]);
                }
        }
        __syncthreads();                // protect single-buffered B
    }

    #pragma unroll
    for (int mb = 0; mb < 2; ++mb) {
        const int row0 = pbase + pxg * 32 + mb * 16 + (lane >> 2);
        const int row1 = row0 + 8;
        const bool v0 = (row0 < totalPx), v1 = (row1 < totalPx);
        #pragma unroll
        for (int nt = 0; nt < 8; ++nt) {
            const int co = cog * 64 + nt * 8 + 2 * (lane & 3);
            const float bz0 = sbias[co], bz1 = sbias[co + 1];
            float p00 = fmaxf(acc[mb][nt][0] + bz0, 0.f);
            float p01 = fmaxf(acc[mb][nt][1] + bz1, 0.f);
            float p10 = fmaxf(acc[mb][nt][2] + bz0, 0.f);
            float p11 = fmaxf(acc[mb][nt][3] + bz1, 0.f);
            if (v0) {
                __nv_bfloat162 h = __floats2bfloat162_rn(p00, p01);
                *(uint32_t*)(outp + (size_t)row0 * 128 + co) = *reinterpret_cast<uint32_t*>(&h);
            }
            if (v1) {
                __nv_bfloat162 h = __floats2bfloat162_rn(p10, p11);
                *(uint32_t*)(outp + (size_t)row1 * 128 + co) = *reinterpret_cast<uint32_t*>(&h);
            }
        }
    }
}

// ====== t2 stride-2 deconv, parity decomposition, M=128, 2 CTAs/SM ============
__global__ void __launch_bounds__(256, 2)
tc_t2(const uint16_t* __restrict__ in, const uint16_t* __restrict__ wpack,
      const float* __restrict__ bias, __nv_bfloat16* __restrict__ outp)
{
    extern __shared__ char dsm[];
    __shared__ float sbias[128];
    const int tid  = threadIdx.x;
    const int wid  = tid >> 5;
    const int lane = tid & 31;
    const int par  = blockIdx.z;
    const int py   = par >> 1, px = par & 1;
    const int totalPx = BB * 100;
    const int pbase = blockIdx.x * 128;

    const uint32_t smA = smem_u32(dsm);
    const uint32_t smB = smA + 2 * TILE;
    if (tid < 128) sbias[tid] = bias[tid];

    const int arow = tid >> 1, ahalf = tid & 1;
    const int ap = pbase + arow;
    const bool apv = (ap < totalPx);
    const int bA  = apv ? ap / 100 : 0;
    const int apn = apv ? ap - bA * 100 : 0;
    const int apy = apn / 10;
    const int apx = apn - apy * 10;
    const uint32_t adst0 = smA + arow * 272 + ahalf * 128;

    const int pxg = wid >> 1, cog = wid & 1;
    float acc[2][8][4];
    #pragma unroll
    for (int m = 0; m < 2; m++)
        #pragma unroll
        for (int n = 0; n < 8; n++)
            #pragma unroll
            for (int j = 0; j < 4; j++) acc[m][n][j] = 0.f;

    const uint32_t a_rd0 = smA + (pxg * 32 + (lane & 15)) * 272 + ((lane >> 4) << 4);
    const uint32_t b_rdb = smB + (cog * 64 + ((lane >> 4) << 3) + (lane & 7)) * 272
                         + (((lane >> 3) & 1) << 4);

    auto stage_A = [&](int tap) {
        const int ti = tap >> 1, tj = tap & 1;
        const int iy = apy - ti, ix = apx - tj;
        const bool inb = apv && (unsigned)iy < 9u && (unsigned)ix < 9u;
        const char* as = inb ? (const char*)(in + ((size_t)(bA * 9 + iy) * 9 + ix) * 128
                                             + ahalf * 64)
                             : (const char*)in;
        const uint32_t ad = adst0 + (tap & 1) * TILE;
        const int sz = inb ? 16 : 0;
        #pragma unroll
        for (int j = 0; j < 8; ++j)
            CP16(ad + j * 16, as + (size_t)j * 16, sz);
    };

    auto stage_B = [&](int tap) {
        const char* wb = (const char*)(wpack + (size_t)(par * 4 + tap) * 128 * 136);
        #pragma unroll
        for (int j = 0; j < 8; ++j)
            CP16(smB + (j * 256 + tid) * 16, wb + (size_t)(j * 256 + tid) * 16, 16);
        if (tid < 128)
            CP16(smB + (2048 + tid) * 16, wb + (size_t)(2048 + tid) * 16, 16);
    };

    stage_A(0);
    CP_COMMIT();
    for (int it = 0; it < 4; ++it) {
        stage_B(it);
        CP_COMMIT();
        if (it + 1 < 4) {
            stage_A(it + 1);
            CP_COMMIT();
            CP_WAIT1();
        } else {
            CP_WAIT0();
        }
        __syncthreads();
        const uint32_t abase = (it & 1) * TILE;
        #pragma unroll
        for (int ks = 0; ks < 8; ++ks) {
            uint32_t a[2][4], bq[4][4];
            #pragma unroll
            for (int i = 0; i < 2; ++i)
                LDSM_X4(a[i][0], a[i][1], a[i][2], a[i][3],
                        a_rd0 + abase + i * 16 * 272 + ks * 32);
            #pragma unroll
            for (int nb = 0; nb < 4; ++nb)
                LDSM_X4(bq[nb][0], bq[nb][1], bq[nb][2], bq[nb][3],
                        b_rdb + nb * 16 * 272 + ks * 32);
            #pragma unroll
            for (int nb = 0; nb < 4; ++nb)
                #pragma unroll
                for (int i = 0; i < 2; ++i) {
                    MMA_BF16(acc[i][2 * nb],     a[i][0], a[i][1], a[i][2], a[i][3],
                             bq[nb][0], bq[nb][1]);
                    MMA_BF16(acc[i][2 * nb + 1], a[i][0], a[i][1], a[i][2], a[i][3],
                             bq[nb][2], bq[nb][3]);
                }
        }
        __syncthreads();
    }

    #pragma unroll
    for (int mb = 0; mb < 2; ++mb) {
        const int r0g = pbase + pxg * 32 + mb * 16 + (lane >> 2);
        const int r1g = r0g + 8;
        int b0 = r0g / 100, q0 = r0g - b0 * 100, y0 = q0 / 10, x0 = q0 - y0 * 10;
        int b1 = r1g / 100, q1 = r1g - b1 * 100, y1 = q1 / 10, x1 = q1 - y1 * 10;
        size_t o0 = ((size_t)b0 * 400 + (2 * y0 + py) * 20 + 2 * x0 + px) * 128;
        size_t o1 = ((size_t)b1 * 400 + (2 * y1 + py) * 20 + 2 * x1 + px) * 128;
        #pragma unroll
        for (int nt = 0; nt < 8; ++nt) {
            const int co = cog * 64 + nt * 8 + 2 * (lane & 3);
            const float bz0 = sbias[co], bz1 = sbias[co + 1];
            float p00 = fmaxf(acc[mb][nt][0] + bz0, 0.f);
            float p01 = fmaxf(acc[mb][nt][1] + bz1, 0.f);
            float p10 = fmaxf(acc[mb][nt][2] + bz0, 0.f);
            float p11 = fmaxf(acc[mb][nt][3] + bz1, 0.f);
            if (r0g < totalPx) {
                __nv_bfloat162 h = __floats2bfloat162_rn(p00, p01);
                *(uint32_t*)(outp + o0 + co) = *reinterpret_cast<uint32_t*>(&h);
            }
            if (r1g < totalPx) {
                __nv_bfloat162 h = __floats2bfloat162_rn(p10, p11);
                *(uint32_t*)(outp + o1 + co) = *reinterpret_cast<uint32_t*>(&h);
            }
        }
    }
}

// ---------------- conv1: 8 px/block, weights in registers ---------------------
__global__ void __launch_bounds__(128)
conv1_split(const float* __restrict__ x, const float* __restrict__ w1,
            const float* __restrict__ b1, __half* __restrict__ hi,
            __half* __restrict__ lo)
{
    const int b = blockIdx.x, g = blockIdx.y;
    const int p0 = g * 8;
    const int oy = p0 / 24, ox0 = p0 - oy * 24;
    const int co = threadIdx.x;
    __shared__ float xs[5][12];
    for (int i = co; i < 60; i += 128) {
        int r = i / 12, c = i - r * 12;
        xs[r][c] = x[(size_t)b * 784 + (oy + r) * 28 + ox0 + c];
    }
    __syncthreads();
    float w[25];
    #pragma unroll
    for (int t = 0; t < 25; ++t) w[t] = w1[co * 25 + t];
    const float bz = b1[co];
    #pragma unroll
    for (int px = 0; px < 8; ++px) {
        float v = bz;
        #pragma unroll
        for (int t = 0; t < 25; ++t)
            v += w[t] * xs[t / 5][t % 5 + px];
        v = fmaxf(v, 0.f);
        __half h = __float2half_rn(v);
        size_t o = ((size_t)b * 576 + p0 + px) * 128 + co;
        hi[o] = h;
        lo[o] = __float2half_rn(v - __half2float(h));
    }
}

// ---------------- NHWC maxpool 2x2: fp32 -> fp16 hi/lo -----------------------
__global__ void mp_split_nhwc(const float* __restrict__ in, __half* __restrict__ hi,
                              __half* __restrict__ lo, int Hin, int Win)
{
    const int Ho = Hin >> 1, Wo = Win >> 1;
    const size_t total = (size_t)BB * Ho * Wo * 128;
    for (size_t i = (size_t)blockIdx.x * blockDim.x + threadIdx.x; i < total;
         i += (size_t)gridDim.x * blockDim.x) {
        int c = (int)(i & 127);
        size_t r = i >> 7;
        int wo = (int)(r % Wo); r /= Wo;
        int ho = (int)(r % Ho); int b = (int)(r / Ho);
        const float* p = in + (((size_t)b * Hin + 2 * ho) * Win + 2 * wo) * 128 + c;
        float v = fmaxf(fmaxf(p[0], p[128]),
                        fmaxf(p[(size_t)Win * 128], p[(size_t)(Win + 1) * 128]));
        __half h = __float2half_rn(v);
        hi[i] = h;
        lo[i] = __float2half_rn(v - __half2float(h));
    }
}

// ---------------- NHWC maxpool 2x2: fp32 -> fp32 -----------------------------
__global__ void mp_nhwc(const float* __restrict__ in, float* __restrict__ out,
                        int Hin, int Win)
{
    const int Ho = Hin >> 1, Wo = Win >> 1;
    const size_t total = (size_t)BB * Ho * Wo * 128;
    for (size_t i = (size_t)blockIdx.x * blockDim.x + threadIdx.x; i < total;
         i += (size_t)gridDim.x * blockDim.x) {
        int c = (int)(i & 127);
        size_t r = i >> 7;
        int wo = (int)(r % Wo); r /= Wo;
        int ho = (int)(r % Ho); int b = (int)(r / Ho);
        const float* p = in + (((size_t)b * Hin + 2 * ho) * Win + 2 * wo) * 128 + c;
        out[i] = fmaxf(fmaxf(p[0], p[128]),
                       fmaxf(p[(size_t)Win * 128], p[(size_t)(Win + 1) * 128]));
    }
}

// ---------------- VQ: argmax(d2), gather val (NHWC bf16), dict MSE ------------
__global__ void __launch_bounds__(256)
vq_kernel(const float* __restrict__ z, const float* __restrict__ dict,
          __nv_bfloat16* __restrict__ valh, float* __restrict__ idx_out)
{
    extern __shared__ float dsmf[];
    __shared__ float zt[36 * 128];
    __shared__ float wn[128];
    __shared__ int   sidx[36];

    const int b = blockIdx.x, tid = threadIdx.x;

    for (int i = tid; i < 128 * 128; i += NT) {
        int k = i >> 7; int c = i & 127;
        dsmf[k * 129 + c] = dict[i];
    }
    for (int i = tid; i < 36 * 128; i += NT)
        zt[i] = z[(size_t)b * 4608 + i];
    __syncthreads();
    if (tid < 128) {
        float s = 0.f;
        const float* dp = dsmf + tid * 129;
        for (int c = 0; c < 128; c++) s += dp[c] * dp[c];
        wn[tid] = s;
    }
    __syncthreads();

    const int lane = tid & 31, wid = tid >> 5;
    for (int pos = wid; pos < 36; pos += 8) {
        float d0 = 0.f, d1 = 0.f, d2s = 0.f, d3 = 0.f, zn = 0.f;
        const float* zp = zt + pos * 128;
        const float* p0 = dsmf + (lane      ) * 129;
        const float* p1 = dsmf + (lane + 32 ) * 129;
        const float* p2 = dsmf + (lane + 64 ) * 129;
        const float* p3 = dsmf + (lane + 96 ) * 129;
        for (int c = 0; c < 128; c++) {
            float zv = zp[c];
            zn += zv * zv;
            d0 += p0[c] * zv; d1 += p1[c] * zv;
            d2s += p2[c] * zv; d3 += p3[c] * zv;
        }
        float bv = zn + wn[lane] - 2.f * d0; int bk = lane;
        float v1 = zn + wn[lane + 32] - 2.f * d1; if (v1 > bv) { bv = v1; bk = lane + 32; }
        float v2 = zn + wn[lane + 64] - 2.f * d2s; if (v2 > bv) { bv = v2; bk = lane + 64; }
        float v3 = zn + wn[lane + 96] - 2.f * d3; if (v3 > bv) { bv = v3; bk = lane + 96; }
        #pragma unroll
        for (int o = 16; o; o >>= 1) {
            float ov = __shfl_xor_sync(0xffffffffu, bv, o);
            int   ok = __shfl_xor_sync(0xffffffffu, bk, o);
            if (ov > bv || (ov == bv && ok < bk)) { bv = ov; bk = ok; }
        }
        if (lane == 0) {
            sidx[pos] = bk;
            if (idx_out) idx_out[b * 36 + pos] = (float)bk;
        }
    }
    __syncthreads();

    float lsum = 0.f;
    for (int i = tid; i < 4608; i += NT) {
        int pos = i >> 7; int c = i & 127;
        float v  = dsmf[sidx[pos] * 129 + c];
        float zv = zt[i];
        valh[(size_t)b * 4608 + i] = __float2bfloat16(v);
        float d = v - zv;
        lsum += d * d;
    }
    lsum = warp_sum(lsum);
    if ((tid & 31) == 0) atomicAdd(&g_dict_sum, (double)lsum);
}

// ---------------- mu (1x1 conv) fused with reconstruction loss (NHWC bf16) ---
__global__ void __launch_bounds__(256)
mu_loss(const __nv_bfloat16* __restrict__ f4, const float* __restrict__ x,
        const float* __restrict__ mw, const float* __restrict__ mb)
{
    __shared__ float mws[128];
    const int b = blockIdx.x, tid = threadIdx.x;
    if (tid < 128) mws[tid] = mw[tid];
    __syncthreads();
    float lsum = 0.f;
    for (int px = tid; px < 784; px += NT) {
        const uint4* fp = (const uint4*)(f4 + ((size_t)b * 784 + px) * 128);
        float s = mb[0];
        #pragma unroll
        for (int j = 0; j < 16; j++) {
            uint4 v = fp[j];
            const __nv_bfloat16* h = (const __nv_bfloat16*)&v;
            #pragma unroll
            for (int t = 0; t < 8; t++)
                s += __bfloat162float(h[t]) * mws[j * 8 + t];
        }
        float d = s - x[(size_t)b * 784 + px];
        lsum += d * d;
    }
    lsum = warp_sum(lsum);
    if ((tid & 31) == 0) atomicAdd(&g_rec_sum, (double)lsum);
}

__global__ void finalize_kernel(float* loss_out)
{
    if (loss_out) {
        double dict_mse = g_dict_sum / 1179648.0;
        loss_out[0] = (float)(g_rec_sum / 200704.0);
        loss_out[1] = (float)(dict_mse * 5.0);
        loss_out[2] = (float)(dict_mse * 1.25);
        loss_out[3] = 0.f;
    }
}

// ---------------- host side ----------------------------------------------------
extern "C" void kernel_launch(void* const* d_in, const int* in_sizes, int n_in,
                              void* d_out, int out_size)
{
    const float* x    = (const float*)d_in[0];
    const float* w1   = (const float*)d_in[1];
    const float* b1   = (const float*)d_in[2];
    const float* w2   = (const float*)d_in[3];
    const float* b2   = (const float*)d_in[4];
    const float* w3   = (const float*)d_in[5];
    const float* b3   = (const float*)d_in[6];
    const float* t1w  = (const float*)d_in[7];
    const float* t1b  = (const float*)d_in[8];
    const float* t2w  = (const float*)d_in[9];
    const float* t2b  = (const float*)d_in[10];
    const float* t3w  = (const float*)d_in[11];
    const float* t3b  = (const float*)d_in[12];
    const float* t4w  = (const float*)d_in[13];
    const float* t4b  = (const float*)d_in[14];
    const float* mw   = (const float*)d_in[15];
    const float* mb   = (const float*)d_in[16];
    const float* dictw= (const float*)d_in[17];

    float* outp = (float*)d_out;
    float* loss_ptr = outp;
    float* idx_ptr  = outp + 4;
    if (out_size < 9220) { loss_ptr = nullptr; idx_ptr = outp; }

    __half *c1hi, *c1lo, *p1hi, *p1lo, *w2hi, *w2lo, *w3hi, *w3lo;
    float *c2f, *c3f, *zn;
    __nv_bfloat16 *valh, *f1h, *f2h, *f3h, *f4h, *wp1, *wpt2, *wp3, *wp4;
    cudaGetSymbolAddress((void**)&c1hi, g_c1hi);
    cudaGetSymbolAddress((void**)&c1lo, g_c1lo);
    cudaGetSymbolAddress((void**)&c2f,  g_c2f);
    cudaGetSymbolAddress((void**)&p1hi, g_p1hi);
    cudaGetSymbolAddress((void**)&p1lo, g_p1lo);
    cudaGetSymbolAddress((void**)&c3f,  g_c3f);
    cudaGetSymbolAddress((void**)&zn,   g_zn);
    cudaGetSymbolAddress((void**)&valh, g_valh);
    cudaGetSymbolAddress((void**)&f1h,  g_f1h);
    cudaGetSymbolAddress((void**)&f2h,  g_f2h);
    cudaGetSymbolAddress((void**)&f3h,  g_f3h);
    cudaGetSymbolAddress((void**)&f4h,  g_f4h);
    cudaGetSymbolAddress((void**)&wp1,  g_wp1);
    cudaGetSymbolAddress((void**)&wpt2, g_wpt2);
    cudaGetSymbolAddress((void**)&wp3,  g_wp3);
    cudaGetSymbolAddress((void**)&wp4,  g_wp4);
    cudaGetSymbolAddress((void**)&w2hi, g_w2hi);
    cudaGetSymbolAddress((void**)&w2lo, g_w2lo);
    cudaGetSymbolAddress((void**)&w3hi, g_w3hi);
    cudaGetSymbolAddress((void**)&w3lo, g_w3lo);

    static bool attr_set = false;
    if (!attr_set) {
        cudaFuncSetAttribute(vq_kernel, cudaFuncAttributeMaxDynamicSharedMemorySize,
                             128 * 129 * (int)sizeof(float));
        cudaFuncSetAttribute(tc_eng1, cudaFuncAttributeMaxDynamicSharedMemorySize,
                             3 * TILE);
        cudaFuncSetAttribute(tc_t2, cudaFuncAttributeMaxDynamicSharedMemorySize,
                             3 * TILE);
        cudaFuncSetAttribute(tc_enc3, cudaFuncAttributeMaxDynamicSharedMemorySize,
                             3 * TILE);
        attr_set = true;
    }

    prepack_all<<<132, 256>>>(w2, w3, t1w, t2w, t3w, t4w,
                              w2hi, w2lo, w3hi, w3lo, wp1, wpt2, wp3, wp4);
    conv1_split<<<dim3(BB, 72), 128>>>(x, w1, b1, c1hi, c1lo);
    tc_enc3<<<1152, 256, 3 * TILE>>>(
        (const uint16_t*)c1hi, (const uint16_t*)c1lo,
        (const uint16_t*)w2hi, (const uint16_t*)w2lo,
        b2, c2f, 24, 24, 24, 24, 2, 1);
    mp_split_nhwc<<<4096, 256>>>(c2f, p1hi, p1lo, 24, 24);
    tc_enc3<<<288, 256, 3 * TILE>>>(
        (const uint16_t*)p1hi, (const uint16_t*)p1lo,
        (const uint16_t*)w3hi, (const uint16_t*)w3lo,
        b3, c3f, 12, 12, 12, 12, 2, 0);
    mp_nhwc<<<2048, 256>>>(c3f, zn, 12, 12);

    vq_kernel<<<BB, NT, 128 * 129 * sizeof(float)>>>(zn, dictw, valh, idx_ptr);

    tc_eng1<<<162, 256, 3 * TILE>>>(
        (const uint16_t*)valh, (const uint16_t*)wp1, t1b, f1h, 6, 6, 9, 9, 3, 4);
    tc_t2<<<dim3(200, 1, 4), 256, 3 * TILE>>>(
        (const uint16_t*)f1h, (const uint16_t*)wpt2, t2b, f2h);
    tc_eng1<<<1152, 256, 3 * TILE>>>(
        (const uint16_t*)f2h, (const uint16_t*)wp3, t3b, f3h, 20, 20, 24, 24, 4, 5);
    tc_eng1<<<1568, 256, 3 * TILE>>>(
        (const uint16_t*)f3h, (const uint16_t*)wp4, t4b, f4h, 24, 24, 28, 28, 4, 5);

    mu_loss<<<BB, NT>>>(f4h, x, mw, mb);
    finalize_kernel<<<1, 1>>>(loss_ptr);
}

// round 15
// speedup vs baseline: 1.1070x; 1.0259x over previous
#include <cuda_runtime.h>
#include <cuda_bf16.h>
#include <cuda_fp16.h>
#include <cstdint>

#define BB 256
#define NT 256
#define TILE 34816          // 128 rows x 272B

// ---------------- scratch (device globals; no allocation APIs) ---------------
__device__ __half g_c1hi[(size_t)BB*576*128];
__device__ __half g_c1lo[(size_t)BB*576*128];
__device__ float  g_c2f [(size_t)BB*576*128];
__device__ __half g_p1hi[(size_t)BB*144*128];
__device__ __half g_p1lo[(size_t)BB*144*128];
__device__ float  g_c3f [(size_t)BB*144*128];
__device__ float  g_zn  [(size_t)BB*36*128];
__device__ __nv_bfloat16 g_valh[(size_t)BB*36*128];
__device__ __nv_bfloat16 g_f1h[(size_t)BB*81*128];
__device__ __nv_bfloat16 g_f2h[(size_t)BB*400*128];
__device__ __nv_bfloat16 g_f3h[(size_t)BB*576*128];
__device__ __nv_bfloat16 g_f4h[(size_t)BB*784*128];
__device__ __nv_bfloat16 g_wp1[16*128*136];
__device__ __nv_bfloat16 g_wpt2[16*128*136];
__device__ __nv_bfloat16 g_wp3[25*128*136];
__device__ __nv_bfloat16 g_wp4[25*128*136];
__device__ __half g_w2hi[25*128*136];
__device__ __half g_w2lo[25*128*136];
__device__ __half g_w3hi[25*128*136];
__device__ __half g_w3lo[25*128*136];
__device__ double g_rec_sum;
__device__ double g_dict_sum;

__inline__ __device__ float warp_sum(float v) {
    #pragma unroll
    for (int o = 16; o; o >>= 1) v += __shfl_xor_sync(0xffffffffu, v, o);
    return v;
}

// ---------------- mma / cp.async helpers --------------------------------------
__device__ __forceinline__ uint32_t smem_u32(const void* p) {
    uint32_t a;
    asm("{ .reg .u64 t; cvta.to.shared.u64 t, %1; cvt.u32.u64 %0, t; }"
        : "=r"(a) : "l"(p));
    return a;
}

#define LDSM_X4(r0, r1, r2, r3, addr)                                          \
    asm volatile("ldmatrix.sync.aligned.m8n8.x4.shared.b16 {%0,%1,%2,%3}, [%4];" \
                 : "=r"(r0), "=r"(r1), "=r"(r2), "=r"(r3) : "r"(addr))

#define MMA_BF16(c, a0, a1, a2, a3, b0, b1)                                    \
    asm volatile("mma.sync.aligned.m16n8k16.row.col.f32.bf16.bf16.f32 "        \
                 "{%0,%1,%2,%3}, {%4,%5,%6,%7}, {%8,%9}, {%0,%1,%2,%3};"       \
                 : "+f"((c)[0]), "+f"((c)[1]), "+f"((c)[2]), "+f"((c)[3])      \
                 : "r"(a0), "r"(a1), "r"(a2), "r"(a3), "r"(b0), "r"(b1))

#define MMA_F16(c, a0, a1, a2, a3, b0, b1)                                     \
    asm volatile("mma.sync.aligned.m16n8k16.row.col.f32.f16.f16.f32 "          \
                 "{%0,%1,%2,%3}, {%4,%5,%6,%7}, {%8,%9}, {%0,%1,%2,%3};"       \
                 : "+f"((c)[0]), "+f"((c)[1]), "+f"((c)[2]), "+f"((c)[3])      \
                 : "r"(a0), "r"(a1), "r"(a2), "r"(a3), "r"(b0), "r"(b1))

#define CP16(d, s, n)                                                          \
    asm volatile("cp.async.cg.shared.global [%0], [%1], 16, %2;"               \
                 :: "r"(d), "l"(s), "r"(n))
#define CP_COMMIT() asm volatile("cp.async.commit_group;" ::: "memory")
#define CP_WAIT0()  asm volatile("cp.async.wait_group 0;" ::: "memory")
#define CP_WAIT1()  asm volatile("cp.async.wait_group 1;" ::: "memory")

// ---------------- fused weight prepack (all layers, one launch) ---------------
__device__ __forceinline__ void pp_fwd_split(const float* W, __half* dh, __half* dl,
                                             int tap)
{
    int ky = tap / 5, kx = tap - ky * 5;
    size_t tb = (size_t)tap * 128 * 136;
    for (int i = threadIdx.x; i < 16384; i += blockDim.x) {
        int co = i >> 7, ci = i & 127;
        float v = W[(((size_t)co * 128 + ci) * 5 + ky) * 5 + kx];
        __half h = __float2half_rn(v);
        dh[tb + co * 136 + ci] = h;
        dl[tb + co * 136 + ci] = __float2half_rn(v - __half2float(h));
    }
}

__device__ __forceinline__ void pp_deconv(const float* W, __nv_bfloat16* dst,
                                          int tap, int K)
{
    int ky = tap / K, kx = tap - ky * K;
    __nv_bfloat16* base = dst + (size_t)tap * 128 * 136;
    for (int i = threadIdx.x; i < 16384; i += blockDim.x) {
        int co = i >> 7, ci = i & 127;
        float v = W[(((size_t)ci * 128 + co) * K + (K - 1 - ky)) * K + (K - 1 - kx)];
        base[co * 136 + ci] = __float2bfloat16(v);
    }
}

__device__ __forceinline__ void pp_t2(const float* W, __nv_bfloat16* dst, int idx)
{
    int par = idx >> 2, tap = idx & 3;
    int py = par >> 1, px = par & 1;
    int ti = tap >> 1, tj = tap & 1;
    int ky = py + 2 * ti, kx = px + 2 * tj;
    __nv_bfloat16* base = dst + (size_t)idx * 128 * 136;
    for (int i = threadIdx.x; i < 16384; i += blockDim.x) {
        int co = i >> 7, ci = i & 127;
        float v = W[(((size_t)ci * 128 + co) * 4 + ky) * 4 + kx];
        base[co * 136 + ci] = __float2bfloat16(v);
    }
}

__global__ void prepack_all(const float* w2, const float* w3,
                            const float* t1w, const float* t2w,
                            const float* t3w, const float* t4w,
                            __half* w2hi, __half* w2lo,
                            __half* w3hi, __half* w3lo,
                            __nv_bfloat16* wp1, __nv_bfloat16* wpt2,
                            __nv_bfloat16* wp3, __nv_bfloat16* wp4)
{
    int bid = blockIdx.x;
    if (bid == 0 && threadIdx.x == 0) { g_rec_sum = 0.0; g_dict_sum = 0.0; }
    if      (bid < 25)  pp_fwd_split(w2, w2hi, w2lo, bid);
    else if (bid < 50)  pp_fwd_split(w3, w3hi, w3lo, bid - 25);
    else if (bid < 66)  pp_deconv(t1w, wp1, bid - 50, 4);
    else if (bid < 82)  pp_t2(t2w, wpt2, bid - 66);
    else if (bid < 107) pp_deconv(t3w, wp3, bid - 82, 5);
    else                pp_deconv(t4w, wp4, bid - 107, 5);
}

// ====== fused 3-pass fp16-split encoder conv, tap-major, M=128, 2 CTAs/SM =====
// Per tap: stage {Ahi, Bhi, Blo}; mma hi*Whi + hi*Wlo; restage Alo; mma lo*Whi.
// B staged once per tap (was twice). SMEM: A + Bhi + Blo = 3*TILE.
__global__ void __launch_bounds__(256, 2)
tc_enc3(const uint16_t* __restrict__ inHi, const uint16_t* __restrict__ inLo,
        const uint16_t* __restrict__ wHi,  const uint16_t* __restrict__ wLo,
        const float* __restrict__ bias, float* __restrict__ outp,
        int Hin, int Win, int Hout, int Wout, int pad, int relu)
{
    extern __shared__ char dsm[];
    __shared__ float sbias[128];
    const int tid  = threadIdx.x;
    const int wid  = tid >> 5;
    const int lane = tid & 31;
    const int Npix = Hout * Wout;
    const int totalPx = BB * Npix;
    const int pbase = blockIdx.x * 128;

    const uint32_t smA   = smem_u32(dsm);
    const uint32_t smBhi = smA + TILE;
    const uint32_t smBlo = smBhi + TILE;
    if (tid < 128) sbias[tid] = bias[tid];

    const int arow = tid >> 1, ahalf = tid & 1;
    const int ap = pbase + arow;
    const bool apv = (ap < totalPx);
    const int bA  = apv ? ap / Npix : 0;
    const int apn = apv ? ap - bA * Npix : 0;
    const int apy = apn / Wout;
    const int apx = apn - apy * Wout;
    const uint32_t adst0 = smA + arow * 272 + ahalf * 128;

    const int pxg = wid >> 1, cog = wid & 1;
    float acc[2][8][4];
    #pragma unroll
    for (int m = 0; m < 2; m++)
        #pragma unroll
        for (int n = 0; n < 8; n++)
            #pragma unroll
            for (int j = 0; j < 4; j++) acc[m][n][j] = 0.f;

    const uint32_t a_rd0 = smA + (pxg * 32 + (lane & 15)) * 272 + ((lane >> 4) << 4);
    const uint32_t b_rdb = (cog * 64 + ((lane >> 4) << 3) + (lane & 7)) * 272
                         + (((lane >> 3) & 1) << 4);

    auto stage_A = [&](const uint16_t* abuf, int tap) {
        const int ky = tap / 5, kx = tap - ky * 5;
        const int iy = apy + ky - pad, ix = apx + kx - pad;
        const bool inb = apv && (unsigned)iy < (unsigned)Hin && (unsigned)ix < (unsigned)Win;
        const char* as = inb ? (const char*)(abuf + ((size_t)(bA * Hin + iy) * Win + ix) * 128
                                             + ahalf * 64)
                             : (const char*)abuf;
        const int sz = inb ? 16 : 0;
        #pragma unroll
        for (int j = 0; j < 8; ++j)
            CP16(adst0 + j * 16, as + (size_t)j * 16, sz);
    };

    auto stage_Btile = [&](const uint16_t* wbuf, int tap, uint32_t bd) {
        const char* wb = (const char*)(wbuf + (size_t)tap * 128 * 136);
        #pragma unroll
        for (int j = 0; j < 8; ++j)
            CP16(bd + (j * 256 + tid) * 16, wb + (size_t)(j * 256 + tid) * 16, 16);
        if (tid < 128)
            CP16(bd + (2048 + tid) * 16, wb + (size_t)(2048 + tid) * 16, 16);
    };

    // pass over one B tile with A currently in smA
    auto mma_one = [&](uint32_t bbase) {
        #pragma unroll
        for (int ks = 0; ks < 8; ++ks) {
            uint32_t a[2][4], bq[4][4];
            #pragma unroll
            for (int i = 0; i < 2; ++i)
                LDSM_X4(a[i][0], a[i][1], a[i][2], a[i][3],
                        a_rd0 + i * 16 * 272 + ks * 32);
            #pragma unroll
            for (int nb = 0; nb < 4; ++nb)
                LDSM_X4(bq[nb][0], bq[nb][1], bq[nb][2], bq[nb][3],
                        bbase + b_rdb + nb * 16 * 272 + ks * 32);
            #pragma unroll
            for (int nb = 0; nb < 4; ++nb)
                #pragma unroll
                for (int i = 0; i < 2; ++i) {
                    MMA_F16(acc[i][2 * nb],     a[i][0], a[i][1], a[i][2], a[i][3],
                            bq[nb][0], bq[nb][1]);
                    MMA_F16(acc[i][2 * nb + 1], a[i][0], a[i][1], a[i][2], a[i][3],
                            bq[nb][2], bq[nb][3]);
                }
        }
    };

    // fused dual pass: A once, Bhi then Blo per ks
    auto mma_dual = [&]() {
        #pragma unroll
        for (int ks = 0; ks < 8; ++ks) {
            uint32_t a[2][4], bq[4][4];
            #pragma unroll
            for (int i = 0; i < 2; ++i)
                LDSM_X4(a[i][0], a[i][1], a[i][2], a[i][3],
                        a_rd0 + i * 16 * 272 + ks * 32);
            #pragma unroll
            for (int nb = 0; nb < 4; ++nb)
                LDSM_X4(bq[nb][0], bq[nb][1], bq[nb][2], bq[nb][3],
                        smBhi + b_rdb + nb * 16 * 272 + ks * 32);
            #pragma unroll
            for (int nb = 0; nb < 4; ++nb)
                #pragma unroll
                for (int i = 0; i < 2; ++i) {
                    MMA_F16(acc[i][2 * nb],     a[i][0], a[i][1], a[i][2], a[i][3],
                            bq[nb][0], bq[nb][1]);
                    MMA_F16(acc[i][2 * nb + 1], a[i][0], a[i][1], a[i][2], a[i][3],
                            bq[nb][2], bq[nb][3]);
                }
            #pragma unroll
            for (int nb = 0; nb < 4; ++nb)
                LDSM_X4(bq[nb][0], bq[nb][1], bq[nb][2], bq[nb][3],
                        smBlo + b_rdb + nb * 16 * 272 + ks * 32);
            #pragma unroll
            for (int nb = 0; nb < 4; ++nb)
                #pragma unroll
                for (int i = 0; i < 2; ++i) {
                    MMA_F16(acc[i][2 * nb],     a[i][0], a[i][1], a[i][2], a[i][3],
                            bq[nb][0], bq[nb][1]);
                    MMA_F16(acc[i][2 * nb + 1], a[i][0], a[i][1], a[i][2], a[i][3],
                            bq[nb][2], bq[nb][3]);
                }
        }
    };

    for (int tap = 0; tap < 25; ++tap) {
        __syncthreads();                    // protect previous reads
        stage_A(inHi, tap);
        stage_Btile(wHi, tap, smBhi);
        stage_Btile(wLo, tap, smBlo);
        CP_COMMIT();
        CP_WAIT0();
        __syncthreads();
        mma_dual();                         // hi*Whi + hi*Wlo
        __syncthreads();                    // A reads done before restage
        stage_A(inLo, tap);
        CP_COMMIT();
        CP_WAIT0();
        __syncthreads();
        mma_one(smBhi);                     // lo*Whi
    }

    #pragma unroll
    for (int mb = 0; mb < 2; ++mb) {
        const int row0 = pbase + pxg * 32 + mb * 16 + (lane >> 2);
        const int row1 = row0 + 8;
        const bool v0 = (row0 < totalPx), v1 = (row1 < totalPx);
        #pragma unroll
        for (int nt = 0; nt < 8; ++nt) {
            const int co = cog * 64 + nt * 8 + 2 * (lane & 3);
            const float bz0 = sbias[co], bz1 = sbias[co + 1];
            float p00 = acc[mb][nt][0] + bz0, p01 = acc[mb][nt][1] + bz1;
            float p10 = acc[mb][nt][2] + bz0, p11 = acc[mb][nt][3] + bz1;
            if (relu) {
                p00 = fmaxf(p00, 0.f); p01 = fmaxf(p01, 0.f);
                p10 = fmaxf(p10, 0.f); p11 = fmaxf(p11, 0.f);
            }
            if (v0) *(float2*)(outp + (size_t)row0 * 128 + co) = make_float2(p00, p01);
            if (v1) *(float2*)(outp + (size_t)row1 * 128 + co) = make_float2(p10, p11);
        }
    }
}

// ====== 1-pass bf16 engine, M=128, 2 CTAs/SM, A single + B double-prefetch ====
__global__ void __launch_bounds__(256, 2)
tc_eng1(const uint16_t* __restrict__ in, const uint16_t* __restrict__ wpack,
        const float* __restrict__ bias, __nv_bfloat16* __restrict__ outp,
        int Hin, int Win, int Hout, int Wout, int pad, int K)
{
    extern __shared__ char dsm[];
    __shared__ float sbias[128];
    const int tid  = threadIdx.x;
    const int wid  = tid >> 5;
    const int lane = tid & 31;
    const int Npix = Hout * Wout;
    const int totalPx = BB * Npix;
    const int pbase = blockIdx.x * 128;

    const uint32_t smA = smem_u32(dsm);      // 1 x TILE
    const uint32_t smB = smA + TILE;         // 2 x TILE (ping-pong)
    if (tid < 128) sbias[tid] = bias[tid];

    const int arow = tid >> 1, ahalf = tid & 1;
    const int ap = pbase + arow;
    const bool apv = (ap < totalPx);
    const int bA  = apv ? ap / Npix : 0;
    const int apn = apv ? ap - bA * Npix : 0;
    const int apy = apn / Wout;
    const int apx = apn - apy * Wout;
    const uint32_t adst0 = smA + arow * 272 + ahalf * 128;

    const int pxg = wid >> 1, cog = wid & 1;
    float acc[2][8][4];
    #pragma unroll
    for (int m = 0; m < 2; m++)
        #pragma unroll
        for (int n = 0; n < 8; n++)
            #pragma unroll
            for (int j = 0; j < 4; j++) acc[m][n][j] = 0.f;

    const uint32_t a_rd0 = smA + (pxg * 32 + (lane & 15)) * 272 + ((lane >> 4) << 4);
    const uint32_t b_rdb = (cog * 64 + ((lane >> 4) << 3) + (lane & 7)) * 272
                         + (((lane >> 3) & 1) << 4);
    const int NIT = K * K;

    auto stage_A = [&](int it) {
        const int ky = it / K, kx = it - (it / K) * K;
        const int iy = apy + ky - pad, ix = apx + kx - pad;
        const bool inb = apv && (unsigned)iy < (unsigned)Hin && (unsigned)ix < (unsigned)Win;
        const char* as = inb ? (const char*)(in + ((size_t)(bA * Hin + iy) * Win + ix) * 128
                                             + ahalf * 64)
                             : (const char*)in;
        const int sz = inb ? 16 : 0;
        #pragma unroll
        for (int j = 0; j < 8; ++j)
            CP16(adst0 + j * 16, as + (size_t)j * 16, sz);
    };

    auto stage_B = [&](int tap) {
        const char* wb = (const char*)(wpack + (size_t)tap * 128 * 136);
        const uint32_t bd = smB + (tap & 1) * TILE;
        #pragma unroll
        for (int j = 0; j < 8; ++j)
            CP16(bd + (j * 256 + tid) * 16, wb + (size_t)(j * 256 + tid) * 16, 16);
        if (tid < 128)
            CP16(bd + (2048 + tid) * 16, wb + (size_t)(2048 + tid) * 16, 16);
    };

    stage_B(0);
    CP_COMMIT();
    for (int it = 0; it < NIT; ++it) {
        stage_A(it);
        CP_COMMIT();
        if (it + 1 < NIT) {
            stage_B(it + 1);                // prefetched under MMA(it)
            CP_COMMIT();
            CP_WAIT1();                     // B(it) + A(it) done
        } else {
            CP_WAIT0();
        }
        __syncthreads();
        const uint32_t bbase = smB + (it & 1) * TILE;
        #pragma unroll
        for (int ks = 0; ks < 8; ++ks) {
            uint32_t a[2][4], bq[4][4];
            #pragma unroll
            for (int i = 0; i < 2; ++i)
                LDSM_X4(a[i][0], a[i][1], a[i][2], a[i][3],
                        a_rd0 + i * 16 * 272 + ks * 32);
            #pragma unroll
            for (int nb = 0; nb < 4; ++nb)
                LDSM_X4(bq[nb][0], bq[nb][1], bq[nb][2], bq[nb][3],
                        bbase + b_rdb + nb * 16 * 272 + ks * 32);
            #pragma unroll
            for (int nb = 0; nb < 4; ++nb)
                #pragma unroll
                for (int i = 0; i < 2; ++i) {
                    MMA_BF16(acc[i][2 * nb],     a[i][0], a[i][1], a[i][2], a[i][3],
                             bq[nb][0], bq[nb][1]);
                    MMA_BF16(acc[i][2 * nb + 1], a[i][0], a[i][1], a[i][2], a[i][3],
                             bq[nb][2], bq[nb][3]);
                }
        }
        __syncthreads();                    // protect single-buffered A
    }

    #pragma unroll
    for (int mb = 0; mb < 2; ++mb) {
        const int row0 = pbase + pxg * 32 + mb * 16 + (lane >> 2);
        const int row1 = row0 + 8;
        const bool v0 = (row0 < totalPx), v1 = (row1 < totalPx);
        #pragma unroll
        for (int nt = 0; nt < 8; ++nt) {
            const int co = cog * 64 + nt * 8 + 2 * (lane & 3);
            const float bz0 = sbias[co], bz1 = sbias[co + 1];
            float p00 = fmaxf(acc[mb][nt][0] + bz0, 0.f);
            float p01 = fmaxf(acc[mb][nt][1] + bz1, 0.f);
            float p10 = fmaxf(acc[mb][nt][2] + bz0, 0.f);
            float p11 = fmaxf(acc[mb][nt][3] + bz1, 0.f);
            if (v0) {
                __nv_bfloat162 h = __floats2bfloat162_rn(p00, p01);
                *(uint32_t*)(outp + (size_t)row0 * 128 + co) = *reinterpret_cast<uint32_t*>(&h);
            }
            if (v1) {
                __nv_bfloat162 h = __floats2bfloat162_rn(p10, p11);
                *(uint32_t*)(outp + (size_t)row1 * 128 + co) = *reinterpret_cast<uint32_t*>(&h);
            }
        }
    }
}

// ====== t2 stride-2 deconv, parity decomp, M=128, 2 CTAs/SM, B prefetch =======
__global__ void __launch_bounds__(256, 2)
tc_t2(const uint16_t* __restrict__ in, const uint16_t* __restrict__ wpack,
      const float* __restrict__ bias, __nv_bfloat16* __restrict__ outp)
{
    extern __shared__ char dsm[];
    __shared__ float sbias[128];
    const int tid  = threadIdx.x;
    const int wid  = tid >> 5;
    const int lane = tid & 31;
    const int par  = blockIdx.z;
    const int py   = par >> 1, px = par & 1;
    const int totalPx = BB * 100;
    const int pbase = blockIdx.x * 128;

    const uint32_t smA = smem_u32(dsm);
    const uint32_t smB = smA + TILE;
    if (tid < 128) sbias[tid] = bias[tid];

    const int arow = tid >> 1, ahalf = tid & 1;
    const int ap = pbase + arow;
    const bool apv = (ap < totalPx);
    const int bA  = apv ? ap / 100 : 0;
    const int apn = apv ? ap - bA * 100 : 0;
    const int apy = apn / 10;
    const int apx = apn - apy * 10;
    const uint32_t adst0 = smA + arow * 272 + ahalf * 128;

    const int pxg = wid >> 1, cog = wid & 1;
    float acc[2][8][4];
    #pragma unroll
    for (int m = 0; m < 2; m++)
        #pragma unroll
        for (int n = 0; n < 8; n++)
            #pragma unroll
            for (int j = 0; j < 4; j++) acc[m][n][j] = 0.f;

    const uint32_t a_rd0 = smA + (pxg * 32 + (lane & 15)) * 272 + ((lane >> 4) << 4);
    const uint32_t b_rdb = (cog * 64 + ((lane >> 4) << 3) + (lane & 7)) * 272
                         + (((lane >> 3) & 1) << 4);

    auto stage_A = [&](int tap) {
        const int ti = tap >> 1, tj = tap & 1;
        const int iy = apy - ti, ix = apx - tj;
        const bool inb = apv && (unsigned)iy < 9u && (unsigned)ix < 9u;
        const char* as = inb ? (const char*)(in + ((size_t)(bA * 9 + iy) * 9 + ix) * 128
                                             + ahalf * 64)
                             : (const char*)in;
        const int sz = inb ? 16 : 0;
        #pragma unroll
        for (int j = 0; j < 8; ++j)
            CP16(adst0 + j * 16, as + (size_t)j * 16, sz);
    };

    auto stage_B = [&](int tap) {
        const char* wb = (const char*)(wpack + (size_t)(par * 4 + tap) * 128 * 136);
        const uint32_t bd = smB + (tap & 1) * TILE;
        #pragma unroll
        for (int j = 0; j < 8; ++j)
            CP16(bd + (j * 256 + tid) * 16, wb + (size_t)(j * 256 + tid) * 16, 16);
        if (tid < 128)
            CP16(bd + (2048 + tid) * 16, wb + (size_t)(2048 + tid) * 16, 16);
    };

    stage_B(0);
    CP_COMMIT();
    for (int it = 0; it < 4; ++it) {
        stage_A(it);
        CP_COMMIT();
        if (it + 1 < 4) {
            stage_B(it + 1);
            CP_COMMIT();
            CP_WAIT1();
        } else {
            CP_WAIT0();
        }
        __syncthreads();
        const uint32_t bbase = smB + (it & 1) * TILE;
        #pragma unroll
        for (int ks = 0; ks < 8; ++ks) {
            uint32_t a[2][4], bq[4][4];
            #pragma unroll
            for (int i = 0; i < 2; ++i)
                LDSM_X4(a[i][0], a[i][1], a[i][2], a[i][3],
                        a_rd0 + i * 16 * 272 + ks * 32);
            #pragma unroll
            for (int nb = 0; nb < 4; ++nb)
                LDSM_X4(bq[nb][0], bq[nb][1], bq[nb][2], bq[nb][3],
                        bbase + b_rdb + nb * 16 * 272 + ks * 32);
            #pragma unroll
            for (int nb = 0; nb < 4; ++nb)
                #pragma unroll
                for (int i = 0; i < 2; ++i) {
                    MMA_BF16(acc[i][2 * nb],     a[i][0], a[i][1], a[i][2], a[i][3],
                             bq[nb][0], bq[nb][1]);
                    MMA_BF16(acc[i][2 * nb + 1], a[i][0], a[i][1], a[i][2], a[i][3],
                             bq[nb][2], bq[nb][3]);
                }
        }
        __syncthreads();
    }

    #pragma unroll
    for (int mb = 0; mb < 2; ++mb) {
        const int r0g = pbase + pxg * 32 + mb * 16 + (lane >> 2);
        const int r1g = r0g + 8;
        int b0 = r0g / 100, q0 = r0g - b0 * 100, y0 = q0 / 10, x0 = q0 - y0 * 10;
        int b1 = r1g / 100, q1 = r1g - b1 * 100, y1 = q1 / 10, x1 = q1 - y1 * 10;
        size_t o0 = ((size_t)b0 * 400 + (2 * y0 + py) * 20 + 2 * x0 + px) * 128;
        size_t o1 = ((size_t)b1 * 400 + (2 * y1 + py) * 20 + 2 * x1 + px) * 128;
        #pragma unroll
        for (int nt = 0; nt < 8; ++nt) {
            const int co = cog * 64 + nt * 8 + 2 * (lane & 3);
            const float bz0 = sbias[co], bz1 = sbias[co + 1];
            float p00 = fmaxf(acc[mb][nt][0] + bz0, 0.f);
            float p01 = fmaxf(acc[mb][nt][1] + bz1, 0.f);
            float p10 = fmaxf(acc[mb][nt][2] + bz0, 0.f);
            float p11 = fmaxf(acc[mb][nt][3] + bz1, 0.f);
            if (r0g < totalPx) {
                __nv_bfloat162 h = __floats2bfloat162_rn(p00, p01);
                *(uint32_t*)(outp + o0 + co) = *reinterpret_cast<uint32_t*>(&h);
            }
            if (r1g < totalPx) {
                __nv_bfloat162 h = __floats2bfloat162_rn(p10, p11);
                *(uint32_t*)(outp + o1 + co) = *reinterpret_cast<uint32_t*>(&h);
            }
        }
    }
}

// ---------------- conv1: 8 px/block, weights in registers ---------------------
__global__ void __launch_bounds__(128)
conv1_split(const float* __restrict__ x, const float* __restrict__ w1,
            const float* __restrict__ b1, __half* __restrict__ hi,
            __half* __restrict__ lo)
{
    const int b = blockIdx.x, g = blockIdx.y;
    const int p0 = g * 8;
    const int oy = p0 / 24, ox0 = p0 - oy * 24;
    const int co = threadIdx.x;
    __shared__ float xs[5][12];
    for (int i = co; i < 60; i += 128) {
        int r = i / 12, c = i - r * 12;
        xs[r][c] = x[(size_t)b * 784 + (oy + r) * 28 + ox0 + c];
    }
    __syncthreads();
    float w[25];
    #pragma unroll
    for (int t = 0; t < 25; ++t) w[t] = w1[co * 25 + t];
    const float bz = b1[co];
    #pragma unroll
    for (int px = 0; px < 8; ++px) {
        float v = bz;
        #pragma unroll
        for (int t = 0; t < 25; ++t)
            v += w[t] * xs[t / 5][t % 5 + px];
        v = fmaxf(v, 0.f);
        __half h = __float2half_rn(v);
        size_t o = ((size_t)b * 576 + p0 + px) * 128 + co;
        hi[o] = h;
        lo[o] = __float2half_rn(v - __half2float(h));
    }
}

// ---------------- NHWC maxpool 2x2: fp32 -> fp16 hi/lo -----------------------
__global__ void mp_split_nhwc(const float* __restrict__ in, __half* __restrict__ hi,
                              __half* __restrict__ lo, int Hin, int Win)
{
    const int Ho = Hin >> 1, Wo = Win >> 1;
    const size_t total = (size_t)BB * Ho * Wo * 128;
    for (size_t i = (size_t)blockIdx.x * blockDim.x + threadIdx.x; i < total;
         i += (size_t)gridDim.x * blockDim.x) {
        int c = (int)(i & 127);
        size_t r = i >> 7;
        int wo = (int)(r % Wo); r /= Wo;
        int ho = (int)(r % Ho); int b = (int)(r / Ho);
        const float* p = in + (((size_t)b * Hin + 2 * ho) * Win + 2 * wo) * 128 + c;
        float v = fmaxf(fmaxf(p[0], p[128]),
                        fmaxf(p[(size_t)Win * 128], p[(size_t)(Win + 1) * 128]));
        __half h = __float2half_rn(v);
        hi[i] = h;
        lo[i] = __float2half_rn(v - __half2float(h));
    }
}

// ---------------- NHWC maxpool 2x2: fp32 -> fp32 -----------------------------
__global__ void mp_nhwc(const float* __restrict__ in, float* __restrict__ out,
                        int Hin, int Win)
{
    const int Ho = Hin >> 1, Wo = Win >> 1;
    const size_t total = (size_t)BB * Ho * Wo * 128;
    for (size_t i = (size_t)blockIdx.x * blockDim.x + threadIdx.x; i < total;
         i += (size_t)gridDim.x * blockDim.x) {
        int c = (int)(i & 127);
        size_t r = i >> 7;
        int wo = (int)(r % Wo); r /= Wo;
        int ho = (int)(r % Ho); int b = (int)(r / Ho);
        const float* p = in + (((size_t)b * Hin + 2 * ho) * Win + 2 * wo) * 128 + c;
        out[i] = fmaxf(fmaxf(p[0], p[128]),
                       fmaxf(p[(size_t)Win * 128], p[(size_t)(Win + 1) * 128]));
    }
}

// ---------------- VQ: argmax(d2), gather val (NHWC bf16), dict MSE ------------
__global__ void __launch_bounds__(256)
vq_kernel(const float* __restrict__ z, const float* __restrict__ dict,
          __nv_bfloat16* __restrict__ valh, float* __restrict__ idx_out)
{
    extern __shared__ float dsmf[];
    __shared__ float zt[36 * 128];
    __shared__ float wn[128];
    __shared__ int   sidx[36];

    const int b = blockIdx.x, tid = threadIdx.x;

    for (int i = tid; i < 128 * 128; i += NT) {
        int k = i >> 7; int c = i & 127;
        dsmf[k * 129 + c] = dict[i];
    }
    for (int i = tid; i < 36 * 128; i += NT)
        zt[i] = z[(size_t)b * 4608 + i];
    __syncthreads();
    if (tid < 128) {
        float s = 0.f;
        const float* dp = dsmf + tid * 129;
        for (int c = 0; c < 128; c++) s += dp[c] * dp[c];
        wn[tid] = s;
    }
    __syncthreads();

    const int lane = tid & 31, wid = tid >> 5;
    for (int pos = wid; pos < 36; pos += 8) {
        float d0 = 0.f, d1 = 0.f, d2s = 0.f, d3 = 0.f, zn = 0.f;
        const float* zp = zt + pos * 128;
        const float* p0 = dsmf + (lane      ) * 129;
        const float* p1 = dsmf + (lane + 32 ) * 129;
        const float* p2 = dsmf + (lane + 64 ) * 129;
        const float* p3 = dsmf + (lane + 96 ) * 129;
        for (int c = 0; c < 128; c++) {
            float zv = zp[c];
            zn += zv * zv;
            d0 += p0[c] * zv; d1 += p1[c] * zv;
            d2s += p2[c] * zv; d3 += p3[c] * zv;
        }
        float bv = zn + wn[lane] - 2.f * d0; int bk = lane;
        float v1 = zn + wn[lane + 32] - 2.f * d1; if (v1 > bv) { bv = v1; bk = lane + 32; }
        float v2 = zn + wn[lane + 64] - 2.f * d2s; if (v2 > bv) { bv = v2; bk = lane + 64; }
        float v3 = zn + wn[lane + 96] - 2.f * d3; if (v3 > bv) { bv = v3; bk = lane + 96; }
        #pragma unroll
        for (int o = 16; o; o >>= 1) {
            float ov = __shfl_xor_sync(0xffffffffu, bv, o);
            int   ok = __shfl_xor_sync(0xffffffffu, bk, o);
            if (ov > bv || (ov == bv && ok < bk)) { bv = ov; bk = ok; }
        }
        if (lane == 0) {
            sidx[pos] = bk;
            if (idx_out) idx_out[b * 36 + pos] = (float)bk;
        }
    }
    __syncthreads();

    float lsum = 0.f;
    for (int i = tid; i < 4608; i += NT) {
        int pos = i >> 7; int c = i & 127;
        float v  = dsmf[sidx[pos] * 129 + c];
        float zv = zt[i];
        valh[(size_t)b * 4608 + i] = __float2bfloat16(v);
        float d = v - zv;
        lsum += d * d;
    }
    lsum = warp_sum(lsum);
    if ((tid & 31) == 0) atomicAdd(&g_dict_sum, (double)lsum);
}

// ---------------- mu (1x1 conv) fused with reconstruction loss (NHWC bf16) ---
__global__ void __launch_bounds__(256)
mu_loss(const __nv_bfloat16* __restrict__ f4, const float* __restrict__ x,
        const float* __restrict__ mw, const float* __restrict__ mb)
{
    __shared__ float mws[128];
    const int b = blockIdx.x, tid = threadIdx.x;
    if (tid < 128) mws[tid] = mw[tid];
    __syncthreads();
    float lsum = 0.f;
    for (int px = tid; px < 784; px += NT) {
        const uint4* fp = (const uint4*)(f4 + ((size_t)b * 784 + px) * 128);
        float s = mb[0];
        #pragma unroll
        for (int j = 0; j < 16; j++) {
            uint4 v = fp[j];
            const __nv_bfloat16* h = (const __nv_bfloat16*)&v;
            #pragma unroll
            for (int t = 0; t < 8; t++)
                s += __bfloat162float(h[t]) * mws[j * 8 + t];
        }
        float d = s - x[(size_t)b * 784 + px];
        lsum += d * d;
    }
    lsum = warp_sum(lsum);
    if ((tid & 31) == 0) atomicAdd(&g_rec_sum, (double)lsum);
}

__global__ void finalize_kernel(float* loss_out)
{
    if (loss_out) {
        double dict_mse = g_dict_sum / 1179648.0;
        loss_out[0] = (float)(g_rec_sum / 200704.0);
        loss_out[1] = (float)(dict_mse * 5.0);
        loss_out[2] = (float)(dict_mse * 1.25);
        loss_out[3] = 0.f;
    }
}

// ---------------- host side ----------------------------------------------------
extern "C" void kernel_launch(void* const* d_in, const int* in_sizes, int n_in,
                              void* d_out, int out_size)
{
    const float* x    = (const float*)d_in[0];
    const float* w1   = (const float*)d_in[1];
    const float* b1   = (const float*)d_in[2];
    const float* w2   = (const float*)d_in[3];
    const float* b2   = (const float*)d_in[4];
    const float* w3   = (const float*)d_in[5];
    const float* b3   = (const float*)d_in[6];
    const float* t1w  = (const float*)d_in[7];
    const float* t1b  = (const float*)d_in[8];
    const float* t2w  = (const float*)d_in[9];
    const float* t2b  = (const float*)d_in[10];
    const float* t3w  = (const float*)d_in[11];
    const float* t3b  = (const float*)d_in[12];
    const float* t4w  = (const float*)d_in[13];
    const float* t4b  = (const float*)d_in[14];
    const float* mw   = (const float*)d_in[15];
    const float* mb   = (const float*)d_in[16];
    const float* dictw= (const float*)d_in[17];

    float* outp = (float*)d_out;
    float* loss_ptr = outp;
    float* idx_ptr  = outp + 4;
    if (out_size < 9220) { loss_ptr = nullptr; idx_ptr = outp; }

    __half *c1hi, *c1lo, *p1hi, *p1lo, *w2hi, *w2lo, *w3hi, *w3lo;
    float *c2f, *c3f, *zn;
    __nv_bfloat16 *valh, *f1h, *f2h, *f3h, *f4h, *wp1, *wpt2, *wp3, *wp4;
    cudaGetSymbolAddress((void**)&c1hi, g_c1hi);
    cudaGetSymbolAddress((void**)&c1lo, g_c1lo);
    cudaGetSymbolAddress((void**)&c2f,  g_c2f);
    cudaGetSymbolAddress((void**)&p1hi, g_p1hi);
    cudaGetSymbolAddress((void**)&p1lo, g_p1lo);
    cudaGetSymbolAddress((void**)&c3f,  g_c3f);
    cudaGetSymbolAddress((void**)&zn,   g_zn);
    cudaGetSymbolAddress((void**)&valh, g_valh);
    cudaGetSymbolAddress((void**)&f1h,  g_f1h);
    cudaGetSymbolAddress((void**)&f2h,  g_f2h);
    cudaGetSymbolAddress((void**)&f3h,  g_f3h);
    cudaGetSymbolAddress((void**)&f4h,  g_f4h);
    cudaGetSymbolAddress((void**)&wp1,  g_wp1);
    cudaGetSymbolAddress((void**)&wpt2, g_wpt2);
    cudaGetSymbolAddress((void**)&wp3,  g_wp3);
    cudaGetSymbolAddress((void**)&wp4,  g_wp4);
    cudaGetSymbolAddress((void**)&w2hi, g_w2hi);
    cudaGetSymbolAddress((void**)&w2lo, g_w2lo);
    cudaGetSymbolAddress((void**)&w3hi, g_w3hi);
    cudaGetSymbolAddress((void**)&w3lo, g_w3lo);

    static bool attr_set = false;
    if (!attr_set) {
        cudaFuncSetAttribute(vq_kernel, cudaFuncAttributeMaxDynamicSharedMemorySize,
                             128 * 129 * (int)sizeof(float));
        cudaFuncSetAttribute(tc_eng1, cudaFuncAttributeMaxDynamicSharedMemorySize,
                             3 * TILE);
        cudaFuncSetAttribute(tc_t2, cudaFuncAttributeMaxDynamicSharedMemorySize,
                             3 * TILE);
        cudaFuncSetAttribute(tc_enc3, cudaFuncAttributeMaxDynamicSharedMemorySize,
                             3 * TILE);
        attr_set = true;
    }

    prepack_all<<<132, 256>>>(w2, w3, t1w, t2w, t3w, t4w,
                              w2hi, w2lo, w3hi, w3lo, wp1, wpt2, wp3, wp4);
    conv1_split<<<dim3(BB, 72), 128>>>(x, w1, b1, c1hi, c1lo);
    tc_enc3<<<1152, 256, 3 * TILE>>>(
        (const uint16_t*)c1hi, (const uint16_t*)c1lo,
        (const uint16_t*)w2hi, (const uint16_t*)w2lo,
        b2, c2f, 24, 24, 24, 24, 2, 1);
    mp_split_nhwc<<<4096, 256>>>(c2f, p1hi, p1lo, 24, 24);
    tc_enc3<<<288, 256, 3 * TILE>>>(
        (const uint16_t*)p1hi, (const uint16_t*)p1lo,
        (const uint16_t*)w3hi, (const uint16_t*)w3lo,
        b3, c3f, 12, 12, 12, 12, 2, 0);
    mp_nhwc<<<2048, 256>>>(c3f, zn, 12, 12);

    vq_kernel<<<BB, NT, 128 * 129 * sizeof(float)>>>(zn, dictw, valh, idx_ptr);

    tc_eng1<<<162, 256, 3 * TILE>>>(
        (const uint16_t*)valh, (const uint16_t*)wp1, t1b, f1h, 6, 6, 9, 9, 3, 4);
    tc_t2<<<dim3(200, 1, 4), 256, 3 * TILE>>>(
        (const uint16_t*)f1h, (const uint16_t*)wpt2, t2b, f2h);
    tc_eng1<<<1152, 256, 3 * TILE>>>(
        (const uint16_t*)f2h, (const uint16_t*)wp3, t3b, f3h, 20, 20, 24, 24, 4, 5);
    tc_eng1<<<1568, 256, 3 * TILE>>>(
        (const uint16_t*)f3h, (const uint16_t*)wp4, t4b, f4h, 24, 24, 28, 28, 4, 5);

    mu_loss<<<BB, NT>>>(f4h, x, mw, mb);
    finalize_kernel<<<1, 1>>>(loss_ptr);
}

// round 16
// speedup vs baseline: 1.1260x; 1.0172x over previous
#include <cuda_runtime.h>
#include <cuda_bf16.h>
#include <cuda_fp16.h>
#include <cuda_fp8.h>
#include <cstdint>

#define BB 256
#define NT 256
#define TILE 34816          // bf16/fp16 tile: 128 rows x 272B
#define FTILE 18432         // fp8 tile: 128 rows x 144B

// ---------------- scratch (device globals; no allocation APIs) ---------------
__device__ __half g_c1hi[(size_t)BB*576*128];
__device__ __half g_c1lo[(size_t)BB*576*128];
__device__ float  g_c2f [(size_t)BB*576*128];
__device__ __half g_p1hi[(size_t)BB*144*128];
__device__ __half g_p1lo[(size_t)BB*144*128];
__device__ float  g_c3f [(size_t)BB*144*128];
__device__ float  g_zn  [(size_t)BB*36*128];
__device__ uint8_t g_valf8[(size_t)BB*36*128];   // codes, NHWC e4m3
__device__ uint8_t g_f1f8[(size_t)BB*81*128];
__device__ uint8_t g_f2f8[(size_t)BB*400*128];
__device__ uint8_t g_f3f8[(size_t)BB*576*128];
__device__ uint8_t g_f4f8[(size_t)BB*784*128];
// fp8 packed weights, pitch 144B per co-row
__device__ uint8_t g_wp1f8[16*128*144];
__device__ uint8_t g_wpt2f8[16*128*144];
__device__ uint8_t g_wp3f8[25*128*144];
__device__ uint8_t g_wp4f8[25*128*144];
__device__ __half g_w2hi[25*128*136];
__device__ __half g_w2lo[25*128*136];
__device__ __half g_w3hi[25*128*136];
__device__ __half g_w3lo[25*128*136];
__device__ double g_rec_sum;
__device__ double g_dict_sum;

__inline__ __device__ float warp_sum(float v) {
    #pragma unroll
    for (int o = 16; o; o >>= 1) v += __shfl_xor_sync(0xffffffffu, v, o);
    return v;
}

// ---------------- mma / cp.async helpers --------------------------------------
__device__ __forceinline__ uint32_t smem_u32(const void* p) {
    uint32_t a;
    asm("{ .reg .u64 t; cvta.to.shared.u64 t, %1; cvt.u32.u64 %0, t; }"
        : "=r"(a) : "l"(p));
    return a;
}

#define LDSM_X4(r0, r1, r2, r3, addr)                                          \
    asm volatile("ldmatrix.sync.aligned.m8n8.x4.shared.b16 {%0,%1,%2,%3}, [%4];" \
                 : "=r"(r0), "=r"(r1), "=r"(r2), "=r"(r3) : "r"(addr))

#define MMA_F16(c, a0, a1, a2, a3, b0, b1)                                     \
    asm volatile("mma.sync.aligned.m16n8k16.row.col.f32.f16.f16.f32 "          \
                 "{%0,%1,%2,%3}, {%4,%5,%6,%7}, {%8,%9}, {%0,%1,%2,%3};"       \
                 : "+f"((c)[0]), "+f"((c)[1]), "+f"((c)[2]), "+f"((c)[3])      \
                 : "r"(a0), "r"(a1), "r"(a2), "r"(a3), "r"(b0), "r"(b1))

#define MMA_FP8(c, a0, a1, a2, a3, b0, b1)                                     \
    asm volatile("mma.sync.aligned.m16n8k32.row.col.f32.e4m3.e4m3.f32 "        \
                 "{%0,%1,%2,%3}, {%4,%5,%6,%7}, {%8,%9}, {%0,%1,%2,%3};"       \
                 : "+f"((c)[0]), "+f"((c)[1]), "+f"((c)[2]), "+f"((c)[3])      \
                 : "r"(a0), "r"(a1), "r"(a2), "r"(a3), "r"(b0), "r"(b1))

#define CP16(d, s, n)                                                          \
    asm volatile("cp.async.cg.shared.global [%0], [%1], 16, %2;"               \
                 :: "r"(d), "l"(s), "r"(n))
#define CP_COMMIT() asm volatile("cp.async.commit_group;" ::: "memory")
#define CP_WAIT0()  asm volatile("cp.async.wait_group 0;" ::: "memory")
#define CP_WAIT1()  asm volatile("cp.async.wait_group 1;" ::: "memory")

// ---------------- fused weight prepack (all layers, one launch) ---------------
__device__ __forceinline__ void pp_fwd_split(const float* W, __half* dh, __half* dl,
                                             int tap)
{
    int ky = tap / 5, kx = tap - ky * 5;
    size_t tb = (size_t)tap * 128 * 136;
    for (int i = threadIdx.x; i < 16384; i += blockDim.x) {
        int co = i >> 7, ci = i & 127;
        float v = W[(((size_t)co * 128 + ci) * 5 + ky) * 5 + kx];
        __half h = __float2half_rn(v);
        dh[tb + co * 136 + ci] = h;
        dl[tb + co * 136 + ci] = __float2half_rn(v - __half2float(h));
    }
}

__device__ __forceinline__ void pp_deconv_f8(const float* W, uint8_t* dst,
                                             int tap, int K)
{
    int ky = tap / K, kx = tap - ky * K;
    uint8_t* base = dst + (size_t)tap * 128 * 144;
    for (int i = threadIdx.x; i < 16384; i += blockDim.x) {
        int co = i >> 7, ci = i & 127;
        float v = W[(((size_t)ci * 128 + co) * K + (K - 1 - ky)) * K + (K - 1 - kx)];
        base[co * 144 + ci] = __nv_cvt_float_to_fp8(v, __NV_SATFINITE, __NV_E4M3);
    }
}

__device__ __forceinline__ void pp_t2_f8(const float* W, uint8_t* dst, int idx)
{
    int par = idx >> 2, tap = idx & 3;
    int py = par >> 1, px = par & 1;
    int ti = tap >> 1, tj = tap & 1;
    int ky = py + 2 * ti, kx = px + 2 * tj;
    uint8_t* base = dst + (size_t)idx * 128 * 144;
    for (int i = threadIdx.x; i < 16384; i += blockDim.x) {
        int co = i >> 7, ci = i & 127;
        float v = W[(((size_t)ci * 128 + co) * 4 + ky) * 4 + kx];
        base[co * 144 + ci] = __nv_cvt_float_to_fp8(v, __NV_SATFINITE, __NV_E4M3);
    }
}

__global__ void prepack_all(const float* w2, const float* w3,
                            const float* t1w, const float* t2w,
                            const float* t3w, const float* t4w,
                            __half* w2hi, __half* w2lo,
                            __half* w3hi, __half* w3lo,
                            uint8_t* wp1, uint8_t* wpt2,
                            uint8_t* wp3, uint8_t* wp4)
{
    int bid = blockIdx.x;
    if (bid == 0 && threadIdx.x == 0) { g_rec_sum = 0.0; g_dict_sum = 0.0; }
    if      (bid < 25)  pp_fwd_split(w2, w2hi, w2lo, bid);
    else if (bid < 50)  pp_fwd_split(w3, w3hi, w3lo, bid - 25);
    else if (bid < 66)  pp_deconv_f8(t1w, wp1, bid - 50, 4);
    else if (bid < 82)  pp_t2_f8(t2w, wpt2, bid - 66);
    else if (bid < 107) pp_deconv_f8(t3w, wp3, bid - 82, 5);
    else                pp_deconv_f8(t4w, wp4, bid - 107, 5);
}

// ====== fused 3-pass fp16-split encoder conv, tap-major, M=128, 2 CTAs/SM =====
__global__ void __launch_bounds__(256, 2)
tc_enc3(const uint16_t* __restrict__ inHi, const uint16_t* __restrict__ inLo,
        const uint16_t* __restrict__ wHi,  const uint16_t* __restrict__ wLo,
        const float* __restrict__ bias, float* __restrict__ outp,
        int Hin, int Win, int Hout, int Wout, int pad, int relu)
{
    extern __shared__ char dsm[];
    __shared__ float sbias[128];
    const int tid  = threadIdx.x;
    const int wid  = tid >> 5;
    const int lane = tid & 31;
    const int Npix = Hout * Wout;
    const int totalPx = BB * Npix;
    const int pbase = blockIdx.x * 128;

    const uint32_t smA   = smem_u32(dsm);
    const uint32_t smBhi = smA + TILE;
    const uint32_t smBlo = smBhi + TILE;
    if (tid < 128) sbias[tid] = bias[tid];

    const int arow = tid >> 1, ahalf = tid & 1;
    const int ap = pbase + arow;
    const bool apv = (ap < totalPx);
    const int bA  = apv ? ap / Npix : 0;
    const int apn = apv ? ap - bA * Npix : 0;
    const int apy = apn / Wout;
    const int apx = apn - apy * Wout;
    const uint32_t adst0 = smA + arow * 272 + ahalf * 128;

    const int pxg = wid >> 1, cog = wid & 1;
    float acc[2][8][4];
    #pragma unroll
    for (int m = 0; m < 2; m++)
        #pragma unroll
        for (int n = 0; n < 8; n++)
            #pragma unroll
            for (int j = 0; j < 4; j++) acc[m][n][j] = 0.f;

    const uint32_t a_rd0 = smA + (pxg * 32 + (lane & 15)) * 272 + ((lane >> 4) << 4);
    const uint32_t b_rdb = (cog * 64 + ((lane >> 4) << 3) + (lane & 7)) * 272
                         + (((lane >> 3) & 1) << 4);

    auto stage_A = [&](const uint16_t* abuf, int tap) {
        const int ky = tap / 5, kx = tap - ky * 5;
        const int iy = apy + ky - pad, ix = apx + kx - pad;
        const bool inb = apv && (unsigned)iy < (unsigned)Hin && (unsigned)ix < (unsigned)Win;
        const char* as = inb ? (const char*)(abuf + ((size_t)(bA * Hin + iy) * Win + ix) * 128
                                             + ahalf * 64)
                             : (const char*)abuf;
        const int sz = inb ? 16 : 0;
        #pragma unroll
        for (int j = 0; j < 8; ++j)
            CP16(adst0 + j * 16, as + (size_t)j * 16, sz);
    };

    auto stage_Btile = [&](const uint16_t* wbuf, int tap, uint32_t bd) {
        const char* wb = (const char*)(wbuf + (size_t)tap * 128 * 136);
        #pragma unroll
        for (int j = 0; j < 8; ++j)
            CP16(bd + (j * 256 + tid) * 16, wb + (size_t)(j * 256 + tid) * 16, 16);
        if (tid < 128)
            CP16(bd + (2048 + tid) * 16, wb + (size_t)(2048 + tid) * 16, 16);
    };

    auto mma_one = [&](uint32_t bbase) {
        #pragma unroll
        for (int ks = 0; ks < 8; ++ks) {
            uint32_t a[2][4], bq[4][4];
            #pragma unroll
            for (int i = 0; i < 2; ++i)
                LDSM_X4(a[i][0], a[i][1], a[i][2], a[i][3],
                        a_rd0 + i * 16 * 272 + ks * 32);
            #pragma unroll
            for (int nb = 0; nb < 4; ++nb)
                LDSM_X4(bq[nb][0], bq[nb][1], bq[nb][2], bq[nb][3],
                        bbase + b_rdb + nb * 16 * 272 + ks * 32);
            #pragma unroll
            for (int nb = 0; nb < 4; ++nb)
                #pragma unroll
                for (int i = 0; i < 2; ++i) {
                    MMA_F16(acc[i][2 * nb],     a[i][0], a[i][1], a[i][2], a[i][3],
                            bq[nb][0], bq[nb][1]);
                    MMA_F16(acc[i][2 * nb + 1], a[i][0], a[i][1], a[i][2], a[i][3],
                            bq[nb][2], bq[nb][3]);
                }
        }
    };

    auto mma_dual = [&]() {
        #pragma unroll
        for (int ks = 0; ks < 8; ++ks) {
            uint32_t a[2][4], bq[4][4];
            #pragma unroll
            for (int i = 0; i < 2; ++i)
                LDSM_X4(a[i][0], a[i][1], a[i][2], a[i][3],
                        a_rd0 + i * 16 * 272 + ks * 32);
            #pragma unroll
            for (int nb = 0; nb < 4; ++nb)
                LDSM_X4(bq[nb][0], bq[nb][1], bq[nb][2], bq[nb][3],
                        smBhi + b_rdb + nb * 16 * 272 + ks * 32);
            #pragma unroll
            for (int nb = 0; nb < 4; ++nb)
                #pragma unroll
                for (int i = 0; i < 2; ++i) {
                    MMA_F16(acc[i][2 * nb],     a[i][0], a[i][1], a[i][2], a[i][3],
                            bq[nb][0], bq[nb][1]);
                    MMA_F16(acc[i][2 * nb + 1], a[i][0], a[i][1], a[i][2], a[i][3],
                            bq[nb][2], bq[nb][3]);
                }
            #pragma unroll
            for (int nb = 0; nb < 4; ++nb)
                LDSM_X4(bq[nb][0], bq[nb][1], bq[nb][2], bq[nb][3],
                        smBlo + b_rdb + nb * 16 * 272 + ks * 32);
            #pragma unroll
            for (int nb = 0; nb < 4; ++nb)
                #pragma unroll
                for (int i = 0; i < 2; ++i) {
                    MMA_F16(acc[i][2 * nb],     a[i][0], a[i][1], a[i][2], a[i][3],
                            bq[nb][0], bq[nb][1]);
                    MMA_F16(acc[i][2 * nb + 1], a[i][0], a[i][1], a[i][2], a[i][3],
                            bq[nb][2], bq[nb][3]);
                }
        }
    };

    for (int tap = 0; tap < 25; ++tap) {
        __syncthreads();
        stage_A(inHi, tap);
        stage_Btile(wHi, tap, smBhi);
        stage_Btile(wLo, tap, smBlo);
        CP_COMMIT();
        CP_WAIT0();
        __syncthreads();
        mma_dual();
        __syncthreads();
        stage_A(inLo, tap);
        CP_COMMIT();
        CP_WAIT0();
        __syncthreads();
        mma_one(smBhi);
    }

    #pragma unroll
    for (int mb = 0; mb < 2; ++mb) {
        const int row0 = pbase + pxg * 32 + mb * 16 + (lane >> 2);
        const int row1 = row0 + 8;
        const bool v0 = (row0 < totalPx), v1 = (row1 < totalPx);
        #pragma unroll
        for (int nt = 0; nt < 8; ++nt) {
            const int co = cog * 64 + nt * 8 + 2 * (lane & 3);
            const float bz0 = sbias[co], bz1 = sbias[co + 1];
            float p00 = acc[mb][nt][0] + bz0, p01 = acc[mb][nt][1] + bz1;
            float p10 = acc[mb][nt][2] + bz0, p11 = acc[mb][nt][3] + bz1;
            if (relu) {
                p00 = fmaxf(p00, 0.f); p01 = fmaxf(p01, 0.f);
                p10 = fmaxf(p10, 0.f); p11 = fmaxf(p11, 0.f);
            }
            if (v0) *(float2*)(outp + (size_t)row0 * 128 + co) = make_float2(p00, p01);
            if (v1) *(float2*)(outp + (size_t)row1 * 128 + co) = make_float2(p10, p11);
        }
    }
}

// ====== fp8 1-pass engine, M=128, 2 CTAs/SM, A single + B double ==============
__global__ void __launch_bounds__(256, 2)
tc_f8(const uint8_t* __restrict__ in, const uint8_t* __restrict__ wpack,
      const float* __restrict__ bias, uint8_t* __restrict__ outp,
      int Hin, int Win, int Hout, int Wout, int pad, int K)
{
    extern __shared__ char dsm[];
    __shared__ float sbias[128];
    const int tid  = threadIdx.x;
    const int wid  = tid >> 5;
    const int lane = tid & 31;
    const int Npix = Hout * Wout;
    const int totalPx = BB * Npix;
    const int pbase = blockIdx.x * 128;

    const uint32_t smA = smem_u32(dsm);      // 1 x FTILE
    const uint32_t smB = smA + FTILE;        // 2 x FTILE
    if (tid < 128) sbias[tid] = bias[tid];

    const int arow = tid >> 1, ahalf = tid & 1;
    const int ap = pbase + arow;
    const bool apv = (ap < totalPx);
    const int bA  = apv ? ap / Npix : 0;
    const int apn = apv ? ap - bA * Npix : 0;
    const int apy = apn / Wout;
    const int apx = apn - apy * Wout;
    const uint32_t adst0 = smA + arow * 144 + ahalf * 64;

    const int pxg = wid >> 1, cog = wid & 1;
    float acc[2][8][4];
    #pragma unroll
    for (int m = 0; m < 2; m++)
        #pragma unroll
        for (int n = 0; n < 8; n++)
            #pragma unroll
            for (int j = 0; j < 4; j++) acc[m][n][j] = 0.f;

    const uint32_t a_rd0 = smA + (pxg * 32 + (lane & 15)) * 144 + ((lane >> 4) << 4);
    const uint32_t b_rdb = (cog * 64 + ((lane >> 4) << 3) + (lane & 7)) * 144
                         + (((lane >> 3) & 1) << 4);
    const int NIT = K * K;

    auto stage_A = [&](int it) {
        const int ky = it / K, kx = it - (it / K) * K;
        const int iy = apy + ky - pad, ix = apx + kx - pad;
        const bool inb = apv && (unsigned)iy < (unsigned)Hin && (unsigned)ix < (unsigned)Win;
        const char* as = inb ? (const char*)(in + ((size_t)(bA * Hin + iy) * Win + ix) * 128
                                             + ahalf * 64)
                             : (const char*)in;
        const int sz = inb ? 16 : 0;
        #pragma unroll
        for (int j = 0; j < 4; ++j)
            CP16(adst0 + j * 16, as + (size_t)j * 16, sz);
    };

    auto stage_B = [&](int tap) {
        const char* wb = (const char*)(wpack + (size_t)tap * 128 * 144);
        const uint32_t bd = smB + (tap & 1) * FTILE;
        #pragma unroll
        for (int j = 0; j < 4; ++j) {
            int i = j * 256 + tid;          // 1024 chunks: 128 rows x 8
            int row = i >> 3, c = i & 7;
            uint32_t off = row * 144 + c * 16;
            CP16(bd + off, wb + off, 16);
        }
    };

    stage_B(0);
    CP_COMMIT();
    for (int it = 0; it < NIT; ++it) {
        stage_A(it);
        CP_COMMIT();
        if (it + 1 < NIT) {
            stage_B(it + 1);                // prefetched under MMA(it)
            CP_COMMIT();
            CP_WAIT1();
        } else {
            CP_WAIT0();
        }
        __syncthreads();
        const uint32_t bbase = smB + (it & 1) * FTILE;
        #pragma unroll
        for (int ks = 0; ks < 4; ++ks) {    // k32 per step
            uint32_t a[2][4], bq[4][4];
            #pragma unroll
            for (int i = 0; i < 2; ++i)
                LDSM_X4(a[i][0], a[i][1], a[i][2], a[i][3],
                        a_rd0 + i * 16 * 144 + ks * 32);
            #pragma unroll
            for (int nb = 0; nb < 4; ++nb)
                LDSM_X4(bq[nb][0], bq[nb][1], bq[nb][2], bq[nb][3],
                        bbase + b_rdb + nb * 16 * 144 + ks * 32);
            #pragma unroll
            for (int nb = 0; nb < 4; ++nb)
                #pragma unroll
                for (int i = 0; i < 2; ++i) {
                    MMA_FP8(acc[i][2 * nb],     a[i][0], a[i][1], a[i][2], a[i][3],
                            bq[nb][0], bq[nb][1]);
                    MMA_FP8(acc[i][2 * nb + 1], a[i][0], a[i][1], a[i][2], a[i][3],
                            bq[nb][2], bq[nb][3]);
                }
        }
        __syncthreads();                    // protect single-buffered A
    }

    #pragma unroll
    for (int mb = 0; mb < 2; ++mb) {
        const int row0 = pbase + pxg * 32 + mb * 16 + (lane >> 2);
        const int row1 = row0 + 8;
        const bool v0 = (row0 < totalPx), v1 = (row1 < totalPx);
        #pragma unroll
        for (int nt = 0; nt < 8; ++nt) {
            const int co = cog * 64 + nt * 8 + 2 * (lane & 3);
            const float bz0 = sbias[co], bz1 = sbias[co + 1];
            float p00 = fmaxf(acc[mb][nt][0] + bz0, 0.f);
            float p01 = fmaxf(acc[mb][nt][1] + bz1, 0.f);
            float p10 = fmaxf(acc[mb][nt][2] + bz0, 0.f);
            float p11 = fmaxf(acc[mb][nt][3] + bz1, 0.f);
            if (v0) {
                __nv_fp8x2_storage_t h =
                    __nv_cvt_float2_to_fp8x2(make_float2(p00, p01), __NV_SATFINITE, __NV_E4M3);
                *(uint16_t*)(outp + (size_t)row0 * 128 + co) = h;
            }
            if (v1) {
                __nv_fp8x2_storage_t h =
                    __nv_cvt_float2_to_fp8x2(make_float2(p10, p11), __NV_SATFINITE, __NV_E4M3);
                *(uint16_t*)(outp + (size_t)row1 * 128 + co) = h;
            }
        }
    }
}

// ====== fp8 t2 stride-2 deconv, parity decomposition ==========================
__global__ void __launch_bounds__(256, 2)
tc_t2_f8(const uint8_t* __restrict__ in, const uint8_t* __restrict__ wpack,
         const float* __restrict__ bias, uint8_t* __restrict__ outp)
{
    extern __shared__ char dsm[];
    __shared__ float sbias[128];
    const int tid  = threadIdx.x;
    const int wid  = tid >> 5;
    const int lane = tid & 31;
    const int par  = blockIdx.z;
    const int py   = par >> 1, px = par & 1;
    const int totalPx = BB * 100;
    const int pbase = blockIdx.x * 128;

    const uint32_t smA = smem_u32(dsm);
    const uint32_t smB = smA + FTILE;
    if (tid < 128) sbias[tid] = bias[tid];

    const int arow = tid >> 1, ahalf = tid & 1;
    const int ap = pbase + arow;
    const bool apv = (ap < totalPx);
    const int bA  = apv ? ap / 100 : 0;
    const int apn = apv ? ap - bA * 100 : 0;
    const int apy = apn / 10;
    const int apx = apn - apy * 10;
    const uint32_t adst0 = smA + arow * 144 + ahalf * 64;

    const int pxg = wid >> 1, cog = wid & 1;
    float acc[2][8][4];
    #pragma unroll
    for (int m = 0; m < 2; m++)
        #pragma unroll
        for (int n = 0; n < 8; n++)
            #pragma unroll
            for (int j = 0; j < 4; j++) acc[m][n][j] = 0.f;

    const uint32_t a_rd0 = smA + (pxg * 32 + (lane & 15)) * 144 + ((lane >> 4) << 4);
    const uint32_t b_rdb = (cog * 64 + ((lane >> 4) << 3) + (lane & 7)) * 144
                         + (((lane >> 3) & 1) << 4);

    auto stage_A = [&](int tap) {
        const int ti = tap >> 1, tj = tap & 1;
        const int iy = apy - ti, ix = apx - tj;
        const bool inb = apv && (unsigned)iy < 9u && (unsigned)ix < 9u;
        const char* as = inb ? (const char*)(in + ((size_t)(bA * 9 + iy) * 9 + ix) * 128
                                             + ahalf * 64)
                             : (const char*)in;
        const int sz = inb ? 16 : 0;
        #pragma unroll
        for (int j = 0; j < 4; ++j)
            CP16(adst0 + j * 16, as + (size_t)j * 16, sz);
    };

    auto stage_B = [&](int tap) {
        const char* wb = (const char*)(wpack + (size_t)(par * 4 + tap) * 128 * 144);
        const uint32_t bd = smB + (tap & 1) * FTILE;
        #pragma unroll
        for (int j = 0; j < 4; ++j) {
            int i = j * 256 + tid;
            int row = i >> 3, c = i & 7;
            uint32_t off = row * 144 + c * 16;
            CP16(bd + off, wb + off, 16);
        }
    };

    stage_B(0);
    CP_COMMIT();
    for (int it = 0; it < 4; ++it) {
        stage_A(it);
        CP_COMMIT();
        if (it + 1 < 4) {
            stage_B(it + 1);
            CP_COMMIT();
            CP_WAIT1();
        } else {
            CP_WAIT0();
        }
        __syncthreads();
        const uint32_t bbase = smB + (it & 1) * FTILE;
        #pragma unroll
        for (int ks = 0; ks < 4; ++ks) {
            uint32_t a[2][4], bq[4][4];
            #pragma unroll
            for (int i = 0; i < 2; ++i)
                LDSM_X4(a[i][0], a[i][1], a[i][2], a[i][3],
                        a_rd0 + i * 16 * 144 + ks * 32);
            #pragma unroll
            for (int nb = 0; nb < 4; ++nb)
                LDSM_X4(bq[nb][0], bq[nb][1], bq[nb][2], bq[nb][3],
                        bbase + b_rdb + nb * 16 * 144 + ks * 32);
            #pragma unroll
            for (int nb = 0; nb < 4; ++nb)
                #pragma unroll
                for (int i = 0; i < 2; ++i) {
                    MMA_FP8(acc[i][2 * nb],     a[i][0], a[i][1], a[i][2], a[i][3],
                            bq[nb][0], bq[nb][1]);
                    MMA_FP8(acc[i][2 * nb + 1], a[i][0], a[i][1], a[i][2], a[i][3],
                            bq[nb][2], bq[nb][3]);
                }
        }
        __syncthreads();
    }

    #pragma unroll
    for (int mb = 0; mb < 2; ++mb) {
        const int r0g = pbase + pxg * 32 + mb * 16 + (lane >> 2);
        const int r1g = r0g + 8;
        int b0 = r0g / 100, q0 = r0g - b0 * 100, y0 = q0 / 10, x0 = q0 - y0 * 10;
        int b1 = r1g / 100, q1 = r1g - b1 * 100, y1 = q1 / 10, x1 = q1 - y1 * 10;
        size_t o0 = ((size_t)b0 * 400 + (2 * y0 + py) * 20 + 2 * x0 + px) * 128;
        size_t o1 = ((size_t)b1 * 400 + (2 * y1 + py) * 20 + 2 * x1 + px) * 128;
        #pragma unroll
        for (int nt = 0; nt < 8; ++nt) {
            const int co = cog * 64 + nt * 8 + 2 * (lane & 3);
            const float bz0 = sbias[co], bz1 = sbias[co + 1];
            float p00 = fmaxf(acc[mb][nt][0] + bz0, 0.f);
            float p01 = fmaxf(acc[mb][nt][1] + bz1, 0.f);
            float p10 = fmaxf(acc[mb][nt][2] + bz0, 0.f);
            float p11 = fmaxf(acc[mb][nt][3] + bz1, 0.f);
            if (r0g < totalPx) {
                __nv_fp8x2_storage_t h =
                    __nv_cvt_float2_to_fp8x2(make_float2(p00, p01), __NV_SATFINITE, __NV_E4M3);
                *(uint16_t*)(outp + o0 + co) = h;
            }
            if (r1g < totalPx) {
                __nv_fp8x2_storage_t h =
                    __nv_cvt_float2_to_fp8x2(make_float2(p10, p11), __NV_SATFINITE, __NV_E4M3);
                *(uint16_t*)(outp + o1 + co) = h;
            }
        }
    }
}

// ---------------- conv1: 8 px/block, weights in registers ---------------------
__global__ void __launch_bounds__(128)
conv1_split(const float* __restrict__ x, const float* __restrict__ w1,
            const float* __restrict__ b1, __half* __restrict__ hi,
            __half* __restrict__ lo)
{
    const int b = blockIdx.x, g = blockIdx.y;
    const int p0 = g * 8;
    const int oy = p0 / 24, ox0 = p0 - oy * 24;
    const int co = threadIdx.x;
    __shared__ float xs[5][12];
    for (int i = co; i < 60; i += 128) {
        int r = i / 12, c = i - r * 12;
        xs[r][c] = x[(size_t)b * 784 + (oy + r) * 28 + ox0 + c];
    }
    __syncthreads();
    float w[25];
    #pragma unroll
    for (int t = 0; t < 25; ++t) w[t] = w1[co * 25 + t];
    const float bz = b1[co];
    #pragma unroll
    for (int px = 0; px < 8; ++px) {
        float v = bz;
        #pragma unroll
        for (int t = 0; t < 25; ++t)
            v += w[t] * xs[t / 5][t % 5 + px];
        v = fmaxf(v, 0.f);
        __half h = __float2half_rn(v);
        size_t o = ((size_t)b * 576 + p0 + px) * 128 + co;
        hi[o] = h;
        lo[o] = __float2half_rn(v - __half2float(h));
    }
}

// ---------------- NHWC maxpool 2x2: fp32 -> fp16 hi/lo -----------------------
__global__ void mp_split_nhwc(const float* __restrict__ in, __half* __restrict__ hi,
                              __half* __restrict__ lo, int Hin, int Win)
{
    const int Ho = Hin >> 1, Wo = Win >> 1;
    const size_t total = (size_t)BB * Ho * Wo * 128;
    for (size_t i = (size_t)blockIdx.x * blockDim.x + threadIdx.x; i < total;
         i += (size_t)gridDim.x * blockDim.x) {
        int c = (int)(i & 127);
        size_t r = i >> 7;
        int wo = (int)(r % Wo); r /= Wo;
        int ho = (int)(r % Ho); int b = (int)(r / Ho);
        const float* p = in + (((size_t)b * Hin + 2 * ho) * Win + 2 * wo) * 128 + c;
        float v = fmaxf(fmaxf(p[0], p[128]),
                        fmaxf(p[(size_t)Win * 128], p[(size_t)(Win + 1) * 128]));
        __half h = __float2half_rn(v);
        hi[i] = h;
        lo[i] = __float2half_rn(v - __half2float(h));
    }
}

// ---------------- NHWC maxpool 2x2: fp32 -> fp32 -----------------------------
__global__ void mp_nhwc(const float* __restrict__ in, float* __restrict__ out,
                        int Hin, int Win)
{
    const int Ho = Hin >> 1, Wo = Win >> 1;
    const size_t total = (size_t)BB * Ho * Wo * 128;
    for (size_t i = (size_t)blockIdx.x * blockDim.x + threadIdx.x; i < total;
         i += (size_t)gridDim.x * blockDim.x) {
        int c = (int)(i & 127);
        size_t r = i >> 7;
        int wo = (int)(r % Wo); r /= Wo;
        int ho = (int)(r % Ho); int b = (int)(r / Ho);
        const float* p = in + (((size_t)b * Hin + 2 * ho) * Win + 2 * wo) * 128 + c;
        out[i] = fmaxf(fmaxf(p[0], p[128]),
                       fmaxf(p[(size_t)Win * 128], p[(size_t)(Win + 1) * 128]));
    }
}

// ---------------- VQ: argmax(d2), gather val (NHWC fp8), dict MSE -------------
__global__ void __launch_bounds__(256)
vq_kernel(const float* __restrict__ z, const float* __restrict__ dict,
          uint8_t* __restrict__ valf8, float* __restrict__ idx_out)
{
    extern __shared__ float dsmf[];
    __shared__ float zt[36 * 128];
    __shared__ float wn[128];
    __shared__ int   sidx[36];

    const int b = blockIdx.x, tid = threadIdx.x;

    for (int i = tid; i < 128 * 128; i += NT) {
        int k = i >> 7; int c = i & 127;
        dsmf[k * 129 + c] = dict[i];
    }
    for (int i = tid; i < 36 * 128; i += NT)
        zt[i] = z[(size_t)b * 4608 + i];
    __syncthreads();
    if (tid < 128) {
        float s = 0.f;
        const float* dp = dsmf + tid * 129;
        for (int c = 0; c < 128; c++) s += dp[c] * dp[c];
        wn[tid] = s;
    }
    __syncthreads();

    const int lane = tid & 31, wid = tid >> 5;
    for (int pos = wid; pos < 36; pos += 8) {
        float d0 = 0.f, d1 = 0.f, d2s = 0.f, d3 = 0.f, zn = 0.f;
        const float* zp = zt + pos * 128;
        const float* p0 = dsmf + (lane      ) * 129;
        const float* p1 = dsmf + (lane + 32 ) * 129;
        const float* p2 = dsmf + (lane + 64 ) * 129;
        const float* p3 = dsmf + (lane + 96 ) * 129;
        for (int c = 0; c < 128; c++) {
            float zv = zp[c];
            zn += zv * zv;
            d0 += p0[c] * zv; d1 += p1[c] * zv;
            d2s += p2[c] * zv; d3 += p3[c] * zv;
        }
        float bv = zn + wn[lane] - 2.f * d0; int bk = lane;
        float v1 = zn + wn[lane + 32] - 2.f * d1; if (v1 > bv) { bv = v1; bk = lane + 32; }
        float v2 = zn + wn[lane + 64] - 2.f * d2s; if (v2 > bv) { bv = v2; bk = lane + 64; }
        float v3 = zn + wn[lane + 96] - 2.f * d3; if (v3 > bv) { bv = v3; bk = lane + 96; }
        #pragma unroll
        for (int o = 16; o; o >>= 1) {
            float ov = __shfl_xor_sync(0xffffffffu, bv, o);
            int   ok = __shfl_xor_sync(0xffffffffu, bk, o);
            if (ov > bv || (ov == bv && ok < bk)) { bv = ov; bk = ok; }
        }
        if (lane == 0) {
            sidx[pos] = bk;
            if (idx_out) idx_out[b * 36 + pos] = (float)bk;
        }
    }
    __syncthreads();

    float lsum = 0.f;
    for (int i = tid; i < 4608; i += NT) {
        int pos = i >> 7; int c = i & 127;
        float v  = dsmf[sidx[pos] * 129 + c];
        float zv = zt[i];
        valf8[(size_t)b * 4608 + i] =
            __nv_cvt_float_to_fp8(v, __NV_SATFINITE, __NV_E4M3);
        float d = v - zv;
        lsum += d * d;
    }
    lsum = warp_sum(lsum);
    if ((tid & 31) == 0) atomicAdd(&g_dict_sum, (double)lsum);
}

// ---------------- mu (1x1 conv) fused with reconstruction loss (NHWC fp8) ----
__global__ void __launch_bounds__(256)
mu_loss(const uint8_t* __restrict__ f4, const float* __restrict__ x,
        const float* __restrict__ mw, const float* __restrict__ mb)
{
    __shared__ float mws[128];
    const int b = blockIdx.x, tid = threadIdx.x;
    if (tid < 128) mws[tid] = mw[tid];
    __syncthreads();
    float lsum = 0.f;
    for (int px = tid; px < 784; px += NT) {
        const uint4* fp = (const uint4*)(f4 + ((size_t)b * 784 + px) * 128);
        float s = mb[0];
        #pragma unroll
        for (int j = 0; j < 8; j++) {
            uint4 v = fp[j];
            const uint16_t* hb = (const uint16_t*)&v;
            #pragma unroll
            for (int t = 0; t < 8; t++) {
                __half2 h2 = __half2(__nv_cvt_fp8x2_to_halfraw2(hb[t], __NV_E4M3));
                s += __low2float(h2)  * mws[j * 16 + 2 * t]
                   + __high2float(h2) * mws[j * 16 + 2 * t + 1];
            }
        }
        float d = s - x[(size_t)b * 784 + px];
        lsum += d * d;
    }
    lsum = warp_sum(lsum);
    if ((tid & 31) == 0) atomicAdd(&g_rec_sum, (double)lsum);
}

__global__ void finalize_kernel(float* loss_out)
{
    if (loss_out) {
        double dict_mse = g_dict_sum / 1179648.0;
        loss_out[0] = (float)(g_rec_sum / 200704.0);
        loss_out[1] = (float)(dict_mse * 5.0);
        loss_out[2] = (float)(dict_mse * 1.25);
        loss_out[3] = 0.f;
    }
}

// ---------------- host side ----------------------------------------------------
extern "C" void kernel_launch(void* const* d_in, const int* in_sizes, int n_in,
                              void* d_out, int out_size)
{
    const float* x    = (const float*)d_in[0];
    const float* w1   = (const float*)d_in[1];
    const float* b1   = (const float*)d_in[2];
    const float* w2   = (const float*)d_in[3];
    const float* b2   = (const float*)d_in[4];
    const float* w3   = (const float*)d_in[5];
    const float* b3   = (const float*)d_in[6];
    const float* t1w  = (const float*)d_in[7];
    const float* t1b  = (const float*)d_in[8];
    const float* t2w  = (const float*)d_in[9];
    const float* t2b  = (const float*)d_in[10];
    const float* t3w  = (const float*)d_in[11];
    const float* t3b  = (const float*)d_in[12];
    const float* t4w  = (const float*)d_in[13];
    const float* t4b  = (const float*)d_in[14];
    const float* mw   = (const float*)d_in[15];
    const float* mb   = (const float*)d_in[16];
    const float* dictw= (const float*)d_in[17];

    float* outp = (float*)d_out;
    float* loss_ptr = outp;
    float* idx_ptr  = outp + 4;
    if (out_size < 9220) { loss_ptr = nullptr; idx_ptr = outp; }

    __half *c1hi, *c1lo, *p1hi, *p1lo, *w2hi, *w2lo, *w3hi, *w3lo;
    float *c2f, *c3f, *zn;
    uint8_t *valf8, *f1f8, *f2f8, *f3f8, *f4f8, *wp1, *wpt2, *wp3, *wp4;
    cudaGetSymbolAddress((void**)&c1hi, g_c1hi);
    cudaGetSymbolAddress((void**)&c1lo, g_c1lo);
    cudaGetSymbolAddress((void**)&c2f,  g_c2f);
    cudaGetSymbolAddress((void**)&p1hi, g_p1hi);
    cudaGetSymbolAddress((void**)&p1lo, g_p1lo);
    cudaGetSymbolAddress((void**)&c3f,  g_c3f);
    cudaGetSymbolAddress((void**)&zn,   g_zn);
    cudaGetSymbolAddress((void**)&valf8, g_valf8);
    cudaGetSymbolAddress((void**)&f1f8,  g_f1f8);
    cudaGetSymbolAddress((void**)&f2f8,  g_f2f8);
    cudaGetSymbolAddress((void**)&f3f8,  g_f3f8);
    cudaGetSymbolAddress((void**)&f4f8,  g_f4f8);
    cudaGetSymbolAddress((void**)&wp1,  g_wp1f8);
    cudaGetSymbolAddress((void**)&wpt2, g_wpt2f8);
    cudaGetSymbolAddress((void**)&wp3,  g_wp3f8);
    cudaGetSymbolAddress((void**)&wp4,  g_wp4f8);
    cudaGetSymbolAddress((void**)&w2hi, g_w2hi);
    cudaGetSymbolAddress((void**)&w2lo, g_w2lo);
    cudaGetSymbolAddress((void**)&w3hi, g_w3hi);
    cudaGetSymbolAddress((void**)&w3lo, g_w3lo);

    static bool attr_set = false;
    if (!attr_set) {
        cudaFuncSetAttribute(vq_kernel, cudaFuncAttributeMaxDynamicSharedMemorySize,
                             128 * 129 * (int)sizeof(float));
        cudaFuncSetAttribute(tc_f8, cudaFuncAttributeMaxDynamicSharedMemorySize,
                             3 * FTILE);
        cudaFuncSetAttribute(tc_t2_f8, cudaFuncAttributeMaxDynamicSharedMemorySize,
                             3 * FTILE);
        cudaFuncSetAttribute(tc_enc3, cudaFuncAttributeMaxDynamicSharedMemorySize,
                             3 * TILE);
        attr_set = true;
    }

    prepack_all<<<132, 256>>>(w2, w3, t1w, t2w, t3w, t4w,
                              w2hi, w2lo, w3hi, w3lo, wp1, wpt2, wp3, wp4);
    conv1_split<<<dim3(BB, 72), 128>>>(x, w1, b1, c1hi, c1lo);
    tc_enc3<<<1152, 256, 3 * TILE>>>(
        (const uint16_t*)c1hi, (const uint16_t*)c1lo,
        (const uint16_t*)w2hi, (const uint16_t*)w2lo,
        b2, c2f, 24, 24, 24, 24, 2, 1);
    mp_split_nhwc<<<4096, 256>>>(c2f, p1hi, p1lo, 24, 24);
    tc_enc3<<<288, 256, 3 * TILE>>>(
        (const uint16_t*)p1hi, (const uint16_t*)p1lo,
        (const uint16_t*)w3hi, (const uint16_t*)w3lo,
        b3, c3f, 12, 12, 12, 12, 2, 0);
    mp_nhwc<<<2048, 256>>>(c3f, zn, 12, 12);

    vq_kernel<<<BB, NT, 128 * 129 * sizeof(float)>>>(zn, dictw, valf8, idx_ptr);

    tc_f8<<<162, 256, 3 * FTILE>>>(valf8, wp1, t1b, f1f8, 6, 6, 9, 9, 3, 4);
    tc_t2_f8<<<dim3(200, 1, 4), 256, 3 * FTILE>>>(f1f8, wpt2, t2b, f2f8);
    tc_f8<<<1152, 256, 3 * FTILE>>>(f2f8, wp3, t3b, f3f8, 20, 20, 24, 24, 4, 5);
    tc_f8<<<1568, 256, 3 * FTILE>>>(f3f8, wp4, t4b, f4f8, 24, 24, 28, 28, 4, 5);

    mu_loss<<<BB, NT>>>(f4f8, x, mw, mb);
    finalize_kernel<<<1, 1>>>(loss_ptr);
}

// round 17
// speedup vs baseline: 1.1385x; 1.0111x over previous
#include <cuda_runtime.h>
#include <cuda_bf16.h>
#include <cuda_fp16.h>
#include <cuda_fp8.h>
#include <cstdint>

#define BB 256
#define NT 256
#define TILE 34816          // bf16/fp16 tile: 128 rows x 272B
#define FTILE 18432         // fp8 tile: 128 rows x 144B

// ---------------- scratch (device globals; no allocation APIs) ---------------
__device__ __half g_c1hi[(size_t)BB*576*128];
__device__ __half g_c1lo[(size_t)BB*576*128];
__device__ float  g_c2f [(size_t)BB*576*128];
__device__ __half g_p1hi[(size_t)BB*144*128];
__device__ __half g_p1lo[(size_t)BB*144*128];
__device__ float  g_c3f [(size_t)BB*144*128];
__device__ float  g_zn  [(size_t)BB*36*128];
__device__ uint8_t g_valf8[(size_t)BB*36*128];   // codes, NHWC e4m3
__device__ uint8_t g_f1f8[(size_t)BB*81*128];
__device__ uint8_t g_f2f8[(size_t)BB*400*128];
__device__ uint8_t g_f3f8[(size_t)BB*576*128];
__device__ uint8_t g_f4f8[(size_t)BB*784*128];
// fp8 packed weights, pitch 144B per co-row
__device__ uint8_t g_wp1f8[16*128*144];
__device__ uint8_t g_wpt2f8[16*128*144];
__device__ uint8_t g_wp3f8[25*128*144];
__device__ uint8_t g_wp4f8[25*128*144];
__device__ __half g_w2hi[25*128*136];
__device__ __half g_w2lo[25*128*136];
__device__ __half g_w3hi[25*128*136];
__device__ __half g_w3lo[25*128*136];
__device__ double g_rec_sum;
__device__ double g_dict_sum;

__inline__ __device__ float warp_sum(float v) {
    #pragma unroll
    for (int o = 16; o; o >>= 1) v += __shfl_xor_sync(0xffffffffu, v, o);
    return v;
}

// ---------------- mma / cp.async helpers --------------------------------------
__device__ __forceinline__ uint32_t smem_u32(const void* p) {
    uint32_t a;
    asm("{ .reg .u64 t; cvta.to.shared.u64 t, %1; cvt.u32.u64 %0, t; }"
        : "=r"(a) : "l"(p));
    return a;
}

#define LDSM_X4(r0, r1, r2, r3, addr)                                          \
    asm volatile("ldmatrix.sync.aligned.m8n8.x4.shared.b16 {%0,%1,%2,%3}, [%4];" \
                 : "=r"(r0), "=r"(r1), "=r"(r2), "=r"(r3) : "r"(addr))

#define MMA_F16(c, a0, a1, a2, a3, b0, b1)                                     \
    asm volatile("mma.sync.aligned.m16n8k16.row.col.f32.f16.f16.f32 "          \
                 "{%0,%1,%2,%3}, {%4,%5,%6,%7}, {%8,%9}, {%0,%1,%2,%3};"       \
                 : "+f"((c)[0]), "+f"((c)[1]), "+f"((c)[2]), "+f"((c)[3])      \
                 : "r"(a0), "r"(a1), "r"(a2), "r"(a3), "r"(b0), "r"(b1))

#define MMA_FP8(c, a0, a1, a2, a3, b0, b1)                                     \
    asm volatile("mma.sync.aligned.m16n8k32.row.col.f32.e4m3.e4m3.f32 "        \
                 "{%0,%1,%2,%3}, {%4,%5,%6,%7}, {%8,%9}, {%0,%1,%2,%3};"       \
                 : "+f"((c)[0]), "+f"((c)[1]), "+f"((c)[2]), "+f"((c)[3])      \
                 : "r"(a0), "r"(a1), "r"(a2), "r"(a3), "r"(b0), "r"(b1))

#define CP16(d, s, n)                                                          \
    asm volatile("cp.async.cg.shared.global [%0], [%1], 16, %2;"               \
                 :: "r"(d), "l"(s), "r"(n))
#define CP_COMMIT() asm volatile("cp.async.commit_group;" ::: "memory")
#define CP_WAIT0()  asm volatile("cp.async.wait_group 0;" ::: "memory")
#define CP_WAIT1()  asm volatile("cp.async.wait_group 1;" ::: "memory")

// ---------------- fused weight prepack (all layers, one launch) ---------------
__device__ __forceinline__ void pp_fwd_split(const float* W, __half* dh, __half* dl,
                                             int tap)
{
    int ky = tap / 5, kx = tap - ky * 5;
    size_t tb = (size_t)tap * 128 * 136;
    for (int i = threadIdx.x; i < 16384; i += blockDim.x) {
        int co = i >> 7, ci = i & 127;
        float v = W[(((size_t)co * 128 + ci) * 5 + ky) * 5 + kx];
        __half h = __float2half_rn(v);
        dh[tb + co * 136 + ci] = h;
        dl[tb + co * 136 + ci] = __float2half_rn(v - __half2float(h));
    }
}

__device__ __forceinline__ void pp_deconv_f8(const float* W, uint8_t* dst,
                                             int tap, int K)
{
    int ky = tap / K, kx = tap - ky * K;
    uint8_t* base = dst + (size_t)tap * 128 * 144;
    for (int i = threadIdx.x; i < 16384; i += blockDim.x) {
        int co = i >> 7, ci = i & 127;
        float v = W[(((size_t)ci * 128 + co) * K + (K - 1 - ky)) * K + (K - 1 - kx)];
        base[co * 144 + ci] = __nv_cvt_float_to_fp8(v, __NV_SATFINITE, __NV_E4M3);
    }
}

__device__ __forceinline__ void pp_t2_f8(const float* W, uint8_t* dst, int idx)
{
    int par = idx >> 2, tap = idx & 3;
    int py = par >> 1, px = par & 1;
    int ti = tap >> 1, tj = tap & 1;
    int ky = py + 2 * ti, kx = px + 2 * tj;
    uint8_t* base = dst + (size_t)idx * 128 * 144;
    for (int i = threadIdx.x; i < 16384; i += blockDim.x) {
        int co = i >> 7, ci = i & 127;
        float v = W[(((size_t)ci * 128 + co) * 4 + ky) * 4 + kx];
        base[co * 144 + ci] = __nv_cvt_float_to_fp8(v, __NV_SATFINITE, __NV_E4M3);
    }
}

__global__ void prepack_all(const float* w2, const float* w3,
                            const float* t1w, const float* t2w,
                            const float* t3w, const float* t4w,
                            __half* w2hi, __half* w2lo,
                            __half* w3hi, __half* w3lo,
                            uint8_t* wp1, uint8_t* wpt2,
                            uint8_t* wp3, uint8_t* wp4)
{
    int bid = blockIdx.x;
    if (bid == 0 && threadIdx.x == 0) { g_rec_sum = 0.0; g_dict_sum = 0.0; }
    if      (bid < 25)  pp_fwd_split(w2, w2hi, w2lo, bid);
    else if (bid < 50)  pp_fwd_split(w3, w3hi, w3lo, bid - 25);
    else if (bid < 66)  pp_deconv_f8(t1w, wp1, bid - 50, 4);
    else if (bid < 82)  pp_t2_f8(t2w, wpt2, bid - 66);
    else if (bid < 107) pp_deconv_f8(t3w, wp3, bid - 82, 5);
    else                pp_deconv_f8(t4w, wp4, bid - 107, 5);
}

// ====== fused 3-pass fp16-split encoder conv, tap-major, M=128, 2 CTAs/SM =====
__global__ void __launch_bounds__(256, 2)
tc_enc3(const uint16_t* __restrict__ inHi, const uint16_t* __restrict__ inLo,
        const uint16_t* __restrict__ wHi,  const uint16_t* __restrict__ wLo,
        const float* __restrict__ bias, float* __restrict__ outp,
        int Hin, int Win, int Hout, int Wout, int pad, int relu)
{
    extern __shared__ char dsm[];
    __shared__ float sbias[128];
    const int tid  = threadIdx.x;
    const int wid  = tid >> 5;
    const int lane = tid & 31;
    const int Npix = Hout * Wout;
    const int totalPx = BB * Npix;
    const int pbase = blockIdx.x * 128;

    const uint32_t smA   = smem_u32(dsm);
    const uint32_t smBhi = smA + TILE;
    const uint32_t smBlo = smBhi + TILE;
    if (tid < 128) sbias[tid] = bias[tid];

    const int arow = tid >> 1, ahalf = tid & 1;
    const int ap = pbase + arow;
    const bool apv = (ap < totalPx);
    const int bA  = apv ? ap / Npix : 0;
    const int apn = apv ? ap - bA * Npix : 0;
    const int apy = apn / Wout;
    const int apx = apn - apy * Wout;
    const uint32_t adst0 = smA + arow * 272 + ahalf * 128;

    const int pxg = wid >> 1, cog = wid & 1;
    float acc[2][8][4];
    #pragma unroll
    for (int m = 0; m < 2; m++)
        #pragma unroll
        for (int n = 0; n < 8; n++)
            #pragma unroll
            for (int j = 0; j < 4; j++) acc[m][n][j] = 0.f;

    const uint32_t a_rd0 = smA + (pxg * 32 + (lane & 15)) * 272 + ((lane >> 4) << 4);
    const uint32_t b_rdb = (cog * 64 + ((lane >> 4) << 3) + (lane & 7)) * 272
                         + (((lane >> 3) & 1) << 4);

    auto stage_A = [&](const uint16_t* abuf, int tap) {
        const int ky = tap / 5, kx = tap - ky * 5;
        const int iy = apy + ky - pad, ix = apx + kx - pad;
        const bool inb = apv && (unsigned)iy < (unsigned)Hin && (unsigned)ix < (unsigned)Win;
        const char* as = inb ? (const char*)(abuf + ((size_t)(bA * Hin + iy) * Win + ix) * 128
                                             + ahalf * 64)
                             : (const char*)abuf;
        const int sz = inb ? 16 : 0;
        #pragma unroll
        for (int j = 0; j < 8; ++j)
            CP16(adst0 + j * 16, as + (size_t)j * 16, sz);
    };

    auto stage_Btile = [&](const uint16_t* wbuf, int tap, uint32_t bd) {
        const char* wb = (const char*)(wbuf + (size_t)tap * 128 * 136);
        #pragma unroll
        for (int j = 0; j < 8; ++j)
            CP16(bd + (j * 256 + tid) * 16, wb + (size_t)(j * 256 + tid) * 16, 16);
        if (tid < 128)
            CP16(bd + (2048 + tid) * 16, wb + (size_t)(2048 + tid) * 16, 16);
    };

    auto mma_one = [&](uint32_t bbase) {
        #pragma unroll
        for (int ks = 0; ks < 8; ++ks) {
            uint32_t a[2][4], bq[4][4];
            #pragma unroll
            for (int i = 0; i < 2; ++i)
                LDSM_X4(a[i][0], a[i][1], a[i][2], a[i][3],
                        a_rd0 + i * 16 * 272 + ks * 32);
            #pragma unroll
            for (int nb = 0; nb < 4; ++nb)
                LDSM_X4(bq[nb][0], bq[nb][1], bq[nb][2], bq[nb][3],
                        bbase + b_rdb + nb * 16 * 272 + ks * 32);
            #pragma unroll
            for (int nb = 0; nb < 4; ++nb)
                #pragma unroll
                for (int i = 0; i < 2; ++i) {
                    MMA_F16(acc[i][2 * nb],     a[i][0], a[i][1], a[i][2], a[i][3],
                            bq[nb][0], bq[nb][1]);
                    MMA_F16(acc[i][2 * nb + 1], a[i][0], a[i][1], a[i][2], a[i][3],
                            bq[nb][2], bq[nb][3]);
                }
        }
    };

    auto mma_dual = [&]() {
        #pragma unroll
        for (int ks = 0; ks < 8; ++ks) {
            uint32_t a[2][4], bq[4][4];
            #pragma unroll
            for (int i = 0; i < 2; ++i)
                LDSM_X4(a[i][0], a[i][1], a[i][2], a[i][3],
                        a_rd0 + i * 16 * 272 + ks * 32);
            #pragma unroll
            for (int nb = 0; nb < 4; ++nb)
                LDSM_X4(bq[nb][0], bq[nb][1], bq[nb][2], bq[nb][3],
                        smBhi + b_rdb + nb * 16 * 272 + ks * 32);
            #pragma unroll
            for (int nb = 0; nb < 4; ++nb)
                #pragma unroll
                for (int i = 0; i < 2; ++i) {
                    MMA_F16(acc[i][2 * nb],     a[i][0], a[i][1], a[i][2], a[i][3],
                            bq[nb][0], bq[nb][1]);
                    MMA_F16(acc[i][2 * nb + 1], a[i][0], a[i][1], a[i][2], a[i][3],
                            bq[nb][2], bq[nb][3]);
                }
            #pragma unroll
            for (int nb = 0; nb < 4; ++nb)
                LDSM_X4(bq[nb][0], bq[nb][1], bq[nb][2], bq[nb][3],
                        smBlo + b_rdb + nb * 16 * 272 + ks * 32);
            #pragma unroll
            for (int nb = 0; nb < 4; ++nb)
                #pragma unroll
                for (int i = 0; i < 2; ++i) {
                    MMA_F16(acc[i][2 * nb],     a[i][0], a[i][1], a[i][2], a[i][3],
                            bq[nb][0], bq[nb][1]);
                    MMA_F16(acc[i][2 * nb + 1], a[i][0], a[i][1], a[i][2], a[i][3],
                            bq[nb][2], bq[nb][3]);
                }
        }
    };

    for (int tap = 0; tap < 25; ++tap) {
        __syncthreads();
        stage_A(inHi, tap);
        stage_Btile(wHi, tap, smBhi);
        stage_Btile(wLo, tap, smBlo);
        CP_COMMIT();
        CP_WAIT0();
        __syncthreads();
        mma_dual();
        __syncthreads();
        stage_A(inLo, tap);
        CP_COMMIT();
        CP_WAIT0();
        __syncthreads();
        mma_one(smBhi);
    }

    #pragma unroll
    for (int mb = 0; mb < 2; ++mb) {
        const int row0 = pbase + pxg * 32 + mb * 16 + (lane >> 2);
        const int row1 = row0 + 8;
        const bool v0 = (row0 < totalPx), v1 = (row1 < totalPx);
        #pragma unroll
        for (int nt = 0; nt < 8; ++nt) {
            const int co = cog * 64 + nt * 8 + 2 * (lane & 3);
            const float bz0 = sbias[co], bz1 = sbias[co + 1];
            float p00 = acc[mb][nt][0] + bz0, p01 = acc[mb][nt][1] + bz1;
            float p10 = acc[mb][nt][2] + bz0, p11 = acc[mb][nt][3] + bz1;
            if (relu) {
                p00 = fmaxf(p00, 0.f); p01 = fmaxf(p01, 0.f);
                p10 = fmaxf(p10, 0.f); p11 = fmaxf(p11, 0.f);
            }
            if (v0) *(float2*)(outp + (size_t)row0 * 128 + co) = make_float2(p00, p01);
            if (v1) *(float2*)(outp + (size_t)row1 * 128 + co) = make_float2(p10, p11);
        }
    }
}

// ====== fp8 1-pass engine, M=128, 2 CTAs/SM, A+B double-buffered, 1 sync/tap ==
__global__ void __launch_bounds__(256, 2)
tc_f8(const uint8_t* __restrict__ in, const uint8_t* __restrict__ wpack,
      const float* __restrict__ bias, uint8_t* __restrict__ outp,
      int Hin, int Win, int Hout, int Wout, int pad, int K)
{
    extern __shared__ char dsm[];
    __shared__ float sbias[128];
    const int tid  = threadIdx.x;
    const int wid  = tid >> 5;
    const int lane = tid & 31;
    const int Npix = Hout * Wout;
    const int totalPx = BB * Npix;
    const int pbase = blockIdx.x * 128;

    const uint32_t smA = smem_u32(dsm);      // 2 x FTILE (ping-pong)
    const uint32_t smB = smA + 2 * FTILE;    // 2 x FTILE (ping-pong)
    if (tid < 128) sbias[tid] = bias[tid];

    const int arow = tid >> 1, ahalf = tid & 1;
    const int ap = pbase + arow;
    const bool apv = (ap < totalPx);
    const int bA  = apv ? ap / Npix : 0;
    const int apn = apv ? ap - bA * Npix : 0;
    const int apy = apn / Wout;
    const int apx = apn - apy * Wout;
    const uint32_t adst0 = smA + arow * 144 + ahalf * 64;

    const int pxg = wid >> 1, cog = wid & 1;
    float acc[2][8][4];
    #pragma unroll
    for (int m = 0; m < 2; m++)
        #pragma unroll
        for (int n = 0; n < 8; n++)
            #pragma unroll
            for (int j = 0; j < 4; j++) acc[m][n][j] = 0.f;

    const uint32_t a_rd0 = smA + (pxg * 32 + (lane & 15)) * 144 + ((lane >> 4) << 4);
    const uint32_t b_rdb = (cog * 64 + ((lane >> 4) << 3) + (lane & 7)) * 144
                         + (((lane >> 3) & 1) << 4);
    const int NIT = K * K;

    auto stage_A = [&](int it) {
        const int ky = it / K, kx = it - (it / K) * K;
        const int iy = apy + ky - pad, ix = apx + kx - pad;
        const bool inb = apv && (unsigned)iy < (unsigned)Hin && (unsigned)ix < (unsigned)Win;
        const char* as = inb ? (const char*)(in + ((size_t)(bA * Hin + iy) * Win + ix) * 128
                                             + ahalf * 64)
                             : (const char*)in;
        const uint32_t ad = adst0 + (it & 1) * FTILE;
        const int sz = inb ? 16 : 0;
        #pragma unroll
        for (int j = 0; j < 4; ++j)
            CP16(ad + j * 16, as + (size_t)j * 16, sz);
    };

    auto stage_B = [&](int tap) {
        const char* wb = (const char*)(wpack + (size_t)tap * 128 * 144);
        const uint32_t bd = smB + (tap & 1) * FTILE;
        #pragma unroll
        for (int j = 0; j < 4; ++j) {
            int i = j * 256 + tid;          // 1024 chunks: 128 rows x 8
            int row = i >> 3, c = i & 7;
            uint32_t off = row * 144 + c * 16;
            CP16(bd + off, wb + off, 16);
        }
    };

    stage_A(0);
    stage_B(0);
    CP_COMMIT();
    for (int it = 0; it < NIT; ++it) {
        CP_WAIT0();
        __syncthreads();
        if (it + 1 < NIT) {
            stage_A(it + 1);                // parity buffers != current read
            stage_B(it + 1);
            CP_COMMIT();
        }
        const uint32_t abase = (it & 1) * FTILE;
        const uint32_t bbase = smB + (it & 1) * FTILE;
        #pragma unroll
        for (int ks = 0; ks < 4; ++ks) {    // k32 per step
            uint32_t a[2][4], bq[4][4];
            #pragma unroll
            for (int i = 0; i < 2; ++i)
                LDSM_X4(a[i][0], a[i][1], a[i][2], a[i][3],
                        a_rd0 + abase + i * 16 * 144 + ks * 32);
            #pragma unroll
            for (int nb = 0; nb < 4; ++nb)
                LDSM_X4(bq[nb][0], bq[nb][1], bq[nb][2], bq[nb][3],
                        bbase + b_rdb + nb * 16 * 144 + ks * 32);
            #pragma unroll
            for (int nb = 0; nb < 4; ++nb)
                #pragma unroll
                for (int i = 0; i < 2; ++i) {
                    MMA_FP8(acc[i][2 * nb],     a[i][0], a[i][1], a[i][2], a[i][3],
                            bq[nb][0], bq[nb][1]);
                    MMA_FP8(acc[i][2 * nb + 1], a[i][0], a[i][1], a[i][2], a[i][3],
                            bq[nb][2], bq[nb][3]);
                }
        }
        // no trailing sync: double-buffered A and B; next top-of-loop sync
        // (all warps past mma(it)) protects parity-buffer reuse
    }

    #pragma unroll
    for (int mb = 0; mb < 2; ++mb) {
        const int row0 = pbase + pxg * 32 + mb * 16 + (lane >> 2);
        const int row1 = row0 + 8;
        const bool v0 = (row0 < totalPx), v1 = (row1 < totalPx);
        #pragma unroll
        for (int nt = 0; nt < 8; ++nt) {
            const int co = cog * 64 + nt * 8 + 2 * (lane & 3);
            const float bz0 = sbias[co], bz1 = sbias[co + 1];
            float p00 = fmaxf(acc[mb][nt][0] + bz0, 0.f);
            float p01 = fmaxf(acc[mb][nt][1] + bz1, 0.f);
            float p10 = fmaxf(acc[mb][nt][2] + bz0, 0.f);
            float p11 = fmaxf(acc[mb][nt][3] + bz1, 0.f);
            if (v0) {
                __nv_fp8x2_storage_t h =
                    __nv_cvt_float2_to_fp8x2(make_float2(p00, p01), __NV_SATFINITE, __NV_E4M3);
                *(uint16_t*)(outp + (size_t)row0 * 128 + co) = h;
            }
            if (v1) {
                __nv_fp8x2_storage_t h =
                    __nv_cvt_float2_to_fp8x2(make_float2(p10, p11), __NV_SATFINITE, __NV_E4M3);
                *(uint16_t*)(outp + (size_t)row1 * 128 + co) = h;
            }
        }
    }
}

// ====== fp8 t2 stride-2 deconv, parity decomposition, full pipeline ===========
__global__ void __launch_bounds__(256, 2)
tc_t2_f8(const uint8_t* __restrict__ in, const uint8_t* __restrict__ wpack,
         const float* __restrict__ bias, uint8_t* __restrict__ outp)
{
    extern __shared__ char dsm[];
    __shared__ float sbias[128];
    const int tid  = threadIdx.x;
    const int wid  = tid >> 5;
    const int lane = tid & 31;
    const int par  = blockIdx.z;
    const int py   = par >> 1, px = par & 1;
    const int totalPx = BB * 100;
    const int pbase = blockIdx.x * 128;

    const uint32_t smA = smem_u32(dsm);
    const uint32_t smB = smA + 2 * FTILE;
    if (tid < 128) sbias[tid] = bias[tid];

    const int arow = tid >> 1, ahalf = tid & 1;
    const int ap = pbase + arow;
    const bool apv = (ap < totalPx);
    const int bA  = apv ? ap / 100 : 0;
    const int apn = apv ? ap - bA * 100 : 0;
    const int apy = apn / 10;
    const int apx = apn - apy * 10;
    const uint32_t adst0 = smA + arow * 144 + ahalf * 64;

    const int pxg = wid >> 1, cog = wid & 1;
    float acc[2][8][4];
    #pragma unroll
    for (int m = 0; m < 2; m++)
        #pragma unroll
        for (int n = 0; n < 8; n++)
            #pragma unroll
            for (int j = 0; j < 4; j++) acc[m][n][j] = 0.f;

    const uint32_t a_rd0 = smA + (pxg * 32 + (lane & 15)) * 144 + ((lane >> 4) << 4);
    const uint32_t b_rdb = (cog * 64 + ((lane >> 4) << 3) + (lane & 7)) * 144
                         + (((lane >> 3) & 1) << 4);

    auto stage_A = [&](int tap) {
        const int ti = tap >> 1, tj = tap & 1;
        const int iy = apy - ti, ix = apx - tj;
        const bool inb = apv && (unsigned)iy < 9u && (unsigned)ix < 9u;
        const char* as = inb ? (const char*)(in + ((size_t)(bA * 9 + iy) * 9 + ix) * 128
                                             + ahalf * 64)
                             : (const char*)in;
        const uint32_t ad = adst0 + (tap & 1) * FTILE;
        const int sz = inb ? 16 : 0;
        #pragma unroll
        for (int j = 0; j < 4; ++j)
            CP16(ad + j * 16, as + (size_t)j * 16, sz);
    };

    auto stage_B = [&](int tap) {
        const char* wb = (const char*)(wpack + (size_t)(par * 4 + tap) * 128 * 144);
        const uint32_t bd = smB + (tap & 1) * FTILE;
        #pragma unroll
        for (int j = 0; j < 4; ++j) {
            int i = j * 256 + tid;
            int row = i >> 3, c = i & 7;
            uint32_t off = row * 144 + c * 16;
            CP16(bd + off, wb + off, 16);
        }
    };

    stage_A(0);
    stage_B(0);
    CP_COMMIT();
    for (int it = 0; it < 4; ++it) {
        CP_WAIT0();
        __syncthreads();
        if (it + 1 < 4) {
            stage_A(it + 1);
            stage_B(it + 1);
            CP_COMMIT();
        }
        const uint32_t abase = (it & 1) * FTILE;
        const uint32_t bbase = smB + (it & 1) * FTILE;
        #pragma unroll
        for (int ks = 0; ks < 4; ++ks) {
            uint32_t a[2][4], bq[4][4];
            #pragma unroll
            for (int i = 0; i < 2; ++i)
                LDSM_X4(a[i][0], a[i][1], a[i][2], a[i][3],
                        a_rd0 + abase + i * 16 * 144 + ks * 32);
            #pragma unroll
            for (int nb = 0; nb < 4; ++nb)
                LDSM_X4(bq[nb][0], bq[nb][1], bq[nb][2], bq[nb][3],
                        bbase + b_rdb + nb * 16 * 144 + ks * 32);
            #pragma unroll
            for (int nb = 0; nb < 4; ++nb)
                #pragma unroll
                for (int i = 0; i < 2; ++i) {
                    MMA_FP8(acc[i][2 * nb],     a[i][0], a[i][1], a[i][2], a[i][3],
                            bq[nb][0], bq[nb][1]);
                    MMA_FP8(acc[i][2 * nb + 1], a[i][0], a[i][1], a[i][2], a[i][3],
                            bq[nb][2], bq[nb][3]);
                }
        }
    }

    #pragma unroll
    for (int mb = 0; mb < 2; ++mb) {
        const int r0g = pbase + pxg * 32 + mb * 16 + (lane >> 2);
        const int r1g = r0g + 8;
        int b0 = r0g / 100, q0 = r0g - b0 * 100, y0 = q0 / 10, x0 = q0 - y0 * 10;
        int b1 = r1g / 100, q1 = r1g - b1 * 100, y1 = q1 / 10, x1 = q1 - y1 * 10;
        size_t o0 = ((size_t)b0 * 400 + (2 * y0 + py) * 20 + 2 * x0 + px) * 128;
        size_t o1 = ((size_t)b1 * 400 + (2 * y1 + py) * 20 + 2 * x1 + px) * 128;
        #pragma unroll
        for (int nt = 0; nt < 8; ++nt) {
            const int co = cog * 64 + nt * 8 + 2 * (lane & 3);
            const float bz0 = sbias[co], bz1 = sbias[co + 1];
            float p00 = fmaxf(acc[mb][nt][0] + bz0, 0.f);
            float p01 = fmaxf(acc[mb][nt][1] + bz1, 0.f);
            float p10 = fmaxf(acc[mb][nt][2] + bz0, 0.f);
            float p11 = fmaxf(acc[mb][nt][3] + bz1, 0.f);
            if (r0g < totalPx) {
                __nv_fp8x2_storage_t h =
                    __nv_cvt_float2_to_fp8x2(make_float2(p00, p01), __NV_SATFINITE, __NV_E4M3);
                *(uint16_t*)(outp + o0 + co) = h;
            }
            if (r1g < totalPx) {
                __nv_fp8x2_storage_t h =
                    __nv_cvt_float2_to_fp8x2(make_float2(p10, p11), __NV_SATFINITE, __NV_E4M3);
                *(uint16_t*)(outp + o1 + co) = h;
            }
        }
    }
}

// ---------------- conv1: 8 px/block, weights in registers ---------------------
__global__ void __launch_bounds__(128)
conv1_split(const float* __restrict__ x, const float* __restrict__ w1,
            const float* __restrict__ b1, __half* __restrict__ hi,
            __half* __restrict__ lo)
{
    const int b = blockIdx.x, g = blockIdx.y;
    const int p0 = g * 8;
    const int oy = p0 / 24, ox0 = p0 - oy * 24;
    const int co = threadIdx.x;
    __shared__ float xs[5][12];
    for (int i = co; i < 60; i += 128) {
        int r = i / 12, c = i - r * 12;
        xs[r][c] = x[(size_t)b * 784 + (oy + r) * 28 + ox0 + c];
    }
    __syncthreads();
    float w[25];
    #pragma unroll
    for (int t = 0; t < 25; ++t) w[t] = w1[co * 25 + t];
    const float bz = b1[co];
    #pragma unroll
    for (int px = 0; px < 8; ++px) {
        float v = bz;
        #pragma unroll
        for (int t = 0; t < 25; ++t)
            v += w[t] * xs[t / 5][t % 5 + px];
        v = fmaxf(v, 0.f);
        __half h = __float2half_rn(v);
        size_t o = ((size_t)b * 576 + p0 + px) * 128 + co;
        hi[o] = h;
        lo[o] = __float2half_rn(v - __half2float(h));
    }
}

// ---------------- NHWC maxpool 2x2: fp32 -> fp16 hi/lo -----------------------
__global__ void mp_split_nhwc(const float* __restrict__ in, __half* __restrict__ hi,
                              __half* __restrict__ lo, int Hin, int Win)
{
    const int Ho = Hin >> 1, Wo = Win >> 1;
    const size_t total = (size_t)BB * Ho * Wo * 128;
    for (size_t i = (size_t)blockIdx.x * blockDim.x + threadIdx.x; i < total;
         i += (size_t)gridDim.x * blockDim.x) {
        int c = (int)(i & 127);
        size_t r = i >> 7;
        int wo = (int)(r % Wo); r /= Wo;
        int ho = (int)(r % Ho); int b = (int)(r / Ho);
        const float* p = in + (((size_t)b * Hin + 2 * ho) * Win + 2 * wo) * 128 + c;
        float v = fmaxf(fmaxf(p[0], p[128]),
                        fmaxf(p[(size_t)Win * 128], p[(size_t)(Win + 1) * 128]));
        __half h = __float2half_rn(v);
        hi[i] = h;
        lo[i] = __float2half_rn(v - __half2float(h));
    }
}

// ---------------- NHWC maxpool 2x2: fp32 -> fp32 -----------------------------
__global__ void mp_nhwc(const float* __restrict__ in, float* __restrict__ out,
                        int Hin, int Win)
{
    const int Ho = Hin >> 1, Wo = Win >> 1;
    const size_t total = (size_t)BB * Ho * Wo * 128;
    for (size_t i = (size_t)blockIdx.x * blockDim.x + threadIdx.x; i < total;
         i += (size_t)gridDim.x * blockDim.x) {
        int c = (int)(i & 127);
        size_t r = i >> 7;
        int wo = (int)(r % Wo); r /= Wo;
        int ho = (int)(r % Ho); int b = (int)(r / Ho);
        const float* p = in + (((size_t)b * Hin + 2 * ho) * Win + 2 * wo) * 128 + c;
        out[i] = fmaxf(fmaxf(p[0], p[128]),
                       fmaxf(p[(size_t)Win * 128], p[(size_t)(Win + 1) * 128]));
    }
}

// ---------------- VQ: argmax(d2), gather val (NHWC fp8), dict MSE -------------
__global__ void __launch_bounds__(256)
vq_kernel(const float* __restrict__ z, const float* __restrict__ dict,
          uint8_t* __restrict__ valf8, float* __restrict__ idx_out)
{
    extern __shared__ float dsmf[];
    __shared__ float zt[36 * 128];
    __shared__ float wn[128];
    __shared__ int   sidx[36];

    const int b = blockIdx.x, tid = threadIdx.x;

    for (int i = tid; i < 128 * 128; i += NT) {
        int k = i >> 7; int c = i & 127;
        dsmf[k * 129 + c] = dict[i];
    }
    for (int i = tid; i < 36 * 128; i += NT)
        zt[i] = z[(size_t)b * 4608 + i];
    __syncthreads();
    if (tid < 128) {
        float s = 0.f;
        const float* dp = dsmf + tid * 129;
        for (int c = 0; c < 128; c++) s += dp[c] * dp[c];
        wn[tid] = s;
    }
    __syncthreads();

    const int lane = tid & 31, wid = tid >> 5;
    for (int pos = wid; pos < 36; pos += 8) {
        float d0 = 0.f, d1 = 0.f, d2s = 0.f, d3 = 0.f, zn = 0.f;
        const float* zp = zt + pos * 128;
        const float* p0 = dsmf + (lane      ) * 129;
        const float* p1 = dsmf + (lane + 32 ) * 129;
        const float* p2 = dsmf + (lane + 64 ) * 129;
        const float* p3 = dsmf + (lane + 96 ) * 129;
        for (int c = 0; c < 128; c++) {
            float zv = zp[c];
            zn += zv * zv;
            d0 += p0[c] * zv; d1 += p1[c] * zv;
            d2s += p2[c] * zv; d3 += p3[c] * zv;
        }
        float bv = zn + wn[lane] - 2.f * d0; int bk = lane;
        float v1 = zn + wn[lane + 32] - 2.f * d1; if (v1 > bv) { bv = v1; bk = lane + 32; }
        float v2 = zn + wn[lane + 64] - 2.f * d2s; if (v2 > bv) { bv = v2; bk = lane + 64; }
        float v3 = zn + wn[lane + 96] - 2.f * d3; if (v3 > bv) { bv = v3; bk = lane + 96; }
        #pragma unroll
        for (int o = 16; o; o >>= 1) {
            float ov = __shfl_xor_sync(0xffffffffu, bv, o);
            int   ok = __shfl_xor_sync(0xffffffffu, bk, o);
            if (ov > bv || (ov == bv && ok < bk)) { bv = ov; bk = ok; }
        }
        if (lane == 0) {
            sidx[pos] = bk;
            if (idx_out) idx_out[b * 36 + pos] = (float)bk;
        }
    }
    __syncthreads();

    float lsum = 0.f;
    for (int i = tid; i < 4608; i += NT) {
        int pos = i >> 7; int c = i & 127;
        float v  = dsmf[sidx[pos] * 129 + c];
        float zv = zt[i];
        valf8[(size_t)b * 4608 + i] =
            __nv_cvt_float_to_fp8(v, __NV_SATFINITE, __NV_E4M3);
        float d = v - zv;
        lsum += d * d;
    }
    lsum = warp_sum(lsum);
    if ((tid & 31) == 0) atomicAdd(&g_dict_sum, (double)lsum);
}

// ---------------- mu (1x1 conv) fused with reconstruction loss (NHWC fp8) ----
__global__ void __launch_bounds__(256)
mu_loss(const uint8_t* __restrict__ f4, const float* __restrict__ x,
        const float* __restrict__ mw, const float* __restrict__ mb)
{
    __shared__ float mws[128];
    const int b = blockIdx.x, tid = threadIdx.x;
    if (tid < 128) mws[tid] = mw[tid];
    __syncthreads();
    float lsum = 0.f;
    for (int px = tid; px < 784; px += NT) {
        const uint4* fp = (const uint4*)(f4 + ((size_t)b * 784 + px) * 128);
        float s = mb[0];
        #pragma unroll
        for (int j = 0; j < 8; j++) {
            uint4 v = fp[j];
            const uint16_t* hb = (const uint16_t*)&v;
            #pragma unroll
            for (int t = 0; t < 8; t++) {
                __half2 h2 = __half2(__nv_cvt_fp8x2_to_halfraw2(hb[t], __NV_E4M3));
                s += __low2float(h2)  * mws[j * 16 + 2 * t]
                   + __high2float(h2) * mws[j * 16 + 2 * t + 1];
            }
        }
        float d = s - x[(size_t)b * 784 + px];
        lsum += d * d;
    }
    lsum = warp_sum(lsum);
    if ((tid & 31) == 0) atomicAdd(&g_rec_sum, (double)lsum);
}

__global__ void finalize_kernel(float* loss_out)
{
    if (loss_out) {
        double dict_mse = g_dict_sum / 1179648.0;
        loss_out[0] = (float)(g_rec_sum / 200704.0);
        loss_out[1] = (float)(dict_mse * 5.0);
        loss_out[2] = (float)(dict_mse * 1.25);
        loss_out[3] = 0.f;
    }
}

// ---------------- host side ----------------------------------------------------
extern "C" void kernel_launch(void* const* d_in, const int* in_sizes, int n_in,
                              void* d_out, int out_size)
{
    const float* x    = (const float*)d_in[0];
    const float* w1   = (const float*)d_in[1];
    const float* b1   = (const float*)d_in[2];
    const float* w2   = (const float*)d_in[3];
    const float* b2   = (const float*)d_in[4];
    const float* w3   = (const float*)d_in[5];
    const float* b3   = (const float*)d_in[6];
    const float* t1w  = (const float*)d_in[7];
    const float* t1b  = (const float*)d_in[8];
    const float* t2w  = (const float*)d_in[9];
    const float* t2b  = (const float*)d_in[10];
    const float* t3w  = (const float*)d_in[11];
    const float* t3b  = (const float*)d_in[12];
    const float* t4w  = (const float*)d_in[13];
    const float* t4b  = (const float*)d_in[14];
    const float* mw   = (const float*)d_in[15];
    const float* mb   = (const float*)d_in[16];
    const float* dictw= (const float*)d_in[17];

    float* outp = (float*)d_out;
    float* loss_ptr = outp;
    float* idx_ptr  = outp + 4;
    if (out_size < 9220) { loss_ptr = nullptr; idx_ptr = outp; }

    __half *c1hi, *c1lo, *p1hi, *p1lo, *w2hi, *w2lo, *w3hi, *w3lo;
    float *c2f, *c3f, *zn;
    uint8_t *valf8, *f1f8, *f2f8, *f3f8, *f4f8, *wp1, *wpt2, *wp3, *wp4;
    cudaGetSymbolAddress((void**)&c1hi, g_c1hi);
    cudaGetSymbolAddress((void**)&c1lo, g_c1lo);
    cudaGetSymbolAddress((void**)&c2f,  g_c2f);
    cudaGetSymbolAddress((void**)&p1hi, g_p1hi);
    cudaGetSymbolAddress((void**)&p1lo, g_p1lo);
    cudaGetSymbolAddress((void**)&c3f,  g_c3f);
    cudaGetSymbolAddress((void**)&zn,   g_zn);
    cudaGetSymbolAddress((void**)&valf8, g_valf8);
    cudaGetSymbolAddress((void**)&f1f8,  g_f1f8);
    cudaGetSymbolAddress((void**)&f2f8,  g_f2f8);
    cudaGetSymbolAddress((void**)&f3f8,  g_f3f8);
    cudaGetSymbolAddress((void**)&f4f8,  g_f4f8);
    cudaGetSymbolAddress((void**)&wp1,  g_wp1f8);
    cudaGetSymbolAddress((void**)&wpt2, g_wpt2f8);
    cudaGetSymbolAddress((void**)&wp3,  g_wp3f8);
    cudaGetSymbolAddress((void**)&wp4,  g_wp4f8);
    cudaGetSymbolAddress((void**)&w2hi, g_w2hi);
    cudaGetSymbolAddress((void**)&w2lo, g_w2lo);
    cudaGetSymbolAddress((void**)&w3hi, g_w3hi);
    cudaGetSymbolAddress((void**)&w3lo, g_w3lo);

    static bool attr_set = false;
    if (!attr_set) {
        cudaFuncSetAttribute(vq_kernel, cudaFuncAttributeMaxDynamicSharedMemorySize,
                             128 * 129 * (int)sizeof(float));
        cudaFuncSetAttribute(tc_f8, cudaFuncAttributeMaxDynamicSharedMemorySize,
                             4 * FTILE);
        cudaFuncSetAttribute(tc_t2_f8, cudaFuncAttributeMaxDynamicSharedMemorySize,
                             4 * FTILE);
        cudaFuncSetAttribute(tc_enc3, cudaFuncAttributeMaxDynamicSharedMemorySize,
                             3 * TILE);
        attr_set = true;
    }

    prepack_all<<<132, 256>>>(w2, w3, t1w, t2w, t3w, t4w,
                              w2hi, w2lo, w3hi, w3lo, wp1, wpt2, wp3, wp4);
    conv1_split<<<dim3(BB, 72), 128>>>(x, w1, b1, c1hi, c1lo);
    tc_enc3<<<1152, 256, 3 * TILE>>>(
        (const uint16_t*)c1hi, (const uint16_t*)c1lo,
        (const uint16_t*)w2hi, (const uint16_t*)w2lo,
        b2, c2f, 24, 24, 24, 24, 2, 1);
    mp_split_nhwc<<<4096, 256>>>(c2f, p1hi, p1lo, 24, 24);
    tc_enc3<<<288, 256, 3 * TILE>>>(
        (const uint16_t*)p1hi, (const uint16_t*)p1lo,
        (const uint16_t*)w3hi, (const uint16_t*)w3lo,
        b3, c3f, 12, 12, 12, 12, 2, 0);
    mp_nhwc<<<2048, 256>>>(c3f, zn, 12, 12);

    vq_kernel<<<BB, NT, 128 * 129 * sizeof(float)>>>(zn, dictw, valf8, idx_ptr);

    tc_f8<<<162, 256, 4 * FTILE>>>(valf8, wp1, t1b, f1f8, 6, 6, 9, 9, 3, 4);
    tc_t2_f8<<<dim3(200, 1, 4), 256, 4 * FTILE>>>(f1f8, wpt2, t2b, f2f8);
    tc_f8<<<1152, 256, 4 * FTILE>>>(f2f8, wp3, t3b, f3f8, 20, 20, 24, 24, 4, 5);
    tc_f8<<<1568, 256, 4 * FTILE>>>(f3f8, wp4, t4b, f4f8, 24, 24, 28, 28, 4, 5);

    mu_loss<<<BB, NT>>>(f4f8, x, mw, mb);
    finalize_kernel<<<1, 1>>>(loss_ptr);
}